// round 2
// baseline (speedup 1.0000x reference)
#include <cuda_runtime.h>
#include <math.h>

#define Bb 4
#define Nn 4096
#define Dd 256
#define Pp 64
#define Hh 1024
#define NCc 256
#define BN (Bb*Nn)

// ---------------- device scratch (no allocations allowed) ----------------
__device__ float g_QT[Bb*Pp*Nn];     // Q transposed:  [b][p][n]
__device__ float g_KT[Bb*Pp*Nn];     // K transposed:  [b][p][n]
__device__ float g_PNT[Bb*Pp*Nn];    // pn transposed: [b][p][n]
__device__ float g_INC[(size_t)BN*Dd];       // incoming (B,N,D)
__device__ int   g_hitcnt[BN];
__device__ int   g_hitlist[BN*32];

// ---------------- kernel 1: projections Q,K,pn (+zero hit counters) ------
__global__ __launch_bounds__(256) void proj_kernel(
    const float* __restrict__ actions,
    const float* __restrict__ Wq, const float* __restrict__ bq,
    const float* __restrict__ Wk, const float* __restrict__ bk,
    const float* __restrict__ Wc, const float* __restrict__ bc)
{
    __shared__ float As[32*Dd];          // 32 KB, reused for outputs
    __shared__ float invn[32];
    // output overlays (padded to 65 to avoid bank conflicts on final read)
    float* Qs = As;                      // 32*65
    float* Ks = As + 32*65;
    float* Ps = As + 64*65;
    int tid = threadIdx.x;
    int row0 = blockIdx.x * 32;          // flattened b*N+n

    for (int idx = tid; idx < 32*Dd; idx += 256)
        As[idx] = actions[(size_t)row0*Dd + idx];
    __syncthreads();

    int p = tid & 63, g = tid >> 6;      // 64 cols x 4 row-groups (8 rows each)
    float aq[8], ak[8], ac[8];
#pragma unroll
    for (int i = 0; i < 8; i++){ aq[i]=0.f; ak[i]=0.f; ac[i]=0.f; }
    for (int d = 0; d < Dd; d++){
        float wq = Wq[d*Pp+p], wk = Wk[d*Pp+p], wc = Wc[d*Pp+p];
#pragma unroll
        for (int i = 0; i < 8; i++){
            float a = As[(g*8+i)*Dd + d];
            aq[i] = fmaf(a, wq, aq[i]);
            ak[i] = fmaf(a, wk, ak[i]);
            ac[i] = fmaf(a, wc, ac[i]);
        }
    }
    float vbq = bq[p], vbk = bk[p], vbc = bc[p];
    __syncthreads();                      // done reading As, safe to overlay
#pragma unroll
    for (int i = 0; i < 8; i++){
        int r = g*8+i;
        Qs[r*65+p] = aq[i]+vbq;
        Ks[r*65+p] = ak[i]+vbk;
        Ps[r*65+p] = ac[i]+vbc;
    }
    __syncthreads();
    if (tid < 32){
        float s = 0.f;
        for (int j = 0; j < 64; j++){ float v = Ps[tid*65+j]; s = fmaf(v,v,s); }
        invn[tid] = 1.0f / fmaxf(sqrtf(s), 1e-12f);
        g_hitcnt[row0 + tid] = 0;
    }
    __syncthreads();
    int bb = row0 / Nn, n0 = row0 % Nn;
    for (int idx = tid; idx < 64*32; idx += 256){
        int pp = idx >> 5, r = idx & 31;
        size_t o = ((size_t)bb*Pp + pp)*Nn + n0 + r;
        g_QT[o]  = Qs[r*65+pp];
        g_KT[o]  = Ks[r*65+pp];
        g_PNT[o] = Ps[r*65+pp]*invn[r];
    }
}

// ---------------- kernel 2: scores + sim GEMMs, top-8, softmax, incoming -
#define RA 64
#define TMa 128
#define SSTR 129

__global__ __launch_bounds__(256) void graph_kernel(const float* __restrict__ states)
{
    extern __shared__ float sm[];
    float* Qt  = sm;                 // [64 k][64 r]
    float* Pnt = Qt  + 64*64;
    float* Kt  = Pnt + 64*64;        // [64 k][128 m]
    float* Pmt = Kt  + 64*128;
    float* Ssm = Pmt + 64*128;       // [64 r][129]

    int tid = threadIdx.x;
    int bb = blockIdx.y;
    int n0 = blockIdx.x * RA;
    const float* QTb  = g_QT  + (size_t)bb*Pp*Nn;
    const float* KTb  = g_KT  + (size_t)bb*Pp*Nn;
    const float* PNTb = g_PNT + (size_t)bb*Pp*Nn;

    for (int idx = tid; idx < 64*64; idx += 256){
        int k = idx >> 6, r = idx & 63;
        Qt[idx]  = QTb[(size_t)k*Nn + n0 + r];
        Pnt[idx] = PNTb[(size_t)k*Nn + n0 + r];
    }

    // per-thread persistent top-8 state (threads 0..63 own one row each)
    float tv[8]; int ti8[8]; float minv = -1e30f; int minp = 0;
#pragma unroll
    for (int j = 0; j < 8; j++){ tv[j] = -1e30f; ti8[j] = 0; }

    int ty = tid >> 5, tx = tid & 31;
    int r0 = ty*8, mth = tx*4;

    for (int t = 0; t < Nn/TMa; t++){
        int m0 = t*TMa;
        for (int idx = tid; idx < 64*128; idx += 256){
            int k = idx >> 7, m = idx & 127;
            Kt[idx]  = KTb[(size_t)k*Nn + m0 + m];
            Pmt[idx] = PNTb[(size_t)k*Nn + m0 + m];
        }
        __syncthreads();

        float sA[8][4], cA[8][4];
#pragma unroll
        for (int i = 0; i < 8; i++)
#pragma unroll
            for (int j = 0; j < 4; j++){ sA[i][j]=0.f; cA[i][j]=0.f; }

#pragma unroll 4
        for (int k = 0; k < 64; k++){
            float4 kf = *(const float4*)(Kt  + k*128 + mth);
            float4 pm = *(const float4*)(Pmt + k*128 + mth);
            float4 qa = *(const float4*)(Qt  + k*64 + r0);
            float4 qb = *(const float4*)(Qt  + k*64 + r0 + 4);
            float4 pa = *(const float4*)(Pnt + k*64 + r0);
            float4 pb = *(const float4*)(Pnt + k*64 + r0 + 4);
            float qv[8] = {qa.x,qa.y,qa.z,qa.w,qb.x,qb.y,qb.z,qb.w};
            float pv[8] = {pa.x,pa.y,pa.z,pa.w,pb.x,pb.y,pb.z,pb.w};
            float kv[4] = {kf.x,kf.y,kf.z,kf.w};
            float pw[4] = {pm.x,pm.y,pm.z,pm.w};
#pragma unroll
            for (int i = 0; i < 8; i++)
#pragma unroll
                for (int j = 0; j < 4; j++){
                    sA[i][j] = fmaf(qv[i], kv[j], sA[i][j]);
                    cA[i][j] = fmaf(pv[i], pw[j], cA[i][j]);
                }
        }

#pragma unroll
        for (int i = 0; i < 8; i++)
#pragma unroll
            for (int j = 0; j < 4; j++){
                Ssm[(r0+i)*SSTR + mth + j] = sA[i][j]*0.125f;   // / sqrt(64)
                if (cA[i][j] > 0.7f){
                    int hidx = bb*Nn + n0 + r0 + i;
                    int slot = atomicAdd(&g_hitcnt[hidx], 1);
                    if (slot < 32) g_hitlist[(size_t)hidx*32 + slot] = m0 + mth + j;
                }
            }
        __syncthreads();

        if (tid < 64){
            const float* Sr = Ssm + tid*SSTR;
            for (int m = 0; m < TMa; m++){
                float v = Sr[m];
                if (v > minv){
                    tv[minp] = v; ti8[minp] = m0 + m;
                    minv = tv[0]; minp = 0;
#pragma unroll
                    for (int j = 1; j < 8; j++)
                        if (tv[j] < minv){ minv = tv[j]; minp = j; }
                }
            }
        }
        __syncthreads();
    }

    // stage top-8 to smem (reuse tile space)
    float* topV = Kt;
    int*   topI = (int*)Pmt;
    if (tid < 64){
#pragma unroll
        for (int j = 0; j < 8; j++){ topV[tid*8+j] = tv[j]; topI[tid*8+j] = ti8[j]; }
    }
    __syncthreads();

    // softmax over top-8 + gather incoming = adjacency @ states
    int w = tid >> 5, lane = tid & 31;
    const float* Sb = states + (size_t)bb*Nn*Dd;
    for (int rr = 0; rr < 8; rr++){
        int r = w*8 + rr;
        float v = (lane < 8) ? topV[r*8+lane] : -1e30f;
        float mx = v;
#pragma unroll
        for (int off = 4; off; off >>= 1) mx = fmaxf(mx, __shfl_xor_sync(0xffffffffu, mx, off));
        float e = (lane < 8) ? __expf(v - mx) : 0.f;
        float s = e;
#pragma unroll
        for (int off = 4; off; off >>= 1) s += __shfl_xor_sync(0xffffffffu, s, off);
        float wgt = (lane < 8) ? (e / s) : 0.f;
        int myi = (lane < 8) ? topI[r*8+lane] : 0;
        float w8[8]; int i8[8];
#pragma unroll
        for (int j = 0; j < 8; j++){
            w8[j] = __shfl_sync(0xffffffffu, wgt, j);
            i8[j] = __shfl_sync(0xffffffffu, myi, j);
        }
        float* Ig = g_INC + ((size_t)bb*Nn + n0 + r)*Dd;
#pragma unroll
        for (int dd = 0; dd < 8; dd++){
            int d = lane + dd*32;
            float a = 0.f;
#pragma unroll
            for (int j = 0; j < 8; j++) a = fmaf(w8[j], Sb[(size_t)i8[j]*Dd + d], a);
            Ig[d] = a;
        }
    }
}

// ---------------- kernel 3: out_states + Wh GEMM + HDC episodic ----------
#define RC 16
#define HSTR 1040

__global__ __launch_bounds__(256) void hdc_kernel(
    const float* __restrict__ episodic,
    const float* __restrict__ Wh, const float* __restrict__ bh,
    const float* __restrict__ keys, const float* __restrict__ pcodes,
    const int* __restrict__ step,
    float* __restrict__ out_states, float* __restrict__ out_epi,
    float* __restrict__ out_sim)
{
    extern __shared__ float smc[];
    float* Xs   = smc;               // [16][256]
    float* Hs   = smc + 16*256;      // [16][HSTR]
    float* poss = Hs + 16*HSTR;      // [1024]

    int tid = threadIdx.x;
    int row0 = blockIdx.x * RC;      // flattened row
    int bb = row0 / Nn;
    int prow = ((step[0] % NCc) + NCc) % NCc;
    for (int idx = tid; idx < Hh; idx += 256) poss[idx] = pcodes[(size_t)prow*Hh + idx];

    // phase 1: combined from hit lists -> out_states (d = tid)
    for (int r = 0; r < RC; r++){
        int row = row0 + r;
        int cnt = g_hitcnt[row];
        int lim = cnt < 32 ? cnt : 32;
        const int* hl = g_hitlist + (size_t)row*32;
        float comb = 0.f;
        for (int j = 0; j < lim; j++){
            int m = hl[j];
            comb += g_INC[((size_t)bb*Nn + m)*Dd + tid];
        }
        float inc = g_INC[(size_t)row*Dd + tid];
        float ov = 0.8f*inc + 0.2f*comb/((float)cnt + 1e-8f);
        Xs[r*Dd + tid] = ov;
        out_states[(size_t)row*Dd + tid] = ov;
    }
    __syncthreads();

    // phase 2: Xs(16x256) @ Wh(256x1024), tanh(3x) -> Hs
    float acc[16][4];
#pragma unroll
    for (int r = 0; r < 16; r++)
#pragma unroll
        for (int j = 0; j < 4; j++) acc[r][j] = 0.f;
    int c0 = tid*4;
    for (int k = 0; k < Dd; k++){
        float4 wv = *(const float4*)(Wh + (size_t)k*Hh + c0);
#pragma unroll
        for (int r = 0; r < 16; r++){
            float x = Xs[r*Dd + k];
            acc[r][0] = fmaf(x, wv.x, acc[r][0]);
            acc[r][1] = fmaf(x, wv.y, acc[r][1]);
            acc[r][2] = fmaf(x, wv.z, acc[r][2]);
            acc[r][3] = fmaf(x, wv.w, acc[r][3]);
        }
    }
    float4 bv = *(const float4*)(bh + c0);
#pragma unroll
    for (int r = 0; r < 16; r++){
        float b4[4] = {bv.x, bv.y, bv.z, bv.w};
#pragma unroll
        for (int j = 0; j < 4; j++){
            float y = 6.0f*(acc[r][j] + b4[j]);           // tanh(3x)=1-2/(e^{6x}+1)
            Hs[r*HSTR + c0 + j] = 1.0f - 2.0f/(__expf(y) + 1.0f);
        }
    }
    __syncthreads();

    // phase 3: episodic update + cosine read
    int rg = tid >> 4, j = tid & 15;
    int row = row0 + rg;
    int n = row % Nn;
    const float* keyr = keys + (size_t)n*Hh;
    const float* epr  = episodic + (size_t)row*Hh;
    float* oer = out_epi + (size_t)row*Hh;
    float dot = 0.f, na2 = 0.f, nb2 = 0.f;
    for (int i = 0; i < 64; i++){
        int c = i*16 + j;
        float pers = Hs[rg*HSTR + c]*keyr[c];
        float ne = 0.95f*epr[c] + 0.05f*pers*poss[c];
        oer[c] = ne;
        dot = fmaf(ne, pers, dot);
        na2 = fmaf(ne, ne, na2);
        nb2 = fmaf(pers, pers, nb2);
    }
#pragma unroll
    for (int off = 8; off; off >>= 1){
        dot += __shfl_down_sync(0xffffffffu, dot, off, 16);
        na2 += __shfl_down_sync(0xffffffffu, na2, off, 16);
        nb2 += __shfl_down_sync(0xffffffffu, nb2, off, 16);
    }
    if (j == 0)
        out_sim[row] = dot / (fmaxf(sqrtf(na2), 1e-8f)*fmaxf(sqrtf(nb2), 1e-8f));
}

// ---------------- launch ----------------
extern "C" void kernel_launch(void* const* d_in, const int* in_sizes, int n_in,
                              void* d_out, int out_size)
{
    (void)in_sizes; (void)n_in; (void)out_size;
    const float* states   = (const float*)d_in[0];
    const float* actions  = (const float*)d_in[1];
    const float* episodic = (const float*)d_in[2];
    const float* Wq = (const float*)d_in[3];  const float* bq = (const float*)d_in[4];
    const float* Wk = (const float*)d_in[5];  const float* bk = (const float*)d_in[6];
    const float* Wc = (const float*)d_in[7];  const float* bc = (const float*)d_in[8];
    const float* Wh = (const float*)d_in[9];  const float* bh = (const float*)d_in[10];
    const float* keys   = (const float*)d_in[11];
    const float* pcodes = (const float*)d_in[12];
    const int*   step   = (const int*)d_in[13];

    float* out = (float*)d_out;
    float* o_states = out;
    float* o_epi    = out + (size_t)BN*Dd;
    float* o_sim    = out + (size_t)BN*Dd + (size_t)BN*Hh;

    proj_kernel<<<BN/32, 256>>>(actions, Wq, bq, Wk, bk, Wc, bc);

    size_t smA = (size_t)(64*64*2 + 64*128*2 + 64*SSTR) * sizeof(float);
    cudaFuncSetAttribute(graph_kernel, cudaFuncAttributeMaxDynamicSharedMemorySize, (int)smA);
    graph_kernel<<<dim3(Nn/RA, Bb), 256, smA>>>(states);

    size_t smC = (size_t)(16*256 + 16*HSTR + Hh) * sizeof(float);
    cudaFuncSetAttribute(hdc_kernel, cudaFuncAttributeMaxDynamicSharedMemorySize, (int)smC);
    hdc_kernel<<<BN/RC, 256, smC>>>(episodic, Wh, bh, keys, pcodes, step,
                                    o_states, o_epi, o_sim);
}

// round 4
// speedup vs baseline: 1.3242x; 1.3242x over previous
#include <cuda_runtime.h>
#include <cuda_bf16.h>
#include <cstdint>
#include <math.h>

#define Bb 4
#define Nn 4096
#define Dd 256
#define Pp 64
#define Hh 1024
#define NCc 256
#define BN (Bb*Nn)

// ---------------- device scratch ----------------
__device__ float g_Qf[(size_t)BN*64];
__device__ float g_Kf[(size_t)BN*64];
__device__ __nv_bfloat16 g_Qhi[(size_t)BN*64], g_Qlo[(size_t)BN*64];
__device__ __nv_bfloat16 g_Khi[(size_t)BN*64], g_Klo[(size_t)BN*64];
__device__ __nv_bfloat16 g_Phi[(size_t)BN*64], g_Plo[(size_t)BN*64];
__device__ __nv_bfloat16 g_WhhiT[(size_t)Hh*Dd], g_WhloT[(size_t)Hh*Dd];
__device__ float g_INC[(size_t)BN*Dd];
__device__ int   g_hitcnt[BN];
__device__ int   g_hitlist[BN*32];

// ---------------- warp MMA helpers (sm_80+ path, valid on sm_100) --------
__device__ __forceinline__ uint32_t smem_u32(const void* p){
    uint32_t a;
    asm("{ .reg .u64 t; cvta.to.shared.u64 t, %1; cvt.u32.u64 %0, t; }" : "=r"(a) : "l"(p));
    return a;
}
// A fragment: 16x16 bf16 tile, rows m0.., k chunk kc (32B per 16 bf16)
__device__ __forceinline__ void ldmA(uint32_t tile, int m0, int kc, int stride, uint32_t* a){
    int lane = threadIdx.x & 31;
    uint32_t addr = tile + (uint32_t)(m0 + (lane & 15))*stride + (uint32_t)kc*32 + ((lane >> 4)*16);
    asm volatile("ldmatrix.sync.aligned.m8n8.x4.shared.b16 {%0,%1,%2,%3}, [%4];"
        : "=r"(a[0]),"=r"(a[1]),"=r"(a[2]),"=r"(a[3]) : "r"(addr));
}
// B fragment: n8 x k16 tile from row-major [n][k] storage
__device__ __forceinline__ void ldmB(uint32_t tile, int n0, int kc, int stride, uint32_t* b){
    int lane = threadIdx.x & 31;
    uint32_t addr = tile + (uint32_t)(n0 + (lane & 7))*stride + (uint32_t)kc*32 + (((lane >> 3) & 1)*16);
    asm volatile("ldmatrix.sync.aligned.m8n8.x2.shared.b16 {%0,%1}, [%2];"
        : "=r"(b[0]),"=r"(b[1]) : "r"(addr));
}
__device__ __forceinline__ void mma16816(float* c, const uint32_t* a, const uint32_t* b){
    asm volatile("mma.sync.aligned.m16n8k16.row.col.f32.bf16.bf16.f32 "
        "{%0,%1,%2,%3}, {%4,%5,%6,%7}, {%8,%9}, {%0,%1,%2,%3};"
        : "+f"(c[0]),"+f"(c[1]),"+f"(c[2]),"+f"(c[3])
        : "r"(a[0]),"r"(a[1]),"r"(a[2]),"r"(a[3]), "r"(b[0]),"r"(b[1]));
}

// ---------------- kernel 0: Wh transpose + bf16 hi/lo split --------------
__global__ __launch_bounds__(256) void whprep(const float* __restrict__ Wh){
    int idx = blockIdx.x*256 + threadIdx.x;          // k*1024+n
    int k = idx >> 10, n = idx & 1023;
    float w = Wh[idx];
    __nv_bfloat16 h = __float2bfloat16(w);
    g_WhhiT[(size_t)n*Dd + k] = h;
    g_WhloT[(size_t)n*Dd + k] = __float2bfloat16(w - __bfloat162float(h));
}

// ---------------- kernel 1: projections ----------------
__global__ __launch_bounds__(256) void proj_kernel(
    const float* __restrict__ actions,
    const float* __restrict__ Wq, const float* __restrict__ bq,
    const float* __restrict__ Wk, const float* __restrict__ bk,
    const float* __restrict__ Wc, const float* __restrict__ bc)
{
    __shared__ float As[32*Dd];
    __shared__ float invn[32];
    float* Qs = As;
    float* Ks = As + 32*65;
    float* Ps = As + 64*65;
    int tid = threadIdx.x;
    int row0 = blockIdx.x * 32;

    for (int idx = tid; idx < 32*Dd; idx += 256)
        As[idx] = actions[(size_t)row0*Dd + idx];
    __syncthreads();

    int p = tid & 63, g = tid >> 6;
    float aq[8], ak[8], ac[8];
#pragma unroll
    for (int i = 0; i < 8; i++){ aq[i]=0.f; ak[i]=0.f; ac[i]=0.f; }
    for (int d = 0; d < Dd; d++){
        float wq = Wq[d*Pp+p], wk = Wk[d*Pp+p], wc = Wc[d*Pp+p];
#pragma unroll
        for (int i = 0; i < 8; i++){
            float a = As[(g*8+i)*Dd + d];
            aq[i] = fmaf(a, wq, aq[i]);
            ak[i] = fmaf(a, wk, ak[i]);
            ac[i] = fmaf(a, wc, ac[i]);
        }
    }
    float vbq = bq[p], vbk = bk[p], vbc = bc[p];
    __syncthreads();
#pragma unroll
    for (int i = 0; i < 8; i++){
        int r = g*8+i;
        Qs[r*65+p] = aq[i]+vbq;
        Ks[r*65+p] = ak[i]+vbk;
        Ps[r*65+p] = ac[i]+vbc;
    }
    __syncthreads();
    if (tid < 32){
        float s = 0.f;
        for (int j = 0; j < 64; j++){ float v = Ps[tid*65+j]; s = fmaf(v,v,s); }
        invn[tid] = 1.0f / fmaxf(sqrtf(s), 1e-12f);
        g_hitcnt[row0 + tid] = 0;
    }
    __syncthreads();
    for (int idx = tid; idx < 32*64; idx += 256){
        int r = idx >> 6, pp = idx & 63;
        size_t o = (size_t)(row0 + r)*64 + pp;
        float q = Qs[r*65+pp], k = Ks[r*65+pp], pn = Ps[r*65+pp]*invn[r];
        g_Qf[o] = q; g_Kf[o] = k;
        __nv_bfloat16 qh = __float2bfloat16(q);
        g_Qhi[o] = qh; g_Qlo[o] = __float2bfloat16(q - __bfloat162float(qh));
        __nv_bfloat16 kh = __float2bfloat16(k);
        g_Khi[o] = kh; g_Klo[o] = __float2bfloat16(k - __bfloat162float(kh));
        __nv_bfloat16 ph = __float2bfloat16(pn);
        g_Phi[o] = ph; g_Plo[o] = __float2bfloat16(pn - __bfloat162float(ph));
    }
}

// ---------------- kernel 2: graph (scores + sim via mma.sync) ------------
#define SR 144                 // smem row stride bytes for [128][64] bf16 tiles
#define A_QHI 0
#define A_QLO 18432
#define A_PHI 36864
#define A_PLO 55296
#define B_KHI 73728
#define B_KLO 92160
#define B_PHI 110592
#define B_PLO 129024
#define G_SSM 147456           // 128 rows x 129 floats (516B stride)
#define G_TOPW 213504
#define G_TOPI 217600
#define G_TOT 221696

__device__ __forceinline__ void load_tile128(char* sm, int dst, const __nv_bfloat16* src, int tid){
    const uint4* s = (const uint4*)src;      // 128 rows x 128B contiguous
#pragma unroll
    for (int i = tid; i < 1024; i += 256){
        uint4 v = s[i];
        int row = i >> 3, ch = i & 7;
        *(uint4*)(sm + dst + row*SR + ch*16) = v;
    }
}

__global__ __launch_bounds__(256,1) void graph_kernel(const float* __restrict__ states)
{
    extern __shared__ char sm[];
    uint32_t sb = smem_u32(sm);
    float* Ssm = (float*)(sm + G_SSM);
    int tid = threadIdx.x, wid = tid >> 5, lane = tid & 31;
    int bb = blockIdx.y, n0 = blockIdx.x * 128;
    size_t bofs = (size_t)bb*Nn*64;

    // A tiles: rows n0..n0+127
    load_tile128(sm, A_QHI, g_Qhi + bofs + (size_t)n0*64, tid);
    load_tile128(sm, A_QLO, g_Qlo + bofs + (size_t)n0*64, tid);
    load_tile128(sm, A_PHI, g_Phi + bofs + (size_t)n0*64, tid);
    load_tile128(sm, A_PLO, g_Plo + bofs + (size_t)n0*64, tid);

    int m0w = wid*16;
    int rql = lane >> 2, cq = (lane & 3)*2;

    float cv[16]; int ci[16]; float cmin = -1e30f; int cminp = 0;
#pragma unroll
    for (int j = 0; j < 16; j++){ cv[j] = -1e30f; ci[j] = 0; }

    for (int t = 0; t < Nn/128; t++){
        size_t mofs = bofs + (size_t)t*128*64;
        load_tile128(sm, B_KHI, g_Khi + mofs, tid);
        load_tile128(sm, B_KLO, g_Klo + mofs, tid);
        load_tile128(sm, B_PHI, g_Phi + mofs, tid);
        load_tile128(sm, B_PLO, g_Plo + mofs, tid);
        __syncthreads();

        // ---- pass 1: scores = Q.K^T (3-term bf16 split) ----
        float acc[16][4];
#pragma unroll
        for (int nt = 0; nt < 16; nt++)
#pragma unroll
            for (int e = 0; e < 4; e++) acc[nt][e] = 0.f;
#pragma unroll
        for (int kc = 0; kc < 4; kc++){
            uint32_t ah[4], al[4];
            ldmA(sb + A_QHI, m0w, kc, SR, ah);
            ldmA(sb + A_QLO, m0w, kc, SR, al);
#pragma unroll
            for (int nt = 0; nt < 16; nt++){
                uint32_t bh2[2], bl2[2];
                ldmB(sb + B_KHI, nt*8, kc, SR, bh2);
                ldmB(sb + B_KLO, nt*8, kc, SR, bl2);
                mma16816(acc[nt], ah, bh2);
                mma16816(acc[nt], ah, bl2);
                mma16816(acc[nt], al, bh2);
            }
        }
        // stage scores (unscaled) to smem
#pragma unroll
        for (int nt = 0; nt < 16; nt++){
            int c = nt*8 + cq;
            Ssm[(m0w + rql)*129 + c]     = acc[nt][0];
            Ssm[(m0w + rql)*129 + c + 1] = acc[nt][1];
            Ssm[(m0w + rql + 8)*129 + c]     = acc[nt][2];
            Ssm[(m0w + rql + 8)*129 + c + 1] = acc[nt][3];
        }

        // ---- pass 2: sim = pn.pn^T ----
#pragma unroll
        for (int nt = 0; nt < 16; nt++)
#pragma unroll
            for (int e = 0; e < 4; e++) acc[nt][e] = 0.f;
#pragma unroll
        for (int kc = 0; kc < 4; kc++){
            uint32_t ah[4], al[4];
            ldmA(sb + A_PHI, m0w, kc, SR, ah);
            ldmA(sb + A_PLO, m0w, kc, SR, al);
#pragma unroll
            for (int nt = 0; nt < 16; nt++){
                uint32_t bh2[2], bl2[2];
                ldmB(sb + B_PHI, nt*8, kc, SR, bh2);
                ldmB(sb + B_PLO, nt*8, kc, SR, bl2);
                mma16816(acc[nt], ah, bh2);
                mma16816(acc[nt], ah, bl2);
                mma16816(acc[nt], al, bh2);
            }
        }
        // threshold hits straight from registers
#pragma unroll
        for (int nt = 0; nt < 16; nt++)
#pragma unroll
            for (int e = 0; e < 4; e++){
                if (acc[nt][e] > 0.7f){
                    int row = n0 + m0w + rql + ((e >= 2) ? 8 : 0);
                    int col = t*128 + nt*8 + cq + (e & 1);
                    int hidx = bb*Nn + row;
                    int slot = atomicAdd(&g_hitcnt[hidx], 1);
                    if (slot < 32) g_hitlist[(size_t)hidx*32 + slot] = col;
                }
            }
        __syncthreads();

        // ---- scan: approximate top-16 per row ----
        if (tid < 128){
            const float* Sr = Ssm + tid*129;
            for (int m = 0; m < 128; m++){
                float v = Sr[m];
                if (v > cmin){
                    cv[cminp] = v; ci[cminp] = t*128 + m;
                    cmin = cv[0]; cminp = 0;
#pragma unroll
                    for (int q = 1; q < 16; q++)
                        if (cv[q] < cmin){ cmin = cv[q]; cminp = q; }
                }
            }
        }
        __syncthreads();
    }

    // ---- exact fp32 rescore of 16 candidates -> top-8 + softmax ----
    float* topW = (float*)(sm + G_TOPW);
    int*   topI = (int*)(sm + G_TOPI);
    if (tid < 128){
        const float4* Q4 = (const float4*)(g_Qf + bofs + (size_t)(n0 + tid)*64);
        float q[64];
#pragma unroll
        for (int i = 0; i < 16; i++){
            float4 v = Q4[i];
            q[4*i] = v.x; q[4*i+1] = v.y; q[4*i+2] = v.z; q[4*i+3] = v.w;
        }
        float ex[16];
#pragma unroll
        for (int c = 0; c < 16; c++){
            const float4* K4 = (const float4*)(g_Kf + bofs + (size_t)ci[c]*64);
            float a2 = 0.f;
#pragma unroll
            for (int i = 0; i < 16; i++){
                float4 kv = K4[i];
                a2 = fmaf(q[4*i],   kv.x, a2);
                a2 = fmaf(q[4*i+1], kv.y, a2);
                a2 = fmaf(q[4*i+2], kv.z, a2);
                a2 = fmaf(q[4*i+3], kv.w, a2);
            }
            ex[c] = a2 * 0.125f;
        }
        unsigned used = 0;
        float tv[8]; int ti8[8];
#pragma unroll
        for (int s = 0; s < 8; s++){
            float best = -1e30f; int bi = 0;
#pragma unroll
            for (int c = 0; c < 16; c++){
                bool ok = !((used >> c) & 1u) && ex[c] > best;
                if (ok){ best = ex[c]; bi = c; }
            }
            used |= 1u << bi; tv[s] = best; ti8[s] = ci[bi];
        }
        float mx = tv[0];
        float e[8], ssum = 0.f;
#pragma unroll
        for (int j = 0; j < 8; j++){ e[j] = __expf(tv[j] - mx); ssum += e[j]; }
        float inv = 1.f / ssum;
#pragma unroll
        for (int j = 0; j < 8; j++){ topW[tid*8+j] = e[j]*inv; topI[tid*8+j] = ti8[j]; }
    }
    __syncthreads();

    // ---- gather incoming = adjacency @ states ----
    const float* Sb = states + (size_t)bb*Nn*Dd;
    for (int rr = 0; rr < 16; rr++){
        int r = wid*16 + rr;
        float w8[8]; int i8[8];
#pragma unroll
        for (int j = 0; j < 8; j++){ w8[j] = topW[r*8+j]; i8[j] = topI[r*8+j]; }
        float* Ig = g_INC + ((size_t)bb*Nn + n0 + r)*Dd;
#pragma unroll
        for (int dd = 0; dd < 8; dd++){
            int d = lane + dd*32;
            float a2 = 0.f;
#pragma unroll
            for (int j = 0; j < 8; j++) a2 = fmaf(w8[j], Sb[(size_t)i8[j]*Dd + d], a2);
            Ig[d] = a2;
        }
    }
}

// ---------------- kernel 3: hdc (Wh GEMM via mma.sync + fused episodic) --
#define H_XS  0
#define H_XHI 65536
#define H_XLO 99328
#define H_WHI 133120
#define H_WLO 166912
#define H_HS  200704            // 64 x 66 floats
#define H_POS 217600
#define H_TOT 221696
#define HSR 528                 // row stride bytes for [.. ][256] bf16 tiles

__global__ __launch_bounds__(256,1) void hdc_kernel(
    const float* __restrict__ episodic,
    const float* __restrict__ bh,
    const float* __restrict__ keys, const float* __restrict__ pcodes,
    const int* __restrict__ step,
    float* __restrict__ out_states, float* __restrict__ out_epi,
    float* __restrict__ out_sim)
{
    extern __shared__ char sm[];
    uint32_t sb = smem_u32(sm);
    float* Xs   = (float*)(sm + H_XS);
    float* HsS  = (float*)(sm + H_HS);
    float* posS = (float*)(sm + H_POS);
    int tid = threadIdx.x, wid = tid >> 5, lane = tid & 31;
    int row0 = blockIdx.x * 64;
    int bb = row0 / Nn;
    int prow = ((step[0] % NCc) + NCc) % NCc;
    for (int idx = tid; idx < Hh; idx += 256) posS[idx] = pcodes[(size_t)prow*Hh + idx];

    // ---- phase 1: combined gather -> out_states + Xs ----
    for (int r = 0; r < 64; r++){
        int row = row0 + r;
        int cnt = g_hitcnt[row];
        int lim = cnt < 32 ? cnt : 32;
        const int* hl = g_hitlist + (size_t)row*32;
        float comb = 0.f;
        for (int j = 0; j < lim; j++)
            comb += g_INC[((size_t)bb*Nn + hl[j])*Dd + tid];
        float inc = g_INC[(size_t)row*Dd + tid];
        float ov = 0.8f*inc + 0.2f*comb/((float)cnt + 1e-8f);
        Xs[r*Dd + tid] = ov;
        out_states[(size_t)row*Dd + tid] = ov;
    }
    __syncthreads();

    // ---- convert X to bf16 hi/lo ----
    for (int idx = tid; idx < 64*Dd; idx += 256){
        int r = idx >> 8, k = idx & 255;
        float x = Xs[r*Dd + k];
        __nv_bfloat16 h = __float2bfloat16(x);
        *(__nv_bfloat16*)(sm + H_XHI + r*HSR + k*2) = h;
        *(__nv_bfloat16*)(sm + H_XLO + r*HSR + k*2) = __float2bfloat16(x - __bfloat162float(h));
    }

    int wm = (wid & 3)*16, wn = (wid >> 2)*32;
    int rql = lane >> 2, cq = (lane & 3)*2;
    int pr = tid >> 2, j4 = tid & 3;
    int grow = row0 + pr, n = grow & (Nn - 1);
    const float* keyr = keys + (size_t)n*Hh;
    float dot = 0.f, na2 = 0.f, nb2 = 0.f;

    for (int chunk = 0; chunk < 16; chunk++){
        int c0 = chunk*64;
        // load Wh chunk (cols c0..c0+63, all 256 k) hi/lo
        const uint4* wh4 = (const uint4*)g_WhhiT;
        const uint4* wl4 = (const uint4*)g_WhloT;
#pragma unroll
        for (int idx = tid; idx < 2048; idx += 256){
            int r = idx >> 5, ch = idx & 31;
            *(uint4*)(sm + H_WHI + r*HSR + ch*16) = wh4[(size_t)(c0 + r)*32 + ch];
            *(uint4*)(sm + H_WLO + r*HSR + ch*16) = wl4[(size_t)(c0 + r)*32 + ch];
        }
        __syncthreads();

        // mma: X(64x256) @ WhT-chunk(64x256)^T -> 64x64
        float acc[4][4];
#pragma unroll
        for (int nt = 0; nt < 4; nt++)
#pragma unroll
            for (int e = 0; e < 4; e++) acc[nt][e] = 0.f;
#pragma unroll
        for (int kc = 0; kc < 16; kc++){
            uint32_t ah[4], al[4];
            ldmA(sb + H_XHI, wm, kc, HSR, ah);
            ldmA(sb + H_XLO, wm, kc, HSR, al);
#pragma unroll
            for (int nt = 0; nt < 4; nt++){
                uint32_t bh2[2], bl2[2];
                ldmB(sb + H_WHI, wn + nt*8, kc, HSR, bh2);
                ldmB(sb + H_WLO, wn + nt*8, kc, HSR, bl2);
                mma16816(acc[nt], ah, bh2);
                mma16816(acc[nt], ah, bl2);
                mma16816(acc[nt], al, bh2);
            }
        }
        // bias + tanh(3x) -> Hs chunk
#pragma unroll
        for (int nt = 0; nt < 4; nt++)
#pragma unroll
            for (int e = 0; e < 4; e++){
                int lc = wn + nt*8 + cq + (e & 1);
                int lr = wm + rql + ((e >= 2) ? 8 : 0);
                float y = 6.0f*(acc[nt][e] + bh[c0 + lc]);
                HsS[lr*66 + lc] = 1.0f - 2.0f/(__expf(y) + 1.0f);
            }
        __syncthreads();

        // phase 3 partials: thread = (row pr, 8-col groups)
#pragma unroll
        for (int i = 0; i < 8; i++){
            int lc = i*8 + j4*2;
            int c = c0 + lc;
            float2 ep2 = *(const float2*)(episodic + (size_t)grow*Hh + c);
            float2 ky2 = *(const float2*)(keyr + c);
            float p0 = HsS[pr*66 + lc]     * ky2.x;
            float p1 = HsS[pr*66 + lc + 1] * ky2.y;
            float ne0 = 0.95f*ep2.x + 0.05f*p0*posS[c];
            float ne1 = 0.95f*ep2.y + 0.05f*p1*posS[c+1];
            *(float2*)(out_epi + (size_t)grow*Hh + c) = make_float2(ne0, ne1);
            dot = fmaf(ne0, p0, fmaf(ne1, p1, dot));
            na2 = fmaf(ne0, ne0, fmaf(ne1, ne1, na2));
            nb2 = fmaf(p0, p0, fmaf(p1, p1, nb2));
        }
        __syncthreads();
    }

    // reduce across the 4 threads of each row
#pragma unroll
    for (int off = 2; off; off >>= 1){
        dot += __shfl_down_sync(0xffffffffu, dot, off, 4);
        na2 += __shfl_down_sync(0xffffffffu, na2, off, 4);
        nb2 += __shfl_down_sync(0xffffffffu, nb2, off, 4);
    }
    if (j4 == 0)
        out_sim[grow] = dot / (fmaxf(sqrtf(na2), 1e-8f)*fmaxf(sqrtf(nb2), 1e-8f));
}

// ---------------- launch ----------------
extern "C" void kernel_launch(void* const* d_in, const int* in_sizes, int n_in,
                              void* d_out, int out_size)
{
    (void)in_sizes; (void)n_in; (void)out_size;
    const float* states   = (const float*)d_in[0];
    const float* actions  = (const float*)d_in[1];
    const float* episodic = (const float*)d_in[2];
    const float* Wq = (const float*)d_in[3];  const float* bq = (const float*)d_in[4];
    const float* Wk = (const float*)d_in[5];  const float* bk = (const float*)d_in[6];
    const float* Wc = (const float*)d_in[7];  const float* bc = (const float*)d_in[8];
    const float* Wh = (const float*)d_in[9];  const float* bh = (const float*)d_in[10];
    const float* keys   = (const float*)d_in[11];
    const float* pcodes = (const float*)d_in[12];
    const int*   step   = (const int*)d_in[13];

    float* out = (float*)d_out;
    float* o_states = out;
    float* o_epi    = out + (size_t)BN*Dd;
    float* o_sim    = out + (size_t)BN*Dd + (size_t)BN*Hh;

    whprep<<<(Dd*Hh)/256, 256>>>(Wh);
    proj_kernel<<<BN/32, 256>>>(actions, Wq, bq, Wk, bk, Wc, bc);

    cudaFuncSetAttribute(graph_kernel, cudaFuncAttributeMaxDynamicSharedMemorySize, G_TOT);
    graph_kernel<<<dim3(Nn/128, Bb), 256, G_TOT>>>(states);

    cudaFuncSetAttribute(hdc_kernel, cudaFuncAttributeMaxDynamicSharedMemorySize, H_TOT);
    hdc_kernel<<<BN/64, 256, H_TOT>>>(episodic, bh, keys, pcodes, step,
                                      o_states, o_epi, o_sim);
}

// round 5
// speedup vs baseline: 1.7315x; 1.3076x over previous
#include <cuda_runtime.h>
#include <cuda_bf16.h>
#include <cstdint>
#include <math.h>

#define Bb 4
#define Nn 4096
#define Dd 256
#define Pp 64
#define Hh 1024
#define NCc 256
#define BN (Bb*Nn)

// ---------------- device scratch ----------------
__device__ float g_Qf[(size_t)BN*64];
__device__ float g_Kf[(size_t)BN*64];
__device__ __nv_bfloat16 g_Qhi[(size_t)BN*64], g_Qlo[(size_t)BN*64];
__device__ __nv_bfloat16 g_Khi[(size_t)BN*64], g_Klo[(size_t)BN*64];
__device__ __nv_bfloat16 g_Phi[(size_t)BN*64], g_Plo[(size_t)BN*64];
__device__ __nv_bfloat16 g_WhhiT[(size_t)Hh*Dd], g_WhloT[(size_t)Hh*Dd];
__device__ __nv_bfloat16 g_Xhi[(size_t)BN*Dd], g_Xlo[(size_t)BN*Dd];
__device__ float g_INC[(size_t)BN*Dd];
__device__ float g_dot[BN], g_na[BN], g_nb[BN];
__device__ int   g_hitcnt[BN];
__device__ int   g_hitlist[BN*32];

// ---------------- helpers ----------------
__device__ __forceinline__ uint32_t smem_u32(const void* p){
    uint32_t a;
    asm("{ .reg .u64 t; cvta.to.shared.u64 t, %1; cvt.u32.u64 %0, t; }" : "=r"(a) : "l"(p));
    return a;
}
__device__ __forceinline__ void ldmA(uint32_t tile, int m0, int kc, int stride, uint32_t* a){
    int lane = threadIdx.x & 31;
    uint32_t addr = tile + (uint32_t)(m0 + (lane & 15))*stride + (uint32_t)kc*32 + ((lane >> 4)*16);
    asm volatile("ldmatrix.sync.aligned.m8n8.x4.shared.b16 {%0,%1,%2,%3}, [%4];"
        : "=r"(a[0]),"=r"(a[1]),"=r"(a[2]),"=r"(a[3]) : "r"(addr));
}
__device__ __forceinline__ void ldmB(uint32_t tile, int n0, int kc, int stride, uint32_t* b){
    int lane = threadIdx.x & 31;
    uint32_t addr = tile + (uint32_t)(n0 + (lane & 7))*stride + (uint32_t)kc*32 + (((lane >> 3) & 1)*16);
    asm volatile("ldmatrix.sync.aligned.m8n8.x2.shared.b16 {%0,%1}, [%2];"
        : "=r"(b[0]),"=r"(b[1]) : "r"(addr));
}
__device__ __forceinline__ void mma16816(float* c, const uint32_t* a, const uint32_t* b){
    asm volatile("mma.sync.aligned.m16n8k16.row.col.f32.bf16.bf16.f32 "
        "{%0,%1,%2,%3}, {%4,%5,%6,%7}, {%8,%9}, {%0,%1,%2,%3};"
        : "+f"(c[0]),"+f"(c[1]),"+f"(c[2]),"+f"(c[3])
        : "r"(a[0]),"r"(a[1]),"r"(a[2]),"r"(a[3]), "r"(b[0]),"r"(b[1]));
}
#define CP_COMMIT() asm volatile("cp.async.commit_group;" ::: "memory")
#define CP_WAIT1()  asm volatile("cp.async.wait_group 1;" ::: "memory")
#define CP_WAIT0()  asm volatile("cp.async.wait_group 0;" ::: "memory")

#define UPD8(VV, II, MN, MP, val, col) do { \
    if ((val) > (MN)){ VV[MP] = (val); II[MP] = (col); MN = VV[0]; MP = 0; \
        _Pragma("unroll") for (int _q = 1; _q < 8; _q++) \
            if (VV[_q] < MN){ MN = VV[_q]; MP = _q; } } } while(0)

// ---------------- kernel 0: Wh transpose + split ----------------
__global__ __launch_bounds__(256) void whprep(const float* __restrict__ Wh){
    int idx = blockIdx.x*256 + threadIdx.x;
    int k = idx >> 10, n = idx & 1023;
    float w = Wh[idx];
    __nv_bfloat16 h = __float2bfloat16(w);
    g_WhhiT[(size_t)n*Dd + k] = h;
    g_WhloT[(size_t)n*Dd + k] = __float2bfloat16(w - __bfloat162float(h));
}

// ---------------- kernel 1: projections ----------------
__global__ __launch_bounds__(256) void proj_kernel(
    const float* __restrict__ actions,
    const float* __restrict__ Wq, const float* __restrict__ bq,
    const float* __restrict__ Wk, const float* __restrict__ bk,
    const float* __restrict__ Wc, const float* __restrict__ bc)
{
    __shared__ float As[32*Dd];
    __shared__ float invn[32];
    float* Qs = As;
    float* Ks = As + 32*65;
    float* Ps = As + 64*65;
    int tid = threadIdx.x;
    int row0 = blockIdx.x * 32;

    for (int idx = tid; idx < 32*Dd; idx += 256)
        As[idx] = actions[(size_t)row0*Dd + idx];
    __syncthreads();

    int p = tid & 63, g = tid >> 6;
    float aq[8], ak[8], ac[8];
#pragma unroll
    for (int i = 0; i < 8; i++){ aq[i]=0.f; ak[i]=0.f; ac[i]=0.f; }
    for (int d = 0; d < Dd; d++){
        float wq = Wq[d*Pp+p], wk = Wk[d*Pp+p], wc = Wc[d*Pp+p];
#pragma unroll
        for (int i = 0; i < 8; i++){
            float a = As[(g*8+i)*Dd + d];
            aq[i] = fmaf(a, wq, aq[i]);
            ak[i] = fmaf(a, wk, ak[i]);
            ac[i] = fmaf(a, wc, ac[i]);
        }
    }
    float vbq = bq[p], vbk = bk[p], vbc = bc[p];
    __syncthreads();
#pragma unroll
    for (int i = 0; i < 8; i++){
        int r = g*8+i;
        Qs[r*65+p] = aq[i]+vbq;
        Ks[r*65+p] = ak[i]+vbk;
        Ps[r*65+p] = ac[i]+vbc;
    }
    __syncthreads();
    if (tid < 32){
        float s = 0.f;
        for (int j = 0; j < 64; j++){ float v = Ps[tid*65+j]; s = fmaf(v,v,s); }
        invn[tid] = 1.0f / fmaxf(sqrtf(s), 1e-12f);
        g_hitcnt[row0 + tid] = 0;
    }
    __syncthreads();
    for (int idx = tid; idx < 32*64; idx += 256){
        int r = idx >> 6, pp = idx & 63;
        size_t o = (size_t)(row0 + r)*64 + pp;
        float q = Qs[r*65+pp], k = Ks[r*65+pp], pn = Ps[r*65+pp]*invn[r];
        g_Qf[o] = q; g_Kf[o] = k;
        __nv_bfloat16 qh = __float2bfloat16(q);
        g_Qhi[o] = qh; g_Qlo[o] = __float2bfloat16(q - __bfloat162float(qh));
        __nv_bfloat16 kh = __float2bfloat16(k);
        g_Khi[o] = kh; g_Klo[o] = __float2bfloat16(k - __bfloat162float(kh));
        __nv_bfloat16 ph = __float2bfloat16(pn);
        g_Phi[o] = ph; g_Plo[o] = __float2bfloat16(pn - __bfloat162float(ph));
    }
}

// ---------------- kernel 2: graph ----------------
#define SR 144
#define A_QHI 0
#define A_QLO 18432
#define A_PHI 36864
#define A_PLO 55296
#define B_BASE 73728
#define B_BUF  73728            // per-buffer span (4 tiles x 18432)
#define OB_KHI 0
#define OB_KLO 18432
#define OB_PHI 36864
#define OB_PLO 55296
#define G_TOT  (B_BASE + 2*B_BUF)        // 221184
#define G_CAND B_BASE                     // aliased after mainloop
#define G_TOPW (B_BASE + 32768)
#define G_TOPI (B_BASE + 32768 + 4096)

__device__ __forceinline__ void cp_tile(uint32_t sb, int dst, const __nv_bfloat16* src, int tid){
    const char* s = (const char*)src;
#pragma unroll
    for (int i = tid; i < 1024; i += 256){
        int row = i >> 3, ch = i & 7;
        uint32_t d = sb + dst + row*SR + ch*16;
        asm volatile("cp.async.cg.shared.global [%0], [%1], 16;" :: "r"(d), "l"(s + i*16));
    }
}

__global__ __launch_bounds__(256,1) void graph_kernel(const float* __restrict__ states)
{
    extern __shared__ char sm[];
    uint32_t sb = smem_u32(sm);
    int tid = threadIdx.x, wid = tid >> 5, lane = tid & 31;
    int bb = blockIdx.y, n0 = blockIdx.x * 128;
    size_t bofs = (size_t)bb*Nn*64;

    // prologue: A tiles + B tile0 (group0), B tile1 (group1)
    cp_tile(sb, A_QHI, g_Qhi + bofs + (size_t)n0*64, tid);
    cp_tile(sb, A_QLO, g_Qlo + bofs + (size_t)n0*64, tid);
    cp_tile(sb, A_PHI, g_Phi + bofs + (size_t)n0*64, tid);
    cp_tile(sb, A_PLO, g_Plo + bofs + (size_t)n0*64, tid);
    cp_tile(sb, B_BASE + OB_KHI, g_Khi + bofs, tid);
    cp_tile(sb, B_BASE + OB_KLO, g_Klo + bofs, tid);
    cp_tile(sb, B_BASE + OB_PHI, g_Phi + bofs, tid);
    cp_tile(sb, B_BASE + OB_PLO, g_Plo + bofs, tid);
    CP_COMMIT();
    {
        size_t mofs = bofs + (size_t)128*64;
        cp_tile(sb, B_BASE + B_BUF + OB_KHI, g_Khi + mofs, tid);
        cp_tile(sb, B_BASE + B_BUF + OB_KLO, g_Klo + mofs, tid);
        cp_tile(sb, B_BASE + B_BUF + OB_PHI, g_Phi + mofs, tid);
        cp_tile(sb, B_BASE + B_BUF + OB_PLO, g_Plo + mofs, tid);
        CP_COMMIT();
    }

    int m0w = wid*16;
    int rql = lane >> 2, cq = (lane & 3)*2, j4 = lane & 3;

    // per-thread top-8 for its two rows (disjoint col slices per quad-lane)
    float v0[8], v1[8]; int i0[8], i1[8];
    float mn0 = -1e30f, mn1 = -1e30f; int mp0 = 0, mp1 = 0;
#pragma unroll
    for (int j = 0; j < 8; j++){ v0[j]=-1e30f; v1[j]=-1e30f; i0[j]=0; i1[j]=0; }

    for (int t = 0; t < Nn/128; t++){
        int buf = t & 1;
        if (t + 1 < Nn/128) CP_WAIT1(); else CP_WAIT0();
        __syncthreads();
        uint32_t bB = sb + B_BASE + buf*B_BUF;

        // ---- pass 1: scores ----
        float acc[16][4];
#pragma unroll
        for (int nt = 0; nt < 16; nt++)
#pragma unroll
            for (int e = 0; e < 4; e++) acc[nt][e] = 0.f;
#pragma unroll
        for (int kc = 0; kc < 4; kc++){
            uint32_t ah[4], al[4];
            ldmA(sb + A_QHI, m0w, kc, SR, ah);
            ldmA(sb + A_QLO, m0w, kc, SR, al);
#pragma unroll
            for (int nt = 0; nt < 16; nt++){
                uint32_t bh2[2], bl2[2];
                ldmB(bB + OB_KHI, nt*8, kc, SR, bh2);
                ldmB(bB + OB_KLO, nt*8, kc, SR, bl2);
                mma16816(acc[nt], ah, bh2);
                mma16816(acc[nt], ah, bl2);
                mma16816(acc[nt], al, bh2);
            }
        }
        // in-register top-8 update
#pragma unroll
        for (int nt = 0; nt < 16; nt++){
            int cbase = t*128 + nt*8 + cq;
            UPD8(v0, i0, mn0, mp0, acc[nt][0], cbase);
            UPD8(v0, i0, mn0, mp0, acc[nt][1], cbase+1);
            UPD8(v1, i1, mn1, mp1, acc[nt][2], cbase);
            UPD8(v1, i1, mn1, mp1, acc[nt][3], cbase+1);
        }

        // ---- pass 2: sim ----
#pragma unroll
        for (int nt = 0; nt < 16; nt++)
#pragma unroll
            for (int e = 0; e < 4; e++) acc[nt][e] = 0.f;
#pragma unroll
        for (int kc = 0; kc < 4; kc++){
            uint32_t ah[4], al[4];
            ldmA(sb + A_PHI, m0w, kc, SR, ah);
            ldmA(sb + A_PLO, m0w, kc, SR, al);
#pragma unroll
            for (int nt = 0; nt < 16; nt++){
                uint32_t bh2[2], bl2[2];
                ldmB(bB + OB_PHI, nt*8, kc, SR, bh2);
                ldmB(bB + OB_PLO, nt*8, kc, SR, bl2);
                mma16816(acc[nt], ah, bh2);
                mma16816(acc[nt], ah, bl2);
                mma16816(acc[nt], al, bh2);
            }
        }
#pragma unroll
        for (int nt = 0; nt < 16; nt++)
#pragma unroll
            for (int e = 0; e < 4; e++){
                if (acc[nt][e] > 0.7f){
                    int row = n0 + m0w + rql + ((e >= 2) ? 8 : 0);
                    int col = t*128 + nt*8 + cq + (e & 1);
                    int hidx = bb*Nn + row;
                    int slot = atomicAdd(&g_hitcnt[hidx], 1);
                    if (slot < 32) g_hitlist[(size_t)hidx*32 + slot] = col;
                }
            }
        __syncthreads();

        if (t + 2 < Nn/128){
            size_t mofs = bofs + (size_t)(t+2)*128*64;
            uint32_t nbuf = buf;   // (t+2)&1 == t&1
            cp_tile(sb, B_BASE + nbuf*B_BUF + OB_KHI, g_Khi + mofs, tid);
            cp_tile(sb, B_BASE + nbuf*B_BUF + OB_KLO, g_Klo + mofs, tid);
            cp_tile(sb, B_BASE + nbuf*B_BUF + OB_PHI, g_Phi + mofs, tid);
            cp_tile(sb, B_BASE + nbuf*B_BUF + OB_PLO, g_Plo + mofs, tid);
            CP_COMMIT();
        }
    }
    __syncthreads();

    // ---- merge candidates (alias B region) ----
    float* candV = (float*)(sm + G_CAND);
    int*   candI = (int*)(sm + G_CAND + 16384);
    {
        int r0 = m0w + rql, r1 = m0w + rql + 8;
#pragma unroll
        for (int s = 0; s < 8; s++){
            candV[r0*32 + j4*8 + s] = v0[s]; candI[r0*32 + j4*8 + s] = i0[s];
            candV[r1*32 + j4*8 + s] = v1[s]; candI[r1*32 + j4*8 + s] = i1[s];
        }
    }
    __syncthreads();

    // ---- exact fp32 rescore of 32 candidates -> top-8 + softmax ----
    float* topW = (float*)(sm + G_TOPW);
    int*   topI = (int*)(sm + G_TOPI);
    if (tid < 128){
        const float4* Q4 = (const float4*)(g_Qf + bofs + (size_t)(n0 + tid)*64);
        float q[64];
#pragma unroll
        for (int i = 0; i < 16; i++){
            float4 v = Q4[i];
            q[4*i] = v.x; q[4*i+1] = v.y; q[4*i+2] = v.z; q[4*i+3] = v.w;
        }
        float tv[8]; int ti8[8]; float tmn = -1e30f; int tmp = 0;
#pragma unroll
        for (int j = 0; j < 8; j++){ tv[j] = -1e30f; ti8[j] = 0; }
        for (int c = 0; c < 32; c++){
            int col = candI[tid*32 + c];
            const float4* K4 = (const float4*)(g_Kf + bofs + (size_t)col*64);
            float a2 = 0.f;
#pragma unroll
            for (int i = 0; i < 16; i++){
                float4 kv = K4[i];
                a2 = fmaf(q[4*i],   kv.x, a2);
                a2 = fmaf(q[4*i+1], kv.y, a2);
                a2 = fmaf(q[4*i+2], kv.z, a2);
                a2 = fmaf(q[4*i+3], kv.w, a2);
            }
            a2 *= 0.125f;
            UPD8(tv, ti8, tmn, tmp, a2, col);
        }
        float mx = tv[0];
#pragma unroll
        for (int j = 1; j < 8; j++) mx = fmaxf(mx, tv[j]);
        float e[8], ssum = 0.f;
#pragma unroll
        for (int j = 0; j < 8; j++){ e[j] = __expf(tv[j] - mx); ssum += e[j]; }
        float inv = 1.f / ssum;
#pragma unroll
        for (int j = 0; j < 8; j++){ topW[tid*8+j] = e[j]*inv; topI[tid*8+j] = ti8[j]; }
    }
    __syncthreads();

    // ---- gather incoming ----
    const float* Sb = states + (size_t)bb*Nn*Dd;
    for (int rr = 0; rr < 16; rr++){
        int r = wid*16 + rr;
        float w8[8]; int i8[8];
#pragma unroll
        for (int j = 0; j < 8; j++){ w8[j] = topW[r*8+j]; i8[j] = topI[r*8+j]; }
        float* Ig = g_INC + ((size_t)bb*Nn + n0 + r)*Dd;
#pragma unroll
        for (int dd = 0; dd < 8; dd++){
            int d = lane + dd*32;
            float a2 = 0.f;
#pragma unroll
            for (int j = 0; j < 8; j++) a2 = fmaf(w8[j], Sb[(size_t)i8[j]*Dd + d], a2);
            Ig[d] = a2;
        }
    }
}

// ---------------- kernel 3a: phase-1 gather + X split ----------------
__global__ __launch_bounds__(256) void hdc_a(float* __restrict__ out_states){
    int tid = threadIdx.x, wid = tid >> 5, lane = tid & 31;
    int row0 = blockIdx.x * 64;
    int bb = row0 / Nn;
    for (int r8 = 0; r8 < 8; r8++){
        int row = row0 + wid*8 + r8;
        int cnt = g_hitcnt[row];
        int lim = cnt < 32 ? cnt : 32;
        const int* hl = g_hitlist + (size_t)row*32;
        float comb[8];
#pragma unroll
        for (int i = 0; i < 8; i++) comb[i] = 0.f;
        for (int j = 0; j < lim; j++){
            const float* src = g_INC + ((size_t)bb*Nn + hl[j])*Dd;
#pragma unroll
            for (int i = 0; i < 8; i++) comb[i] += src[lane + i*32];
        }
        const float* inc = g_INC + (size_t)row*Dd;
        float inv = 0.2f / ((float)cnt + 1e-8f);
#pragma unroll
        for (int i = 0; i < 8; i++){
            int d = lane + i*32;
            float ov = 0.8f*inc[d] + comb[i]*inv;
            out_states[(size_t)row*Dd + d] = ov;
            __nv_bfloat16 h = __float2bfloat16(ov);
            g_Xhi[(size_t)row*Dd + d] = h;
            g_Xlo[(size_t)row*Dd + d] = __float2bfloat16(ov - __bfloat162float(h));
        }
    }
    if (tid < 64){
        g_dot[row0+tid] = 0.f; g_na[row0+tid] = 0.f; g_nb[row0+tid] = 0.f;
    }
}

// ---------------- kernel 3b: Wh GEMM + fused episodic ----------------
#define HB_AH0 0
#define HB_AL0 18432
#define HB_AH1 36864
#define HB_AL1 55296
#define HB_BH0 73728
#define HB_BL0 82944
#define HB_BH1 92160
#define HB_BL1 101376
#define HB_TOT 110592

__device__ __forceinline__ void cp_rows(uint32_t sb, int dst, const __nv_bfloat16* src,
                                        int nrows, size_t srcstride, int tid){
    // each row: 64 bf16 = 128B = 8 x 16B chunks
    int total = nrows*8;
    for (int i = tid; i < total; i += 256){
        int row = i >> 3, ch = i & 7;
        uint32_t d = sb + dst + row*SR + ch*16;
        const char* s = (const char*)(src + (size_t)row*srcstride) + ch*16;
        asm volatile("cp.async.cg.shared.global [%0], [%1], 16;" :: "r"(d), "l"(s));
    }
}

__global__ __launch_bounds__(256,2) void hdc_b(
    const float* __restrict__ episodic,
    const float* __restrict__ bh,
    const float* __restrict__ keys, const float* __restrict__ pcodes,
    const int* __restrict__ step,
    float* __restrict__ out_epi)
{
    extern __shared__ char sm[];
    uint32_t sb = smem_u32(sm);
    int tid = threadIdx.x, wid = tid >> 5, lane = tid & 31;
    int row0 = blockIdx.x * 128;
    int c0   = blockIdx.y * 64;
    int prow = ((step[0] % NCc) + NCc) % NCc;
    const float* posr = pcodes + (size_t)prow*Hh;

    const __nv_bfloat16* Xh = g_Xhi + (size_t)row0*Dd;
    const __nv_bfloat16* Xl = g_Xlo + (size_t)row0*Dd;
    const __nv_bfloat16* Wh = g_WhhiT + (size_t)c0*Dd;
    const __nv_bfloat16* Wl = g_WhloT + (size_t)c0*Dd;

    // prologue: k-chunk 0 (group0), chunk 1 (group1)
    cp_rows(sb, HB_AH0, Xh,       128, Dd, tid);
    cp_rows(sb, HB_AL0, Xl,       128, Dd, tid);
    cp_rows(sb, HB_BH0, Wh,       64,  Dd, tid);
    cp_rows(sb, HB_BL0, Wl,       64,  Dd, tid);
    CP_COMMIT();
    cp_rows(sb, HB_AH1, Xh + 64,  128, Dd, tid);
    cp_rows(sb, HB_AL1, Xl + 64,  128, Dd, tid);
    cp_rows(sb, HB_BH1, Wh + 64,  64,  Dd, tid);
    cp_rows(sb, HB_BL1, Wl + 64,  64,  Dd, tid);
    CP_COMMIT();

    int wm = wid*16;
    int rql = lane >> 2, cq = (lane & 3)*2, j4 = lane & 3;

    float acc[8][4];
#pragma unroll
    for (int nt = 0; nt < 8; nt++)
#pragma unroll
        for (int e = 0; e < 4; e++) acc[nt][e] = 0.f;

    for (int c = 0; c < 4; c++){
        int buf = c & 1;
        if (c + 1 < 4) CP_WAIT1(); else CP_WAIT0();
        __syncthreads();
        uint32_t aH = sb + (buf ? HB_AH1 : HB_AH0);
        uint32_t aL = sb + (buf ? HB_AL1 : HB_AL0);
        uint32_t bH = sb + (buf ? HB_BH1 : HB_BH0);
        uint32_t bL = sb + (buf ? HB_BL1 : HB_BL0);
#pragma unroll
        for (int kc = 0; kc < 4; kc++){
            uint32_t ah[4], al[4];
            ldmA(aH, wm, kc, SR, ah);
            ldmA(aL, wm, kc, SR, al);
#pragma unroll
            for (int nt = 0; nt < 8; nt++){
                uint32_t bh2[2], bl2[2];
                ldmB(bH, nt*8, kc, SR, bh2);
                ldmB(bL, nt*8, kc, SR, bl2);
                mma16816(acc[nt], ah, bh2);
                mma16816(acc[nt], ah, bl2);
                mma16816(acc[nt], al, bh2);
            }
        }
        __syncthreads();
        if (c + 2 < 4){
            int koff = (c+2)*64;
            uint32_t nb = buf;
            cp_rows(sb, nb ? HB_AH1 : HB_AH0, Xh + koff, 128, Dd, tid);
            cp_rows(sb, nb ? HB_AL1 : HB_AL0, Xl + koff, 128, Dd, tid);
            cp_rows(sb, nb ? HB_BH1 : HB_BH0, Wh + koff, 64,  Dd, tid);
            cp_rows(sb, nb ? HB_BL1 : HB_BL0, Wl + koff, 64,  Dd, tid);
            CP_COMMIT();
        }
    }

    // epilogue: bias + tanh + episodic + per-row partials
    float d0 = 0.f, a0 = 0.f, b0 = 0.f;   // row wm+rql
    float d1 = 0.f, a1 = 0.f, b1 = 0.f;   // row wm+rql+8
    int grow0 = row0 + wm + rql, grow1 = grow0 + 8;
    int n0k = grow0 & (Nn-1), n1k = grow1 & (Nn-1);
#pragma unroll
    for (int nt = 0; nt < 8; nt++){
        int col = c0 + nt*8 + cq;
        float bh0 = __ldg(bh + col), bh1v = __ldg(bh + col + 1);
        float p0c = __ldg(posr + col), p1c = __ldg(posr + col + 1);
        // row 0
        {
            float y0 = 6.0f*(acc[nt][0] + bh0);
            float y1 = 6.0f*(acc[nt][1] + bh1v);
            float h0 = 1.0f - 2.0f/(__expf(y0) + 1.0f);
            float h1 = 1.0f - 2.0f/(__expf(y1) + 1.0f);
            float2 ky = *(const float2*)(keys + (size_t)n0k*Hh + col);
            float pe0 = h0*ky.x, pe1 = h1*ky.y;
            float2 ep = *(const float2*)(episodic + (size_t)grow0*Hh + col);
            float ne0 = 0.95f*ep.x + 0.05f*pe0*p0c;
            float ne1 = 0.95f*ep.y + 0.05f*pe1*p1c;
            *(float2*)(out_epi + (size_t)grow0*Hh + col) = make_float2(ne0, ne1);
            d0 = fmaf(ne0, pe0, fmaf(ne1, pe1, d0));
            a0 = fmaf(ne0, ne0, fmaf(ne1, ne1, a0));
            b0 = fmaf(pe0, pe0, fmaf(pe1, pe1, b0));
        }
        // row 1
        {
            float y0 = 6.0f*(acc[nt][2] + bh0);
            float y1 = 6.0f*(acc[nt][3] + bh1v);
            float h0 = 1.0f - 2.0f/(__expf(y0) + 1.0f);
            float h1 = 1.0f - 2.0f/(__expf(y1) + 1.0f);
            float2 ky = *(const float2*)(keys + (size_t)n1k*Hh + col);
            float pe0 = h0*ky.x, pe1 = h1*ky.y;
            float2 ep = *(const float2*)(episodic + (size_t)grow1*Hh + col);
            float ne0 = 0.95f*ep.x + 0.05f*pe0*p0c;
            float ne1 = 0.95f*ep.y + 0.05f*pe1*p1c;
            *(float2*)(out_epi + (size_t)grow1*Hh + col) = make_float2(ne0, ne1);
            d1 = fmaf(ne0, pe0, fmaf(ne1, pe1, d1));
            a1 = fmaf(ne0, ne0, fmaf(ne1, ne1, a1));
            b1 = fmaf(pe0, pe0, fmaf(pe1, pe1, b1));
        }
    }
    // quad reduce (lanes rql*4 + j4, j4 = 0..3)
#pragma unroll
    for (int off = 1; off <= 2; off <<= 1){
        d0 += __shfl_xor_sync(0xffffffffu, d0, off);
        a0 += __shfl_xor_sync(0xffffffffu, a0, off);
        b0 += __shfl_xor_sync(0xffffffffu, b0, off);
        d1 += __shfl_xor_sync(0xffffffffu, d1, off);
        a1 += __shfl_xor_sync(0xffffffffu, a1, off);
        b1 += __shfl_xor_sync(0xffffffffu, b1, off);
    }
    if (j4 == 0){
        atomicAdd(&g_dot[grow0], d0); atomicAdd(&g_na[grow0], a0); atomicAdd(&g_nb[grow0], b0);
        atomicAdd(&g_dot[grow1], d1); atomicAdd(&g_na[grow1], a1); atomicAdd(&g_nb[grow1], b1);
    }
}

// ---------------- kernel 3c: out_sim finisher ----------------
__global__ __launch_bounds__(256) void hdc_c(float* __restrict__ out_sim){
    int i = blockIdx.x*256 + threadIdx.x;
    out_sim[i] = g_dot[i] / (fmaxf(sqrtf(g_na[i]), 1e-8f)*fmaxf(sqrtf(g_nb[i]), 1e-8f));
}

// ---------------- launch ----------------
extern "C" void kernel_launch(void* const* d_in, const int* in_sizes, int n_in,
                              void* d_out, int out_size)
{
    (void)in_sizes; (void)n_in; (void)out_size;
    const float* states   = (const float*)d_in[0];
    const float* actions  = (const float*)d_in[1];
    const float* episodic = (const float*)d_in[2];
    const float* Wq = (const float*)d_in[3];  const float* bq = (const float*)d_in[4];
    const float* Wk = (const float*)d_in[5];  const float* bk = (const float*)d_in[6];
    const float* Wc = (const float*)d_in[7];  const float* bc = (const float*)d_in[8];
    const float* Wh = (const float*)d_in[9];  const float* bh = (const float*)d_in[10];
    const float* keys   = (const float*)d_in[11];
    const float* pcodes = (const float*)d_in[12];
    const int*   step   = (const int*)d_in[13];

    float* out = (float*)d_out;
    float* o_states = out;
    float* o_epi    = out + (size_t)BN*Dd;
    float* o_sim    = out + (size_t)BN*Dd + (size_t)BN*Hh;

    whprep<<<(Dd*Hh)/256, 256>>>(Wh);
    proj_kernel<<<BN/32, 256>>>(actions, Wq, bq, Wk, bk, Wc, bc);

    cudaFuncSetAttribute(graph_kernel, cudaFuncAttributeMaxDynamicSharedMemorySize, G_TOT);
    graph_kernel<<<dim3(Nn/128, Bb), 256, G_TOT>>>(states);

    hdc_a<<<BN/64, 256>>>(o_states);

    cudaFuncSetAttribute(hdc_b, cudaFuncAttributeMaxDynamicSharedMemorySize, HB_TOT);
    hdc_b<<<dim3(BN/128, Hh/64), 256, HB_TOT>>>(episodic, bh, keys, pcodes, step, o_epi);

    hdc_c<<<BN/256, 256>>>(o_sim);
}

// round 6
// speedup vs baseline: 1.8129x; 1.0470x over previous
#include <cuda_runtime.h>
#include <cuda_bf16.h>
#include <cstdint>
#include <math.h>

#define Bb 4
#define Nn 4096
#define Dd 256
#define Pp 64
#define Hh 1024
#define NCc 256
#define BN (Bb*Nn)

// ---------------- device scratch ----------------
__device__ float g_Qf[(size_t)BN*64];
__device__ float g_Kf[(size_t)BN*64];
__device__ __nv_bfloat16 g_Qhi[(size_t)BN*64], g_Qlo[(size_t)BN*64];
__device__ __nv_bfloat16 g_Khi[(size_t)BN*64], g_Klo[(size_t)BN*64];
__device__ __nv_bfloat16 g_Phi[(size_t)BN*64], g_Plo[(size_t)BN*64];
__device__ __nv_bfloat16 g_WhhiT[(size_t)Hh*Dd], g_WhloT[(size_t)Hh*Dd];
__device__ __nv_bfloat16 g_Xhi[(size_t)BN*Dd], g_Xlo[(size_t)BN*Dd];
__device__ float g_INC[(size_t)BN*Dd];
__device__ float g_dot[BN], g_na[BN], g_nb[BN];
__device__ int   g_hitcnt[BN];
__device__ int   g_hitlist[BN*32];

// ---------------- helpers ----------------
__device__ __forceinline__ uint32_t smem_u32(const void* p){
    uint32_t a;
    asm("{ .reg .u64 t; cvta.to.shared.u64 t, %1; cvt.u32.u64 %0, t; }" : "=r"(a) : "l"(p));
    return a;
}
__device__ __forceinline__ void ldmA(uint32_t tile, int m0, int kc, int stride, uint32_t* a){
    int lane = threadIdx.x & 31;
    uint32_t addr = tile + (uint32_t)(m0 + (lane & 15))*stride + (uint32_t)kc*32 + ((lane >> 4)*16);
    asm volatile("ldmatrix.sync.aligned.m8n8.x4.shared.b16 {%0,%1,%2,%3}, [%4];"
        : "=r"(a[0]),"=r"(a[1]),"=r"(a[2]),"=r"(a[3]) : "r"(addr));
}
__device__ __forceinline__ void ldmB(uint32_t tile, int n0, int kc, int stride, uint32_t* b){
    int lane = threadIdx.x & 31;
    uint32_t addr = tile + (uint32_t)(n0 + (lane & 7))*stride + (uint32_t)kc*32 + (((lane >> 3) & 1)*16);
    asm volatile("ldmatrix.sync.aligned.m8n8.x2.shared.b16 {%0,%1}, [%2];"
        : "=r"(b[0]),"=r"(b[1]) : "r"(addr));
}
__device__ __forceinline__ void mma16816(float* c, const uint32_t* a, const uint32_t* b){
    asm volatile("mma.sync.aligned.m16n8k16.row.col.f32.bf16.bf16.f32 "
        "{%0,%1,%2,%3}, {%4,%5,%6,%7}, {%8,%9}, {%0,%1,%2,%3};"
        : "+f"(c[0]),"+f"(c[1]),"+f"(c[2]),"+f"(c[3])
        : "r"(a[0]),"r"(a[1]),"r"(a[2]),"r"(a[3]), "r"(b[0]),"r"(b[1]));
}
#define CP_COMMIT() asm volatile("cp.async.commit_group;" ::: "memory")
#define CP_WAIT1()  asm volatile("cp.async.wait_group 1;" ::: "memory")
#define CP_WAIT0()  asm volatile("cp.async.wait_group 0;" ::: "memory")

#define UPD8(VV, II, MN, MP, val, col) do { \
    if ((val) > (MN)){ VV[MP] = (val); II[MP] = (col); MN = VV[0]; MP = 0; \
        _Pragma("unroll") for (int _q = 1; _q < 8; _q++) \
            if (VV[_q] < MN){ MN = VV[_q]; MP = _q; } } } while(0)

// ---------------- kernel 0: Wh transpose + split ----------------
__global__ __launch_bounds__(256) void whprep(const float* __restrict__ Wh){
    int idx = blockIdx.x*256 + threadIdx.x;
    int k = idx >> 10, n = idx & 1023;
    float w = Wh[idx];
    __nv_bfloat16 h = __float2bfloat16(w);
    g_WhhiT[(size_t)n*Dd + k] = h;
    g_WhloT[(size_t)n*Dd + k] = __float2bfloat16(w - __bfloat162float(h));
}

// ---------------- kernel 1: projections ----------------
__global__ __launch_bounds__(256) void proj_kernel(
    const float* __restrict__ actions,
    const float* __restrict__ Wq, const float* __restrict__ bq,
    const float* __restrict__ Wk, const float* __restrict__ bk,
    const float* __restrict__ Wc, const float* __restrict__ bc)
{
    __shared__ float As[32*Dd];
    __shared__ float invn[32];
    float* Qs = As;
    float* Ks = As + 32*65;
    float* Ps = As + 64*65;
    int tid = threadIdx.x;
    int row0 = blockIdx.x * 32;

    for (int idx = tid; idx < 32*Dd; idx += 256)
        As[idx] = actions[(size_t)row0*Dd + idx];
    __syncthreads();

    int p = tid & 63, g = tid >> 6;
    float aq[8], ak[8], ac[8];
#pragma unroll
    for (int i = 0; i < 8; i++){ aq[i]=0.f; ak[i]=0.f; ac[i]=0.f; }
    for (int d = 0; d < Dd; d++){
        float wq = Wq[d*Pp+p], wk = Wk[d*Pp+p], wc = Wc[d*Pp+p];
#pragma unroll
        for (int i = 0; i < 8; i++){
            float a = As[(g*8+i)*Dd + d];
            aq[i] = fmaf(a, wq, aq[i]);
            ak[i] = fmaf(a, wk, ak[i]);
            ac[i] = fmaf(a, wc, ac[i]);
        }
    }
    float vbq = bq[p], vbk = bk[p], vbc = bc[p];
    __syncthreads();
#pragma unroll
    for (int i = 0; i < 8; i++){
        int r = g*8+i;
        Qs[r*65+p] = aq[i]+vbq;
        Ks[r*65+p] = ak[i]+vbk;
        Ps[r*65+p] = ac[i]+vbc;
    }
    __syncthreads();
    if (tid < 32){
        float s = 0.f;
        for (int j = 0; j < 64; j++){ float v = Ps[tid*65+j]; s = fmaf(v,v,s); }
        invn[tid] = 1.0f / fmaxf(sqrtf(s), 1e-12f);
        g_hitcnt[row0 + tid] = 0;
    }
    __syncthreads();
    for (int idx = tid; idx < 32*64; idx += 256){
        int r = idx >> 6, pp = idx & 63;
        size_t o = (size_t)(row0 + r)*64 + pp;
        float q = Qs[r*65+pp], k = Ks[r*65+pp], pn = Ps[r*65+pp]*invn[r];
        g_Qf[o] = q; g_Kf[o] = k;
        __nv_bfloat16 qh = __float2bfloat16(q);
        g_Qhi[o] = qh; g_Qlo[o] = __float2bfloat16(q - __bfloat162float(qh));
        __nv_bfloat16 kh = __float2bfloat16(k);
        g_Khi[o] = kh; g_Klo[o] = __float2bfloat16(k - __bfloat162float(kh));
        __nv_bfloat16 ph = __float2bfloat16(pn);
        g_Phi[o] = ph; g_Plo[o] = __float2bfloat16(pn - __bfloat162float(ph));
    }
}

// ---------------- kernel 2: graph (M=64 tiles, 2 CTA/SM) -----------------
#define GSR 144
#define GA_QHI 0
#define GA_QLO 9216
#define GA_PHI 18432
#define GA_PLO 27648
#define GB 36864
#define GB_BUF 36864
#define GB_KHI 0
#define GB_KLO 9216
#define GB_PHI 18432
#define GB_PLO 27648
#define G_TOT 110592
// post-mainloop aliases
#define G_CANDI 0          // 64*64*4 = 16384
#define G_MV 16384         // 64*32*4 = 8192
#define G_MI 24576         // 8192
#define G_TOPW 36864       // 2048
#define G_TOPI 38912       // 2048

__device__ __forceinline__ void cp_tile64(uint32_t sb, int dst, const __nv_bfloat16* src, int tid){
    const char* s = (const char*)src;      // 64 rows x 128B
#pragma unroll
    for (int i = tid; i < 512; i += 256){
        int row = i >> 3, ch = i & 7;
        uint32_t d = sb + dst + row*GSR + ch*16;
        asm volatile("cp.async.cg.shared.global [%0], [%1], 16;" :: "r"(d), "l"(s + i*16));
    }
}

__global__ __launch_bounds__(256,2) void graph_kernel(const float* __restrict__ states)
{
    extern __shared__ char sm[];
    uint32_t sb = smem_u32(sm);
    int tid = threadIdx.x, wid = tid >> 5, lane = tid & 31;
    int bb = blockIdx.y, n0 = blockIdx.x * 64;
    size_t bofs = (size_t)bb*Nn*64;

    // prologue: A tiles + B buf0 (group0), B buf1 (group1)
    cp_tile64(sb, GA_QHI, g_Qhi + bofs + (size_t)n0*64, tid);
    cp_tile64(sb, GA_QLO, g_Qlo + bofs + (size_t)n0*64, tid);
    cp_tile64(sb, GA_PHI, g_Phi + bofs + (size_t)n0*64, tid);
    cp_tile64(sb, GA_PLO, g_Plo + bofs + (size_t)n0*64, tid);
    cp_tile64(sb, GB + GB_KHI, g_Khi + bofs, tid);
    cp_tile64(sb, GB + GB_KLO, g_Klo + bofs, tid);
    cp_tile64(sb, GB + GB_PHI, g_Phi + bofs, tid);
    cp_tile64(sb, GB + GB_PLO, g_Plo + bofs, tid);
    CP_COMMIT();
    {
        size_t mofs = bofs + (size_t)64*64;
        cp_tile64(sb, GB + GB_BUF + GB_KHI, g_Khi + mofs, tid);
        cp_tile64(sb, GB + GB_BUF + GB_KLO, g_Klo + mofs, tid);
        cp_tile64(sb, GB + GB_BUF + GB_PHI, g_Phi + mofs, tid);
        cp_tile64(sb, GB + GB_BUF + GB_PLO, g_Plo + mofs, tid);
        CP_COMMIT();
    }

    int wm = (wid & 3)*16, wng = wid >> 2;
    int rql = lane >> 2, cq = (lane & 3)*2, j4 = lane & 3;

    float v0[8], v1[8]; int i0[8], i1[8];
    float mn0 = -1e30f, mn1 = -1e30f; int mp0 = 0, mp1 = 0;
#pragma unroll
    for (int j = 0; j < 8; j++){ v0[j]=-1e30f; v1[j]=-1e30f; i0[j]=0; i1[j]=0; }

    for (int t = 0; t < Nn/64; t++){
        int buf = t & 1;
        if (t + 1 < Nn/64) CP_WAIT1(); else CP_WAIT0();
        __syncthreads();
        uint32_t bB = sb + GB + buf*GB_BUF;

        // ---- pass 1: scores ----
        float acc[4][4];
#pragma unroll
        for (int nt = 0; nt < 4; nt++)
#pragma unroll
            for (int e = 0; e < 4; e++) acc[nt][e] = 0.f;
#pragma unroll
        for (int kc = 0; kc < 4; kc++){
            uint32_t ah[4], al[4];
            ldmA(sb + GA_QHI, wm, kc, GSR, ah);
            ldmA(sb + GA_QLO, wm, kc, GSR, al);
            uint32_t bh[4][2], bl[4][2];
#pragma unroll
            for (int nt = 0; nt < 4; nt++){
                ldmB(bB + GB_KHI, wng*32 + nt*8, kc, GSR, bh[nt]);
                ldmB(bB + GB_KLO, wng*32 + nt*8, kc, GSR, bl[nt]);
            }
#pragma unroll
            for (int nt = 0; nt < 4; nt++) mma16816(acc[nt], ah, bh[nt]);
#pragma unroll
            for (int nt = 0; nt < 4; nt++) mma16816(acc[nt], ah, bl[nt]);
#pragma unroll
            for (int nt = 0; nt < 4; nt++) mma16816(acc[nt], al, bh[nt]);
        }
        // gated top-8 update (branchless max tree, one branch per row)
        {
            float t0 = fmaxf(fmaxf(fmaxf(acc[0][0],acc[0][1]), fmaxf(acc[1][0],acc[1][1])),
                             fmaxf(fmaxf(acc[2][0],acc[2][1]), fmaxf(acc[3][0],acc[3][1])));
            float t1 = fmaxf(fmaxf(fmaxf(acc[0][2],acc[0][3]), fmaxf(acc[1][2],acc[1][3])),
                             fmaxf(fmaxf(acc[2][2],acc[2][3]), fmaxf(acc[3][2],acc[3][3])));
            if (t0 > mn0){
#pragma unroll
                for (int nt = 0; nt < 4; nt++){
                    int cb = t*64 + (wng*4+nt)*8 + cq;
                    UPD8(v0, i0, mn0, mp0, acc[nt][0], cb);
                    UPD8(v0, i0, mn0, mp0, acc[nt][1], cb+1);
                }
            }
            if (t1 > mn1){
#pragma unroll
                for (int nt = 0; nt < 4; nt++){
                    int cb = t*64 + (wng*4+nt)*8 + cq;
                    UPD8(v1, i1, mn1, mp1, acc[nt][2], cb);
                    UPD8(v1, i1, mn1, mp1, acc[nt][3], cb+1);
                }
            }
        }

        // ---- pass 2: sim ----
#pragma unroll
        for (int nt = 0; nt < 4; nt++)
#pragma unroll
            for (int e = 0; e < 4; e++) acc[nt][e] = 0.f;
#pragma unroll
        for (int kc = 0; kc < 4; kc++){
            uint32_t ah[4], al[4];
            ldmA(sb + GA_PHI, wm, kc, GSR, ah);
            ldmA(sb + GA_PLO, wm, kc, GSR, al);
            uint32_t bh[4][2], bl[4][2];
#pragma unroll
            for (int nt = 0; nt < 4; nt++){
                ldmB(bB + GB_PHI, wng*32 + nt*8, kc, GSR, bh[nt]);
                ldmB(bB + GB_PLO, wng*32 + nt*8, kc, GSR, bl[nt]);
            }
#pragma unroll
            for (int nt = 0; nt < 4; nt++) mma16816(acc[nt], ah, bh[nt]);
#pragma unroll
            for (int nt = 0; nt < 4; nt++) mma16816(acc[nt], ah, bl[nt]);
#pragma unroll
            for (int nt = 0; nt < 4; nt++) mma16816(acc[nt], al, bh[nt]);
        }
#pragma unroll
        for (int nt = 0; nt < 4; nt++)
#pragma unroll
            for (int e = 0; e < 4; e++){
                if (acc[nt][e] > 0.7f){
                    int row = n0 + wm + rql + ((e >= 2) ? 8 : 0);
                    int col = t*64 + (wng*4+nt)*8 + cq + (e & 1);
                    int hidx = bb*Nn + row;
                    int slot = atomicAdd(&g_hitcnt[hidx], 1);
                    if (slot < 32) g_hitlist[(size_t)hidx*32 + slot] = col;
                }
            }
        __syncthreads();

        if (t + 2 < Nn/64){
            size_t mofs = bofs + (size_t)(t+2)*64*64;
            uint32_t nbuf = buf;
            cp_tile64(sb, GB + nbuf*GB_BUF + GB_KHI, g_Khi + mofs, tid);
            cp_tile64(sb, GB + nbuf*GB_BUF + GB_KLO, g_Klo + mofs, tid);
            cp_tile64(sb, GB + nbuf*GB_BUF + GB_PHI, g_Phi + mofs, tid);
            cp_tile64(sb, GB + nbuf*GB_BUF + GB_PLO, g_Plo + mofs, tid);
            CP_COMMIT();
        }
    }
    __syncthreads();

    // ---- dump candidate indices (alias smem) ----
    int* candI = (int*)(sm + G_CANDI);
    {
        int r0 = wm + rql, r1 = wm + rql + 8;
#pragma unroll
        for (int s = 0; s < 8; s++){
            candI[r0*64 + wng*32 + j4*8 + s] = i0[s];
            candI[r1*64 + wng*32 + j4*8 + s] = i1[s];
        }
    }
    __syncthreads();

    // ---- exact fp32 rescore: 4 threads/row x 16 candidates ----
    float* mergeV = (float*)(sm + G_MV);
    int*   mergeI = (int*)(sm + G_MI);
    {
        int row = tid >> 2, sub = tid & 3;
        const float4* Q4 = (const float4*)(g_Qf + bofs + (size_t)(n0 + row)*64);
        float q[64];
#pragma unroll
        for (int i = 0; i < 16; i++){
            float4 v = Q4[i];
            q[4*i] = v.x; q[4*i+1] = v.y; q[4*i+2] = v.z; q[4*i+3] = v.w;
        }
        float tv[8]; int ti8[8]; float tmn = -1e30f; int tmp = 0;
#pragma unroll
        for (int j = 0; j < 8; j++){ tv[j] = -1e30f; ti8[j] = 0; }
#pragma unroll
        for (int c = 0; c < 16; c++){
            int col = candI[row*64 + sub*16 + c];
            const float4* K4 = (const float4*)(g_Kf + bofs + (size_t)col*64);
            float a2 = 0.f;
#pragma unroll
            for (int i = 0; i < 16; i++){
                float4 kv = K4[i];
                a2 = fmaf(q[4*i],   kv.x, a2);
                a2 = fmaf(q[4*i+1], kv.y, a2);
                a2 = fmaf(q[4*i+2], kv.z, a2);
                a2 = fmaf(q[4*i+3], kv.w, a2);
            }
            a2 *= 0.125f;
            UPD8(tv, ti8, tmn, tmp, a2, col);
        }
#pragma unroll
        for (int s = 0; s < 8; s++){
            mergeV[row*32 + sub*8 + s] = tv[s];
            mergeI[row*32 + sub*8 + s] = ti8[s];
        }
    }
    __syncthreads();

    // ---- final merge + softmax (64 threads) ----
    float* topW = (float*)(sm + G_TOPW);
    int*   topI = (int*)(sm + G_TOPI);
    if (tid < 64){
        float tv[8]; int ti8[8]; float tmn = -1e30f; int tmp = 0;
#pragma unroll
        for (int j = 0; j < 8; j++){ tv[j] = -1e30f; ti8[j] = 0; }
#pragma unroll
        for (int c = 0; c < 32; c++){
            float v = mergeV[tid*32 + c];
            int col = mergeI[tid*32 + c];
            UPD8(tv, ti8, tmn, tmp, v, col);
        }
        float mx = tv[0];
#pragma unroll
        for (int j = 1; j < 8; j++) mx = fmaxf(mx, tv[j]);
        float e[8], ssum = 0.f;
#pragma unroll
        for (int j = 0; j < 8; j++){ e[j] = __expf(tv[j] - mx); ssum += e[j]; }
        float inv = 1.f / ssum;
#pragma unroll
        for (int j = 0; j < 8; j++){ topW[tid*8+j] = e[j]*inv; topI[tid*8+j] = ti8[j]; }
    }
    __syncthreads();

    // ---- gather incoming (8 warps x 8 rows) ----
    const float* Sb = states + (size_t)bb*Nn*Dd;
    for (int rr = 0; rr < 8; rr++){
        int r = wid*8 + rr;
        float w8[8]; int i8[8];
#pragma unroll
        for (int j = 0; j < 8; j++){ w8[j] = topW[r*8+j]; i8[j] = topI[r*8+j]; }
        float* Ig = g_INC + ((size_t)bb*Nn + n0 + r)*Dd;
#pragma unroll
        for (int dd = 0; dd < 8; dd++){
            int d = lane + dd*32;
            float a2 = 0.f;
#pragma unroll
            for (int j = 0; j < 8; j++) a2 = fmaf(w8[j], Sb[(size_t)i8[j]*Dd + d], a2);
            Ig[d] = a2;
        }
    }
}

// ---------------- kernel 3a: phase-1 gather + X split ----------------
__global__ __launch_bounds__(256) void hdc_a(float* __restrict__ out_states){
    int tid = threadIdx.x, wid = tid >> 5, lane = tid & 31;
    int row0 = blockIdx.x * 64;
    int bb = row0 / Nn;
    for (int r8 = 0; r8 < 8; r8++){
        int row = row0 + wid*8 + r8;
        int cnt = g_hitcnt[row];
        int lim = cnt < 32 ? cnt : 32;
        const int* hl = g_hitlist + (size_t)row*32;
        float comb[8];
#pragma unroll
        for (int i = 0; i < 8; i++) comb[i] = 0.f;
        for (int j = 0; j < lim; j++){
            const float* src = g_INC + ((size_t)bb*Nn + hl[j])*Dd;
#pragma unroll
            for (int i = 0; i < 8; i++) comb[i] += src[lane + i*32];
        }
        const float* inc = g_INC + (size_t)row*Dd;
        float inv = 0.2f / ((float)cnt + 1e-8f);
#pragma unroll
        for (int i = 0; i < 8; i++){
            int d = lane + i*32;
            float ov = 0.8f*inc[d] + comb[i]*inv;
            out_states[(size_t)row*Dd + d] = ov;
            __nv_bfloat16 h = __float2bfloat16(ov);
            g_Xhi[(size_t)row*Dd + d] = h;
            g_Xlo[(size_t)row*Dd + d] = __float2bfloat16(ov - __bfloat162float(h));
        }
    }
    if (tid < 64){
        g_dot[row0+tid] = 0.f; g_na[row0+tid] = 0.f; g_nb[row0+tid] = 0.f;
    }
}

// ---------------- kernel 3b: Wh GEMM + fused episodic ----------------
#define SR 144
#define HB_AH0 0
#define HB_AL0 18432
#define HB_AH1 36864
#define HB_AL1 55296
#define HB_BH0 73728
#define HB_BL0 82944
#define HB_BH1 92160
#define HB_BL1 101376
#define HB_TOT 110592

__device__ __forceinline__ void cp_rows(uint32_t sb, int dst, const __nv_bfloat16* src,
                                        int nrows, size_t srcstride, int tid){
    int total = nrows*8;
    for (int i = tid; i < total; i += 256){
        int row = i >> 3, ch = i & 7;
        uint32_t d = sb + dst + row*SR + ch*16;
        const char* s = (const char*)(src + (size_t)row*srcstride) + ch*16;
        asm volatile("cp.async.cg.shared.global [%0], [%1], 16;" :: "r"(d), "l"(s));
    }
}

__global__ __launch_bounds__(256,2) void hdc_b(
    const float* __restrict__ episodic,
    const float* __restrict__ bh,
    const float* __restrict__ keys, const float* __restrict__ pcodes,
    const int* __restrict__ step,
    float* __restrict__ out_epi)
{
    extern __shared__ char sm[];
    uint32_t sb = smem_u32(sm);
    int tid = threadIdx.x, wid = tid >> 5, lane = tid & 31;
    int row0 = blockIdx.x * 128;
    int c0   = blockIdx.y * 64;
    int prow = ((step[0] % NCc) + NCc) % NCc;
    const float* posr = pcodes + (size_t)prow*Hh;

    const __nv_bfloat16* Xh = g_Xhi + (size_t)row0*Dd;
    const __nv_bfloat16* Xl = g_Xlo + (size_t)row0*Dd;
    const __nv_bfloat16* Wh = g_WhhiT + (size_t)c0*Dd;
    const __nv_bfloat16* Wl = g_WhloT + (size_t)c0*Dd;

    cp_rows(sb, HB_AH0, Xh,       128, Dd, tid);
    cp_rows(sb, HB_AL0, Xl,       128, Dd, tid);
    cp_rows(sb, HB_BH0, Wh,       64,  Dd, tid);
    cp_rows(sb, HB_BL0, Wl,       64,  Dd, tid);
    CP_COMMIT();
    cp_rows(sb, HB_AH1, Xh + 64,  128, Dd, tid);
    cp_rows(sb, HB_AL1, Xl + 64,  128, Dd, tid);
    cp_rows(sb, HB_BH1, Wh + 64,  64,  Dd, tid);
    cp_rows(sb, HB_BL1, Wl + 64,  64,  Dd, tid);
    CP_COMMIT();

    int wm = wid*16;
    int rql = lane >> 2, cq = (lane & 3)*2, j4 = lane & 3;

    float acc[8][4];
#pragma unroll
    for (int nt = 0; nt < 8; nt++)
#pragma unroll
        for (int e = 0; e < 4; e++) acc[nt][e] = 0.f;

    for (int c = 0; c < 4; c++){
        int buf = c & 1;
        if (c + 1 < 4) CP_WAIT1(); else CP_WAIT0();
        __syncthreads();
        uint32_t aH = sb + (buf ? HB_AH1 : HB_AH0);
        uint32_t aL = sb + (buf ? HB_AL1 : HB_AL0);
        uint32_t bH = sb + (buf ? HB_BH1 : HB_BH0);
        uint32_t bL = sb + (buf ? HB_BL1 : HB_BL0);
#pragma unroll
        for (int kc = 0; kc < 4; kc++){
            uint32_t ah[4], al[4];
            ldmA(aH, wm, kc, SR, ah);
            ldmA(aL, wm, kc, SR, al);
            uint32_t bh2[8][2], bl2[8][2];
#pragma unroll
            for (int nt = 0; nt < 8; nt++){
                ldmB(bH, nt*8, kc, SR, bh2[nt]);
                ldmB(bL, nt*8, kc, SR, bl2[nt]);
            }
#pragma unroll
            for (int nt = 0; nt < 8; nt++) mma16816(acc[nt], ah, bh2[nt]);
#pragma unroll
            for (int nt = 0; nt < 8; nt++) mma16816(acc[nt], ah, bl2[nt]);
#pragma unroll
            for (int nt = 0; nt < 8; nt++) mma16816(acc[nt], al, bh2[nt]);
        }
        __syncthreads();
        if (c + 2 < 4){
            int koff = (c+2)*64;
            uint32_t nb = buf;
            cp_rows(sb, nb ? HB_AH1 : HB_AH0, Xh + koff, 128, Dd, tid);
            cp_rows(sb, nb ? HB_AL1 : HB_AL0, Xl + koff, 128, Dd, tid);
            cp_rows(sb, nb ? HB_BH1 : HB_BH0, Wh + koff, 64,  Dd, tid);
            cp_rows(sb, nb ? HB_BL1 : HB_BL0, Wl + koff, 64,  Dd, tid);
            CP_COMMIT();
        }
    }

    float d0 = 0.f, a0 = 0.f, b0 = 0.f;
    float d1 = 0.f, a1 = 0.f, b1 = 0.f;
    int grow0 = row0 + wm + rql, grow1 = grow0 + 8;
    int n0k = grow0 & (Nn-1), n1k = grow1 & (Nn-1);
#pragma unroll
    for (int nt = 0; nt < 8; nt++){
        int col = c0 + nt*8 + cq;
        float bh0 = __ldg(bh + col), bh1v = __ldg(bh + col + 1);
        float p0c = __ldg(posr + col), p1c = __ldg(posr + col + 1);
        {
            float y0 = 6.0f*(acc[nt][0] + bh0);
            float y1 = 6.0f*(acc[nt][1] + bh1v);
            float h0 = 1.0f - 2.0f/(__expf(y0) + 1.0f);
            float h1 = 1.0f - 2.0f/(__expf(y1) + 1.0f);
            float2 ky = *(const float2*)(keys + (size_t)n0k*Hh + col);
            float pe0 = h0*ky.x, pe1 = h1*ky.y;
            float2 ep = *(const float2*)(episodic + (size_t)grow0*Hh + col);
            float ne0 = 0.95f*ep.x + 0.05f*pe0*p0c;
            float ne1 = 0.95f*ep.y + 0.05f*pe1*p1c;
            *(float2*)(out_epi + (size_t)grow0*Hh + col) = make_float2(ne0, ne1);
            d0 = fmaf(ne0, pe0, fmaf(ne1, pe1, d0));
            a0 = fmaf(ne0, ne0, fmaf(ne1, ne1, a0));
            b0 = fmaf(pe0, pe0, fmaf(pe1, pe1, b0));
        }
        {
            float y0 = 6.0f*(acc[nt][2] + bh0);
            float y1 = 6.0f*(acc[nt][3] + bh1v);
            float h0 = 1.0f - 2.0f/(__expf(y0) + 1.0f);
            float h1 = 1.0f - 2.0f/(__expf(y1) + 1.0f);
            float2 ky = *(const float2*)(keys + (size_t)n1k*Hh + col);
            float pe0 = h0*ky.x, pe1 = h1*ky.y;
            float2 ep = *(const float2*)(episodic + (size_t)grow1*Hh + col);
            float ne0 = 0.95f*ep.x + 0.05f*pe0*p0c;
            float ne1 = 0.95f*ep.y + 0.05f*pe1*p1c;
            *(float2*)(out_epi + (size_t)grow1*Hh + col) = make_float2(ne0, ne1);
            d1 = fmaf(ne0, pe0, fmaf(ne1, pe1, d1));
            a1 = fmaf(ne0, ne0, fmaf(ne1, ne1, a1));
            b1 = fmaf(pe0, pe0, fmaf(pe1, pe1, b1));
        }
    }
#pragma unroll
    for (int off = 1; off <= 2; off <<= 1){
        d0 += __shfl_xor_sync(0xffffffffu, d0, off);
        a0 += __shfl_xor_sync(0xffffffffu, a0, off);
        b0 += __shfl_xor_sync(0xffffffffu, b0, off);
        d1 += __shfl_xor_sync(0xffffffffu, d1, off);
        a1 += __shfl_xor_sync(0xffffffffu, a1, off);
        b1 += __shfl_xor_sync(0xffffffffu, b1, off);
    }
    if (j4 == 0){
        atomicAdd(&g_dot[grow0], d0); atomicAdd(&g_na[grow0], a0); atomicAdd(&g_nb[grow0], b0);
        atomicAdd(&g_dot[grow1], d1); atomicAdd(&g_na[grow1], a1); atomicAdd(&g_nb[grow1], b1);
    }
}

// ---------------- kernel 3c: out_sim finisher ----------------
__global__ __launch_bounds__(256) void hdc_c(float* __restrict__ out_sim){
    int i = blockIdx.x*256 + threadIdx.x;
    out_sim[i] = g_dot[i] / (fmaxf(sqrtf(g_na[i]), 1e-8f)*fmaxf(sqrtf(g_nb[i]), 1e-8f));
}

// ---------------- launch ----------------
extern "C" void kernel_launch(void* const* d_in, const int* in_sizes, int n_in,
                              void* d_out, int out_size)
{
    (void)in_sizes; (void)n_in; (void)out_size;
    const float* states   = (const float*)d_in[0];
    const float* actions  = (const float*)d_in[1];
    const float* episodic = (const float*)d_in[2];
    const float* Wq = (const float*)d_in[3];  const float* bq = (const float*)d_in[4];
    const float* Wk = (const float*)d_in[5];  const float* bk = (const float*)d_in[6];
    const float* Wc = (const float*)d_in[7];  const float* bc = (const float*)d_in[8];
    const float* Wh = (const float*)d_in[9];  const float* bh = (const float*)d_in[10];
    const float* keys   = (const float*)d_in[11];
    const float* pcodes = (const float*)d_in[12];
    const int*   step   = (const int*)d_in[13];

    float* out = (float*)d_out;
    float* o_states = out;
    float* o_epi    = out + (size_t)BN*Dd;
    float* o_sim    = out + (size_t)BN*Dd + (size_t)BN*Hh;

    whprep<<<(Dd*Hh)/256, 256>>>(Wh);
    proj_kernel<<<BN/32, 256>>>(actions, Wq, bq, Wk, bk, Wc, bc);

    cudaFuncSetAttribute(graph_kernel, cudaFuncAttributeMaxDynamicSharedMemorySize, G_TOT);
    graph_kernel<<<dim3(Nn/64, Bb), 256, G_TOT>>>(states);

    hdc_a<<<BN/64, 256>>>(o_states);

    cudaFuncSetAttribute(hdc_b, cudaFuncAttributeMaxDynamicSharedMemorySize, HB_TOT);
    hdc_b<<<dim3(BN/128, Hh/64), 256, HB_TOT>>>(episodic, bh, keys, pcodes, step, o_epi);

    hdc_c<<<BN/256, 256>>>(o_sim);
}

// round 7
// speedup vs baseline: 1.9937x; 1.0997x over previous
#include <cuda_runtime.h>
#include <cuda_bf16.h>
#include <cstdint>
#include <math.h>

#define Bb 4
#define Nn 4096
#define Dd 256
#define Pp 64
#define Hh 1024
#define NCc 256
#define BN (Bb*Nn)

// ---------------- device scratch ----------------
__device__ float g_Qf[(size_t)BN*64];
__device__ float g_Kf[(size_t)BN*64];
__device__ __nv_bfloat16 g_Qhi[(size_t)BN*64], g_Qlo[(size_t)BN*64];
__device__ __nv_bfloat16 g_Khi[(size_t)BN*64];
__device__ __nv_bfloat16 g_Phi[(size_t)BN*64], g_Plo[(size_t)BN*64];
__device__ __nv_bfloat16 g_WhhiT[(size_t)Hh*Dd], g_WhloT[(size_t)Hh*Dd];
__device__ __nv_bfloat16 g_Xhi[(size_t)BN*Dd], g_Xlo[(size_t)BN*Dd];
__device__ float g_INC[(size_t)BN*Dd];
__device__ float g_dot[BN], g_na[BN], g_nb[BN];
__device__ int   g_hitcnt[BN];
__device__ int   g_hitlist[BN*32];

// ---------------- helpers ----------------
__device__ __forceinline__ uint32_t smem_u32(const void* p){
    uint32_t a;
    asm("{ .reg .u64 t; cvta.to.shared.u64 t, %1; cvt.u32.u64 %0, t; }" : "=r"(a) : "l"(p));
    return a;
}
__device__ __forceinline__ void ldmA(uint32_t tile, int m0, int kc, int stride, uint32_t* a){
    int lane = threadIdx.x & 31;
    uint32_t addr = tile + (uint32_t)(m0 + (lane & 15))*stride + (uint32_t)kc*32 + ((lane >> 4)*16);
    asm volatile("ldmatrix.sync.aligned.m8n8.x4.shared.b16 {%0,%1,%2,%3}, [%4];"
        : "=r"(a[0]),"=r"(a[1]),"=r"(a[2]),"=r"(a[3]) : "r"(addr));
}
// x4 B-load: covers TWO n-tiles (n0..n0+7 and n0+8..n0+15) for one k16 chunk.
// b[0],b[1] = frag for nt at n0 ; b[2],b[3] = frag for nt at n0+8.
__device__ __forceinline__ void ldmB4(uint32_t tile, int n0, int kc, int stride, uint32_t* b){
    int lane = threadIdx.x & 31;
    int g = lane >> 3;
    uint32_t addr = tile + (uint32_t)(n0 + ((g & 2) ? 8 : 0) + (lane & 7))*stride
                  + (uint32_t)kc*32 + ((g & 1)*16);
    asm volatile("ldmatrix.sync.aligned.m8n8.x4.shared.b16 {%0,%1,%2,%3}, [%4];"
        : "=r"(b[0]),"=r"(b[1]),"=r"(b[2]),"=r"(b[3]) : "r"(addr));
}
__device__ __forceinline__ void mma16816(float* c, const uint32_t* a, const uint32_t* b){
    asm volatile("mma.sync.aligned.m16n8k16.row.col.f32.bf16.bf16.f32 "
        "{%0,%1,%2,%3}, {%4,%5,%6,%7}, {%8,%9}, {%0,%1,%2,%3};"
        : "+f"(c[0]),"+f"(c[1]),"+f"(c[2]),"+f"(c[3])
        : "r"(a[0]),"r"(a[1]),"r"(a[2]),"r"(a[3]), "r"(b[0]),"r"(b[1]));
}
#define CP_COMMIT() asm volatile("cp.async.commit_group;" ::: "memory")
#define CP_WAIT1()  asm volatile("cp.async.wait_group 1;" ::: "memory")
#define CP_WAIT0()  asm volatile("cp.async.wait_group 0;" ::: "memory")

#define UPD8(VV, II, MN, MP, val, col) do { \
    if ((val) > (MN)){ VV[MP] = (val); II[MP] = (col); MN = VV[0]; MP = 0; \
        _Pragma("unroll") for (int _q = 1; _q < 8; _q++) \
            if (VV[_q] < MN){ MN = VV[_q]; MP = _q; } } } while(0)

// ---------------- kernel 0: Wh transpose + split ----------------
__global__ __launch_bounds__(256) void whprep(const float* __restrict__ Wh){
    int idx = blockIdx.x*256 + threadIdx.x;
    int k = idx >> 10, n = idx & 1023;
    float w = Wh[idx];
    __nv_bfloat16 h = __float2bfloat16(w);
    g_WhhiT[(size_t)n*Dd + k] = h;
    g_WhloT[(size_t)n*Dd + k] = __float2bfloat16(w - __bfloat162float(h));
}

// ---------------- kernel 1: projections ----------------
__global__ __launch_bounds__(256) void proj_kernel(
    const float* __restrict__ actions,
    const float* __restrict__ Wq, const float* __restrict__ bq,
    const float* __restrict__ Wk, const float* __restrict__ bk,
    const float* __restrict__ Wc, const float* __restrict__ bc)
{
    __shared__ float As[32*Dd];
    __shared__ float invn[32];
    float* Qs = As;
    float* Ks = As + 32*65;
    float* Ps = As + 64*65;
    int tid = threadIdx.x;
    int row0 = blockIdx.x * 32;

    for (int idx = tid; idx < 32*Dd; idx += 256)
        As[idx] = actions[(size_t)row0*Dd + idx];
    __syncthreads();

    int p = tid & 63, g = tid >> 6;
    float aq[8], ak[8], ac[8];
#pragma unroll
    for (int i = 0; i < 8; i++){ aq[i]=0.f; ak[i]=0.f; ac[i]=0.f; }
    for (int d = 0; d < Dd; d++){
        float wq = Wq[d*Pp+p], wk = Wk[d*Pp+p], wc = Wc[d*Pp+p];
#pragma unroll
        for (int i = 0; i < 8; i++){
            float a = As[(g*8+i)*Dd + d];
            aq[i] = fmaf(a, wq, aq[i]);
            ak[i] = fmaf(a, wk, ak[i]);
            ac[i] = fmaf(a, wc, ac[i]);
        }
    }
    float vbq = bq[p], vbk = bk[p], vbc = bc[p];
    __syncthreads();
#pragma unroll
    for (int i = 0; i < 8; i++){
        int r = g*8+i;
        Qs[r*65+p] = aq[i]+vbq;
        Ks[r*65+p] = ak[i]+vbk;
        Ps[r*65+p] = ac[i]+vbc;
    }
    __syncthreads();
    if (tid < 32){
        float s = 0.f;
        for (int j = 0; j < 64; j++){ float v = Ps[tid*65+j]; s = fmaf(v,v,s); }
        invn[tid] = 1.0f / fmaxf(sqrtf(s), 1e-12f);
        g_hitcnt[row0 + tid] = 0;
    }
    __syncthreads();
    for (int idx = tid; idx < 32*64; idx += 256){
        int r = idx >> 6, pp = idx & 63;
        size_t o = (size_t)(row0 + r)*64 + pp;
        float q = Qs[r*65+pp], k = Ks[r*65+pp], pn = Ps[r*65+pp]*invn[r];
        g_Qf[o] = q; g_Kf[o] = k;
        __nv_bfloat16 qh = __float2bfloat16(q);
        g_Qhi[o] = qh; g_Qlo[o] = __float2bfloat16(q - __bfloat162float(qh));
        g_Khi[o] = __float2bfloat16(k);
        __nv_bfloat16 ph = __float2bfloat16(pn);
        g_Phi[o] = ph; g_Plo[o] = __float2bfloat16(pn - __bfloat162float(ph));
    }
}

// ---------------- kernel 2: graph (M=64 x N=128 tiles, 2-term split) -----
#define GSR 144
#define GA_QHI 0
#define GA_QLO 9216
#define GA_PHI 18432
#define GA_PLO 27648
#define GB 36864
#define GB_BUF 36864          // per buffer: KHI(18432) + PHI(18432)
#define GB_KHI 0
#define GB_PHI2 18432
#define G_TOT 110592
// post-mainloop aliases (inside A region, 36864 bytes)
#define G_CANDI 0             // 64*64*4 = 16384
#define G_MV 16384            // 8192
#define G_MI 24576            // 8192
#define G_TOPW 32768          // 2048
#define G_TOPI 34816          // 2048

__device__ __forceinline__ void cp_tile64(uint32_t sb, int dst, const __nv_bfloat16* src, int tid){
    const char* s = (const char*)src;
#pragma unroll
    for (int i = tid; i < 512; i += 256){
        int row = i >> 3, ch = i & 7;
        uint32_t d = sb + dst + row*GSR + ch*16;
        asm volatile("cp.async.cg.shared.global [%0], [%1], 16;" :: "r"(d), "l"(s + i*16));
    }
}
__device__ __forceinline__ void cp_tile128(uint32_t sb, int dst, const __nv_bfloat16* src, int tid){
    const char* s = (const char*)src;
#pragma unroll
    for (int i = tid; i < 1024; i += 256){
        int row = i >> 3, ch = i & 7;
        uint32_t d = sb + dst + row*GSR + ch*16;
        asm volatile("cp.async.cg.shared.global [%0], [%1], 16;" :: "r"(d), "l"(s + i*16));
    }
}

__global__ __launch_bounds__(256,2) void graph_kernel(const float* __restrict__ states)
{
    extern __shared__ char sm[];
    uint32_t sb = smem_u32(sm);
    int tid = threadIdx.x, wid = tid >> 5, lane = tid & 31;
    int bb = blockIdx.y, n0 = blockIdx.x * 64;
    size_t bofs = (size_t)bb*Nn*64;

    cp_tile64(sb, GA_QHI, g_Qhi + bofs + (size_t)n0*64, tid);
    cp_tile64(sb, GA_QLO, g_Qlo + bofs + (size_t)n0*64, tid);
    cp_tile64(sb, GA_PHI, g_Phi + bofs + (size_t)n0*64, tid);
    cp_tile64(sb, GA_PLO, g_Plo + bofs + (size_t)n0*64, tid);
    cp_tile128(sb, GB + GB_KHI,  g_Khi + bofs, tid);
    cp_tile128(sb, GB + GB_PHI2, g_Phi + bofs, tid);
    CP_COMMIT();
    {
        size_t mofs = bofs + (size_t)128*64;
        cp_tile128(sb, GB + GB_BUF + GB_KHI,  g_Khi + mofs, tid);
        cp_tile128(sb, GB + GB_BUF + GB_PHI2, g_Phi + mofs, tid);
        CP_COMMIT();
    }

    int wm = (wid & 3)*16, wn0 = (wid >> 2)*64, wng = wid >> 2;
    int rql = lane >> 2, cq = (lane & 3)*2, j4 = lane & 3;

    float v0[8], v1[8]; int i0[8], i1[8];
    float mn0 = -1e30f, mn1 = -1e30f; int mp0 = 0, mp1 = 0;
#pragma unroll
    for (int j = 0; j < 8; j++){ v0[j]=-1e30f; v1[j]=-1e30f; i0[j]=0; i1[j]=0; }

    for (int t = 0; t < Nn/128; t++){
        int buf = t & 1;
        if (t + 1 < Nn/128) CP_WAIT1(); else CP_WAIT0();
        __syncthreads();
        uint32_t bB = sb + GB + buf*GB_BUF;

        // ---- pass 1: scores = (Qhi+Qlo) . Khi ----
        float acc[8][4];
#pragma unroll
        for (int nt = 0; nt < 8; nt++)
#pragma unroll
            for (int e = 0; e < 4; e++) acc[nt][e] = 0.f;
#pragma unroll
        for (int kc = 0; kc < 4; kc++){
            uint32_t ah[4], al[4];
            ldmA(sb + GA_QHI, wm, kc, GSR, ah);
            ldmA(sb + GA_QLO, wm, kc, GSR, al);
            uint32_t bf[4][4];
#pragma unroll
            for (int p = 0; p < 4; p++) ldmB4(bB + GB_KHI, wn0 + p*16, kc, GSR, bf[p]);
#pragma unroll
            for (int nt = 0; nt < 8; nt++) mma16816(acc[nt], ah, &bf[nt>>1][(nt&1)*2]);
#pragma unroll
            for (int nt = 0; nt < 8; nt++) mma16816(acc[nt], al, &bf[nt>>1][(nt&1)*2]);
        }
        {
            float t0 = -1e30f, t1 = -1e30f;
#pragma unroll
            for (int nt = 0; nt < 8; nt++){
                t0 = fmaxf(t0, fmaxf(acc[nt][0], acc[nt][1]));
                t1 = fmaxf(t1, fmaxf(acc[nt][2], acc[nt][3]));
            }
            if (t0 > mn0){
#pragma unroll
                for (int nt = 0; nt < 8; nt++){
                    int cb = t*128 + wn0 + nt*8 + cq;
                    UPD8(v0, i0, mn0, mp0, acc[nt][0], cb);
                    UPD8(v0, i0, mn0, mp0, acc[nt][1], cb+1);
                }
            }
            if (t1 > mn1){
#pragma unroll
                for (int nt = 0; nt < 8; nt++){
                    int cb = t*128 + wn0 + nt*8 + cq;
                    UPD8(v1, i1, mn1, mp1, acc[nt][2], cb);
                    UPD8(v1, i1, mn1, mp1, acc[nt][3], cb+1);
                }
            }
        }

        // ---- pass 2: sim = (Phi+Plo) . Phi ----
#pragma unroll
        for (int nt = 0; nt < 8; nt++)
#pragma unroll
            for (int e = 0; e < 4; e++) acc[nt][e] = 0.f;
#pragma unroll
        for (int kc = 0; kc < 4; kc++){
            uint32_t ah[4], al[4];
            ldmA(sb + GA_PHI, wm, kc, GSR, ah);
            ldmA(sb + GA_PLO, wm, kc, GSR, al);
            uint32_t bf[4][4];
#pragma unroll
            for (int p = 0; p < 4; p++) ldmB4(bB + GB_PHI2, wn0 + p*16, kc, GSR, bf[p]);
#pragma unroll
            for (int nt = 0; nt < 8; nt++) mma16816(acc[nt], ah, &bf[nt>>1][(nt&1)*2]);
#pragma unroll
            for (int nt = 0; nt < 8; nt++) mma16816(acc[nt], al, &bf[nt>>1][(nt&1)*2]);
        }
#pragma unroll
        for (int nt = 0; nt < 8; nt++)
#pragma unroll
            for (int e = 0; e < 4; e++){
                if (acc[nt][e] > 0.7f){
                    int row = n0 + wm + rql + ((e >= 2) ? 8 : 0);
                    int col = t*128 + wn0 + nt*8 + cq + (e & 1);
                    int hidx = bb*Nn + row;
                    int slot = atomicAdd(&g_hitcnt[hidx], 1);
                    if (slot < 32) g_hitlist[(size_t)hidx*32 + slot] = col;
                }
            }
        __syncthreads();

        if (t + 2 < Nn/128){
            size_t mofs = bofs + (size_t)(t+2)*128*64;
            cp_tile128(sb, GB + buf*GB_BUF + GB_KHI,  g_Khi + mofs, tid);
            cp_tile128(sb, GB + buf*GB_BUF + GB_PHI2, g_Phi + mofs, tid);
            CP_COMMIT();
        }
    }
    __syncthreads();

    // ---- dump candidates: 8 slices/row x 8 = 64 candidates ----
    int* candI = (int*)(sm + G_CANDI);
    {
        int r0 = wm + rql, r1 = wm + rql + 8;
        int slice = wng*4 + j4;
#pragma unroll
        for (int s = 0; s < 8; s++){
            candI[r0*64 + slice*8 + s] = i0[s];
            candI[r1*64 + slice*8 + s] = i1[s];
        }
    }
    __syncthreads();

    // ---- exact fp32 rescore: 4 threads/row x 16 candidates ----
    float* mergeV = (float*)(sm + G_MV);
    int*   mergeI = (int*)(sm + G_MI);
    {
        int row = tid >> 2, sub = tid & 3;
        const float4* Q4 = (const float4*)(g_Qf + bofs + (size_t)(n0 + row)*64);
        float q[64];
#pragma unroll
        for (int i = 0; i < 16; i++){
            float4 v = Q4[i];
            q[4*i] = v.x; q[4*i+1] = v.y; q[4*i+2] = v.z; q[4*i+3] = v.w;
        }
        float tv[8]; int ti8[8]; float tmn = -1e30f; int tmp = 0;
#pragma unroll
        for (int j = 0; j < 8; j++){ tv[j] = -1e30f; ti8[j] = 0; }
#pragma unroll
        for (int c = 0; c < 16; c++){
            int col = candI[row*64 + sub*16 + c];
            const float4* K4 = (const float4*)(g_Kf + bofs + (size_t)col*64);
            float a2 = 0.f;
#pragma unroll
            for (int i = 0; i < 16; i++){
                float4 kv = K4[i];
                a2 = fmaf(q[4*i],   kv.x, a2);
                a2 = fmaf(q[4*i+1], kv.y, a2);
                a2 = fmaf(q[4*i+2], kv.z, a2);
                a2 = fmaf(q[4*i+3], kv.w, a2);
            }
            a2 *= 0.125f;
            UPD8(tv, ti8, tmn, tmp, a2, col);
        }
#pragma unroll
        for (int s = 0; s < 8; s++){
            mergeV[row*32 + sub*8 + s] = tv[s];
            mergeI[row*32 + sub*8 + s] = ti8[s];
        }
    }
    __syncthreads();

    // ---- final merge + softmax (64 threads) ----
    float* topW = (float*)(sm + G_TOPW);
    int*   topI = (int*)(sm + G_TOPI);
    if (tid < 64){
        float tv[8]; int ti8[8]; float tmn = -1e30f; int tmp = 0;
#pragma unroll
        for (int j = 0; j < 8; j++){ tv[j] = -1e30f; ti8[j] = 0; }
#pragma unroll
        for (int c = 0; c < 32; c++){
            UPD8(tv, ti8, tmn, tmp, mergeV[tid*32 + c], mergeI[tid*32 + c]);
        }
        float mx = tv[0];
#pragma unroll
        for (int j = 1; j < 8; j++) mx = fmaxf(mx, tv[j]);
        float e[8], ssum = 0.f;
#pragma unroll
        for (int j = 0; j < 8; j++){ e[j] = __expf(tv[j] - mx); ssum += e[j]; }
        float inv = 1.f / ssum;
#pragma unroll
        for (int j = 0; j < 8; j++){ topW[tid*8+j] = e[j]*inv; topI[tid*8+j] = ti8[j]; }
    }
    __syncthreads();

    // ---- gather incoming (8 warps x 8 rows) ----
    const float* Sb = states + (size_t)bb*Nn*Dd;
    for (int rr = 0; rr < 8; rr++){
        int r = wid*8 + rr;
        float w8[8]; int i8[8];
#pragma unroll
        for (int j = 0; j < 8; j++){ w8[j] = topW[r*8+j]; i8[j] = topI[r*8+j]; }
        float* Ig = g_INC + ((size_t)bb*Nn + n0 + r)*Dd;
#pragma unroll
        for (int dd = 0; dd < 8; dd++){
            int d = lane + dd*32;
            float a2 = 0.f;
#pragma unroll
            for (int j = 0; j < 8; j++) a2 = fmaf(w8[j], Sb[(size_t)i8[j]*Dd + d], a2);
            Ig[d] = a2;
        }
    }
}

// ---------------- kernel 3a: phase-1 gather + X split ----------------
__global__ __launch_bounds__(256) void hdc_a(float* __restrict__ out_states){
    int tid = threadIdx.x, wid = tid >> 5, lane = tid & 31;
    int row0 = blockIdx.x * 64;
    int bb = row0 / Nn;
    for (int r8 = 0; r8 < 8; r8++){
        int row = row0 + wid*8 + r8;
        int cnt = g_hitcnt[row];
        int lim = cnt < 32 ? cnt : 32;
        const int* hl = g_hitlist + (size_t)row*32;
        float comb[8];
#pragma unroll
        for (int i = 0; i < 8; i++) comb[i] = 0.f;
        for (int j = 0; j < lim; j++){
            const float* src = g_INC + ((size_t)bb*Nn + hl[j])*Dd;
#pragma unroll
            for (int i = 0; i < 8; i++) comb[i] += src[lane + i*32];
        }
        const float* inc = g_INC + (size_t)row*Dd;
        float inv = 0.2f / ((float)cnt + 1e-8f);
#pragma unroll
        for (int i = 0; i < 8; i++){
            int d = lane + i*32;
            float ov = 0.8f*inc[d] + comb[i]*inv;
            out_states[(size_t)row*Dd + d] = ov;
            __nv_bfloat16 h = __float2bfloat16(ov);
            g_Xhi[(size_t)row*Dd + d] = h;
            g_Xlo[(size_t)row*Dd + d] = __float2bfloat16(ov - __bfloat162float(h));
        }
    }
    if (tid < 64){
        g_dot[row0+tid] = 0.f; g_na[row0+tid] = 0.f; g_nb[row0+tid] = 0.f;
    }
}

// ---------------- kernel 3b: Wh GEMM + fused episodic ----------------
#define SR 144
#define HB_AH0 0
#define HB_AL0 18432
#define HB_AH1 36864
#define HB_AL1 55296
#define HB_BH0 73728
#define HB_BL0 82944
#define HB_BH1 92160
#define HB_BL1 101376
#define HB_TOT 110592

__device__ __forceinline__ void cp_rows(uint32_t sb, int dst, const __nv_bfloat16* src,
                                        int nrows, size_t srcstride, int tid){
    int total = nrows*8;
    for (int i = tid; i < total; i += 256){
        int row = i >> 3, ch = i & 7;
        uint32_t d = sb + dst + row*SR + ch*16;
        const char* s = (const char*)(src + (size_t)row*srcstride) + ch*16;
        asm volatile("cp.async.cg.shared.global [%0], [%1], 16;" :: "r"(d), "l"(s));
    }
}

__global__ __launch_bounds__(256,2) void hdc_b(
    const float* __restrict__ episodic,
    const float* __restrict__ bh,
    const float* __restrict__ keys, const float* __restrict__ pcodes,
    const int* __restrict__ step,
    float* __restrict__ out_epi)
{
    extern __shared__ char sm[];
    uint32_t sb = smem_u32(sm);
    int tid = threadIdx.x, wid = tid >> 5, lane = tid & 31;
    int row0 = blockIdx.x * 128;
    int c0   = blockIdx.y * 64;
    int prow = ((step[0] % NCc) + NCc) % NCc;
    const float* posr = pcodes + (size_t)prow*Hh;

    const __nv_bfloat16* Xh = g_Xhi + (size_t)row0*Dd;
    const __nv_bfloat16* Xl = g_Xlo + (size_t)row0*Dd;
    const __nv_bfloat16* Wh = g_WhhiT + (size_t)c0*Dd;
    const __nv_bfloat16* Wl = g_WhloT + (size_t)c0*Dd;

    cp_rows(sb, HB_AH0, Xh,       128, Dd, tid);
    cp_rows(sb, HB_AL0, Xl,       128, Dd, tid);
    cp_rows(sb, HB_BH0, Wh,       64,  Dd, tid);
    cp_rows(sb, HB_BL0, Wl,       64,  Dd, tid);
    CP_COMMIT();
    cp_rows(sb, HB_AH1, Xh + 64,  128, Dd, tid);
    cp_rows(sb, HB_AL1, Xl + 64,  128, Dd, tid);
    cp_rows(sb, HB_BH1, Wh + 64,  64,  Dd, tid);
    cp_rows(sb, HB_BL1, Wl + 64,  64,  Dd, tid);
    CP_COMMIT();

    int wm = wid*16;
    int rql = lane >> 2, cq = (lane & 3)*2, j4 = lane & 3;

    float acc[8][4];
#pragma unroll
    for (int nt = 0; nt < 8; nt++)
#pragma unroll
        for (int e = 0; e < 4; e++) acc[nt][e] = 0.f;

    for (int c = 0; c < 4; c++){
        int buf = c & 1;
        if (c + 1 < 4) CP_WAIT1(); else CP_WAIT0();
        __syncthreads();
        uint32_t aH = sb + (buf ? HB_AH1 : HB_AH0);
        uint32_t aL = sb + (buf ? HB_AL1 : HB_AL0);
        uint32_t bH = sb + (buf ? HB_BH1 : HB_BH0);
        uint32_t bL = sb + (buf ? HB_BL1 : HB_BL0);
#pragma unroll
        for (int kc = 0; kc < 4; kc++){
            uint32_t ah[4], al[4];
            ldmA(aH, wm, kc, SR, ah);
            ldmA(aL, wm, kc, SR, al);
            uint32_t bfh[4][4], bfl[4][4];
#pragma unroll
            for (int p = 0; p < 4; p++){
                ldmB4(bH, p*16, kc, SR, bfh[p]);
                ldmB4(bL, p*16, kc, SR, bfl[p]);
            }
#pragma unroll
            for (int nt = 0; nt < 8; nt++) mma16816(acc[nt], ah, &bfh[nt>>1][(nt&1)*2]);
#pragma unroll
            for (int nt = 0; nt < 8; nt++) mma16816(acc[nt], ah, &bfl[nt>>1][(nt&1)*2]);
#pragma unroll
            for (int nt = 0; nt < 8; nt++) mma16816(acc[nt], al, &bfh[nt>>1][(nt&1)*2]);
        }
        __syncthreads();
        if (c + 2 < 4){
            int koff = (c+2)*64;
            cp_rows(sb, buf ? HB_AH1 : HB_AH0, Xh + koff, 128, Dd, tid);
            cp_rows(sb, buf ? HB_AL1 : HB_AL0, Xl + koff, 128, Dd, tid);
            cp_rows(sb, buf ? HB_BH1 : HB_BH0, Wh + koff, 64,  Dd, tid);
            cp_rows(sb, buf ? HB_BL1 : HB_BL0, Wl + koff, 64,  Dd, tid);
            CP_COMMIT();
        }
    }

    float d0 = 0.f, a0 = 0.f, b0 = 0.f;
    float d1 = 0.f, a1 = 0.f, b1 = 0.f;
    int grow0 = row0 + wm + rql, grow1 = grow0 + 8;
    int n0k = grow0 & (Nn-1), n1k = grow1 & (Nn-1);
#pragma unroll
    for (int nt = 0; nt < 8; nt++){
        int col = c0 + nt*8 + cq;
        float bh0 = __ldg(bh + col), bh1v = __ldg(bh + col + 1);
        float p0c = __ldg(posr + col), p1c = __ldg(posr + col + 1);
        {
            float y0 = 6.0f*(acc[nt][0] + bh0);
            float y1 = 6.0f*(acc[nt][1] + bh1v);
            float h0 = 1.0f - 2.0f/(__expf(y0) + 1.0f);
            float h1 = 1.0f - 2.0f/(__expf(y1) + 1.0f);
            float2 ky = *(const float2*)(keys + (size_t)n0k*Hh + col);
            float pe0 = h0*ky.x, pe1 = h1*ky.y;
            float2 ep = *(const float2*)(episodic + (size_t)grow0*Hh + col);
            float ne0 = 0.95f*ep.x + 0.05f*pe0*p0c;
            float ne1 = 0.95f*ep.y + 0.05f*pe1*p1c;
            *(float2*)(out_epi + (size_t)grow0*Hh + col) = make_float2(ne0, ne1);
            d0 = fmaf(ne0, pe0, fmaf(ne1, pe1, d0));
            a0 = fmaf(ne0, ne0, fmaf(ne1, ne1, a0));
            b0 = fmaf(pe0, pe0, fmaf(pe1, pe1, b0));
        }
        {
            float y0 = 6.0f*(acc[nt][2] + bh0);
            float y1 = 6.0f*(acc[nt][3] + bh1v);
            float h0 = 1.0f - 2.0f/(__expf(y0) + 1.0f);
            float h1 = 1.0f - 2.0f/(__expf(y1) + 1.0f);
            float2 ky = *(const float2*)(keys + (size_t)n1k*Hh + col);
            float pe0 = h0*ky.x, pe1 = h1*ky.y;
            float2 ep = *(const float2*)(episodic + (size_t)grow1*Hh + col);
            float ne0 = 0.95f*ep.x + 0.05f*pe0*p0c;
            float ne1 = 0.95f*ep.y + 0.05f*pe1*p1c;
            *(float2*)(out_epi + (size_t)grow1*Hh + col) = make_float2(ne0, ne1);
            d1 = fmaf(ne0, pe0, fmaf(ne1, pe1, d1));
            a1 = fmaf(ne0, ne0, fmaf(ne1, ne1, a1));
            b1 = fmaf(pe0, pe0, fmaf(pe1, pe1, b1));
        }
    }
#pragma unroll
    for (int off = 1; off <= 2; off <<= 1){
        d0 += __shfl_xor_sync(0xffffffffu, d0, off);
        a0 += __shfl_xor_sync(0xffffffffu, a0, off);
        b0 += __shfl_xor_sync(0xffffffffu, b0, off);
        d1 += __shfl_xor_sync(0xffffffffu, d1, off);
        a1 += __shfl_xor_sync(0xffffffffu, a1, off);
        b1 += __shfl_xor_sync(0xffffffffu, b1, off);
    }
    if (j4 == 0){
        atomicAdd(&g_dot[grow0], d0); atomicAdd(&g_na[grow0], a0); atomicAdd(&g_nb[grow0], b0);
        atomicAdd(&g_dot[grow1], d1); atomicAdd(&g_na[grow1], a1); atomicAdd(&g_nb[grow1], b1);
    }
}

// ---------------- kernel 3c: out_sim finisher ----------------
__global__ __launch_bounds__(256) void hdc_c(float* __restrict__ out_sim){
    int i = blockIdx.x*256 + threadIdx.x;
    out_sim[i] = g_dot[i] / (fmaxf(sqrtf(g_na[i]), 1e-8f)*fmaxf(sqrtf(g_nb[i]), 1e-8f));
}

// ---------------- launch ----------------
extern "C" void kernel_launch(void* const* d_in, const int* in_sizes, int n_in,
                              void* d_out, int out_size)
{
    (void)in_sizes; (void)n_in; (void)out_size;
    const float* states   = (const float*)d_in[0];
    const float* actions  = (const float*)d_in[1];
    const float* episodic = (const float*)d_in[2];
    const float* Wq = (const float*)d_in[3];  const float* bq = (const float*)d_in[4];
    const float* Wk = (const float*)d_in[5];  const float* bk = (const float*)d_in[6];
    const float* Wc = (const float*)d_in[7];  const float* bc = (const float*)d_in[8];
    const float* Wh = (const float*)d_in[9];  const float* bh = (const float*)d_in[10];
    const float* keys   = (const float*)d_in[11];
    const float* pcodes = (const float*)d_in[12];
    const int*   step   = (const int*)d_in[13];

    float* out = (float*)d_out;
    float* o_states = out;
    float* o_epi    = out + (size_t)BN*Dd;
    float* o_sim    = out + (size_t)BN*Dd + (size_t)BN*Hh;

    whprep<<<(Dd*Hh)/256, 256>>>(Wh);
    proj_kernel<<<BN/32, 256>>>(actions, Wq, bq, Wk, bk, Wc, bc);

    cudaFuncSetAttribute(graph_kernel, cudaFuncAttributeMaxDynamicSharedMemorySize, G_TOT);
    graph_kernel<<<dim3(Nn/64, Bb), 256, G_TOT>>>(states);

    hdc_a<<<BN/64, 256>>>(o_states);

    cudaFuncSetAttribute(hdc_b, cudaFuncAttributeMaxDynamicSharedMemorySize, HB_TOT);
    hdc_b<<<dim3(BN/128, Hh/64), 256, HB_TOT>>>(episodic, bh, keys, pcodes, step, o_epi);

    hdc_c<<<BN/256, 256>>>(o_sim);
}

// round 8
// speedup vs baseline: 2.5260x; 1.2670x over previous
#include <cuda_runtime.h>
#include <cuda_fp16.h>
#include <cstdint>
#include <math.h>

#define Bb 4
#define Nn 4096
#define Dd 256
#define Pp 64
#define Hh 1024
#define NCc 256
#define BN (Bb*Nn)

// ---------------- device scratch ----------------
__device__ float g_Qf[(size_t)BN*64];
__device__ float g_Kf[(size_t)BN*64];
__device__ __half g_Qh[(size_t)BN*64];
__device__ __half g_Kh[(size_t)BN*64];
__device__ __half g_Ph[(size_t)BN*64];
__device__ __half g_WhT[(size_t)Hh*Dd];
__device__ __half g_Xhi[(size_t)BN*Dd], g_Xlo[(size_t)BN*Dd];
__device__ float g_INC[(size_t)BN*Dd];
__device__ float g_dot[BN], g_na[BN], g_nb[BN];
__device__ int   g_hitcnt[BN];
__device__ int   g_hitlist[BN*32];

// ---------------- helpers ----------------
__device__ __forceinline__ uint32_t smem_u32(const void* p){
    uint32_t a;
    asm("{ .reg .u64 t; cvta.to.shared.u64 t, %1; cvt.u32.u64 %0, t; }" : "=r"(a) : "l"(p));
    return a;
}
__device__ __forceinline__ void ldmA(uint32_t tile, int m0, int kc, int stride, uint32_t* a){
    int lane = threadIdx.x & 31;
    uint32_t addr = tile + (uint32_t)(m0 + (lane & 15))*stride + (uint32_t)kc*32 + ((lane >> 4)*16);
    asm volatile("ldmatrix.sync.aligned.m8n8.x4.shared.b16 {%0,%1,%2,%3}, [%4];"
        : "=r"(a[0]),"=r"(a[1]),"=r"(a[2]),"=r"(a[3]) : "r"(addr));
}
// x4 B-load: two n-tiles (n0..n0+7, n0+8..n0+15) for one k16 chunk.
__device__ __forceinline__ void ldmB4(uint32_t tile, int n0, int kc, int stride, uint32_t* b){
    int lane = threadIdx.x & 31;
    int g = lane >> 3;
    uint32_t addr = tile + (uint32_t)(n0 + ((g & 2) ? 8 : 0) + (lane & 7))*stride
                  + (uint32_t)kc*32 + ((g & 1)*16);
    asm volatile("ldmatrix.sync.aligned.m8n8.x4.shared.b16 {%0,%1,%2,%3}, [%4];"
        : "=r"(b[0]),"=r"(b[1]),"=r"(b[2]),"=r"(b[3]) : "r"(addr));
}
__device__ __forceinline__ void mma_h(float* c, const uint32_t* a, const uint32_t* b){
    asm volatile("mma.sync.aligned.m16n8k16.row.col.f32.f16.f16.f32 "
        "{%0,%1,%2,%3}, {%4,%5,%6,%7}, {%8,%9}, {%0,%1,%2,%3};"
        : "+f"(c[0]),"+f"(c[1]),"+f"(c[2]),"+f"(c[3])
        : "r"(a[0]),"r"(a[1]),"r"(a[2]),"r"(a[3]), "r"(b[0]),"r"(b[1]));
}
#define CP_COMMIT() asm volatile("cp.async.commit_group;" ::: "memory")
#define CP_WAIT1()  asm volatile("cp.async.wait_group 1;" ::: "memory")
#define CP_WAIT0()  asm volatile("cp.async.wait_group 0;" ::: "memory")

#define UPD8(VV, II, MN, MP, val, col) do { \
    if ((val) > (MN)){ VV[MP] = (val); II[MP] = (col); MN = VV[0]; MP = 0; \
        _Pragma("unroll") for (int _q = 1; _q < 8; _q++) \
            if (VV[_q] < MN){ MN = VV[_q]; MP = _q; } } } while(0)

// ---------------- kernel 0: Wh transpose (fp16) ----------------
__global__ __launch_bounds__(256) void whprep(const float* __restrict__ Wh){
    int idx = blockIdx.x*256 + threadIdx.x;
    int k = idx >> 10, n = idx & 1023;
    g_WhT[(size_t)n*Dd + k] = __float2half(Wh[idx]);
}

// ---------------- kernel 1: projections ----------------
__global__ __launch_bounds__(256) void proj_kernel(
    const float* __restrict__ actions,
    const float* __restrict__ Wq, const float* __restrict__ bq,
    const float* __restrict__ Wk, const float* __restrict__ bk,
    const float* __restrict__ Wc, const float* __restrict__ bc)
{
    __shared__ float As[32*Dd];
    __shared__ float invn[32];
    float* Qs = As;
    float* Ks = As + 32*65;
    float* Ps = As + 64*65;
    int tid = threadIdx.x;
    int row0 = blockIdx.x * 32;

    for (int idx = tid; idx < 32*Dd; idx += 256)
        As[idx] = actions[(size_t)row0*Dd + idx];
    __syncthreads();

    int p = tid & 63, g = tid >> 6;
    float aq[8], ak[8], ac[8];
#pragma unroll
    for (int i = 0; i < 8; i++){ aq[i]=0.f; ak[i]=0.f; ac[i]=0.f; }
    for (int d = 0; d < Dd; d++){
        float wq = Wq[d*Pp+p], wk = Wk[d*Pp+p], wc = Wc[d*Pp+p];
#pragma unroll
        for (int i = 0; i < 8; i++){
            float a = As[(g*8+i)*Dd + d];
            aq[i] = fmaf(a, wq, aq[i]);
            ak[i] = fmaf(a, wk, ak[i]);
            ac[i] = fmaf(a, wc, ac[i]);
        }
    }
    float vbq = bq[p], vbk = bk[p], vbc = bc[p];
    __syncthreads();
#pragma unroll
    for (int i = 0; i < 8; i++){
        int r = g*8+i;
        Qs[r*65+p] = aq[i]+vbq;
        Ks[r*65+p] = ak[i]+vbk;
        Ps[r*65+p] = ac[i]+vbc;
    }
    __syncthreads();
    if (tid < 32){
        float s = 0.f;
        for (int j = 0; j < 64; j++){ float v = Ps[tid*65+j]; s = fmaf(v,v,s); }
        invn[tid] = 1.0f / fmaxf(sqrtf(s), 1e-12f);
        g_hitcnt[row0 + tid] = 0;
    }
    __syncthreads();
    for (int idx = tid; idx < 32*64; idx += 256){
        int r = idx >> 6, pp = idx & 63;
        size_t o = (size_t)(row0 + r)*64 + pp;
        float q = Qs[r*65+pp], k = Ks[r*65+pp], pn = Ps[r*65+pp]*invn[r];
        g_Qf[o] = q; g_Kf[o] = k;
        g_Qh[o] = __float2half(q);
        g_Kh[o] = __float2half(k);
        g_Ph[o] = __float2half(pn);
    }
}

// ---------------- kernel 2: graph (fp16 single-term) ----------------
#define GSR 144
#define GA_QH 0
#define GA_PH 9216
#define GB 18432
#define GB_BUF 36864          // per buffer: Kh(18432) + Ph(18432)
#define GB_KH 0
#define GB_PH 18432
#define G_TOT 92160
// post-mainloop aliases
#define G_CANDI 0             // 16384
#define G_MV 16384            // 8192
#define G_MI 24576            // 8192
#define G_TOPW 32768          // 2048
#define G_TOPI 34816          // 2048

__device__ __forceinline__ void cp_tile64(uint32_t sb, int dst, const __half* src, int tid){
    const char* s = (const char*)src;
#pragma unroll
    for (int i = tid; i < 512; i += 256){
        int row = i >> 3, ch = i & 7;
        uint32_t d = sb + dst + row*GSR + ch*16;
        asm volatile("cp.async.cg.shared.global [%0], [%1], 16;" :: "r"(d), "l"(s + i*16));
    }
}
__device__ __forceinline__ void cp_tile128(uint32_t sb, int dst, const __half* src, int tid){
    const char* s = (const char*)src;
#pragma unroll
    for (int i = tid; i < 1024; i += 256){
        int row = i >> 3, ch = i & 7;
        uint32_t d = sb + dst + row*GSR + ch*16;
        asm volatile("cp.async.cg.shared.global [%0], [%1], 16;" :: "r"(d), "l"(s + i*16));
    }
}

__global__ __launch_bounds__(256,2) void graph_kernel(const float* __restrict__ states)
{
    extern __shared__ char sm[];
    uint32_t sb = smem_u32(sm);
    int tid = threadIdx.x, wid = tid >> 5, lane = tid & 31;
    int bb = blockIdx.y, n0 = blockIdx.x * 64;
    size_t bofs = (size_t)bb*Nn*64;

    cp_tile64(sb, GA_QH, g_Qh + bofs + (size_t)n0*64, tid);
    cp_tile64(sb, GA_PH, g_Ph + bofs + (size_t)n0*64, tid);
    cp_tile128(sb, GB + GB_KH, g_Kh + bofs, tid);
    cp_tile128(sb, GB + GB_PH, g_Ph + bofs, tid);
    CP_COMMIT();
    {
        size_t mofs = bofs + (size_t)128*64;
        cp_tile128(sb, GB + GB_BUF + GB_KH, g_Kh + mofs, tid);
        cp_tile128(sb, GB + GB_BUF + GB_PH, g_Ph + mofs, tid);
        CP_COMMIT();
    }

    int wm = (wid & 3)*16, wn0 = (wid >> 2)*64, wng = wid >> 2;
    int rql = lane >> 2, cq = (lane & 3)*2, j4 = lane & 3;

    float v0[8], v1[8]; int i0[8], i1[8];
    float mn0 = -1e30f, mn1 = -1e30f; int mp0 = 0, mp1 = 0;
#pragma unroll
    for (int j = 0; j < 8; j++){ v0[j]=-1e30f; v1[j]=-1e30f; i0[j]=0; i1[j]=0; }

    for (int t = 0; t < Nn/128; t++){
        int buf = t & 1;
        if (t + 1 < Nn/128) CP_WAIT1(); else CP_WAIT0();
        __syncthreads();
        uint32_t bB = sb + GB + buf*GB_BUF;

        // ---- pass 1: scores = Qh . Kh ----
        float acc[8][4];
#pragma unroll
        for (int nt = 0; nt < 8; nt++)
#pragma unroll
            for (int e = 0; e < 4; e++) acc[nt][e] = 0.f;
#pragma unroll
        for (int kc = 0; kc < 4; kc++){
            uint32_t ah[4];
            ldmA(sb + GA_QH, wm, kc, GSR, ah);
            uint32_t bf[4][4];
#pragma unroll
            for (int p = 0; p < 4; p++) ldmB4(bB + GB_KH, wn0 + p*16, kc, GSR, bf[p]);
#pragma unroll
            for (int nt = 0; nt < 8; nt++) mma_h(acc[nt], ah, &bf[nt>>1][(nt&1)*2]);
        }
        {
            float t0 = -1e30f, t1 = -1e30f;
#pragma unroll
            for (int nt = 0; nt < 8; nt++){
                t0 = fmaxf(t0, fmaxf(acc[nt][0], acc[nt][1]));
                t1 = fmaxf(t1, fmaxf(acc[nt][2], acc[nt][3]));
            }
            if (t0 > mn0){
#pragma unroll
                for (int nt = 0; nt < 8; nt++){
                    int cb = t*128 + wn0 + nt*8 + cq;
                    UPD8(v0, i0, mn0, mp0, acc[nt][0], cb);
                    UPD8(v0, i0, mn0, mp0, acc[nt][1], cb+1);
                }
            }
            if (t1 > mn1){
#pragma unroll
                for (int nt = 0; nt < 8; nt++){
                    int cb = t*128 + wn0 + nt*8 + cq;
                    UPD8(v1, i1, mn1, mp1, acc[nt][2], cb);
                    UPD8(v1, i1, mn1, mp1, acc[nt][3], cb+1);
                }
            }
        }

        // ---- pass 2: sim = Ph . Ph ----
#pragma unroll
        for (int nt = 0; nt < 8; nt++)
#pragma unroll
            for (int e = 0; e < 4; e++) acc[nt][e] = 0.f;
#pragma unroll
        for (int kc = 0; kc < 4; kc++){
            uint32_t ah[4];
            ldmA(sb + GA_PH, wm, kc, GSR, ah);
            uint32_t bf[4][4];
#pragma unroll
            for (int p = 0; p < 4; p++) ldmB4(bB + GB_PH, wn0 + p*16, kc, GSR, bf[p]);
#pragma unroll
            for (int nt = 0; nt < 8; nt++) mma_h(acc[nt], ah, &bf[nt>>1][(nt&1)*2]);
        }
#pragma unroll
        for (int nt = 0; nt < 8; nt++)
#pragma unroll
            for (int e = 0; e < 4; e++){
                if (acc[nt][e] > 0.7f){
                    int row = n0 + wm + rql + ((e >= 2) ? 8 : 0);
                    int col = t*128 + wn0 + nt*8 + cq + (e & 1);
                    int hidx = bb*Nn + row;
                    int slot = atomicAdd(&g_hitcnt[hidx], 1);
                    if (slot < 32) g_hitlist[(size_t)hidx*32 + slot] = col;
                }
            }
        __syncthreads();

        if (t + 2 < Nn/128){
            size_t mofs = bofs + (size_t)(t+2)*128*64;
            cp_tile128(sb, GB + buf*GB_BUF + GB_KH, g_Kh + mofs, tid);
            cp_tile128(sb, GB + buf*GB_BUF + GB_PH, g_Ph + mofs, tid);
            CP_COMMIT();
        }
    }
    __syncthreads();

    // ---- dump candidates: 8 slices/row x 8 = 64 per row ----
    int* candI = (int*)(sm + G_CANDI);
    {
        int r0 = wm + rql, r1 = wm + rql + 8;
        int slice = wng*4 + j4;
#pragma unroll
        for (int s = 0; s < 8; s++){
            candI[r0*64 + slice*8 + s] = i0[s];
            candI[r1*64 + slice*8 + s] = i1[s];
        }
    }
    __syncthreads();

    // ---- exact fp32 rescore: 4 threads/row x 16 candidates ----
    float* mergeV = (float*)(sm + G_MV);
    int*   mergeI = (int*)(sm + G_MI);
    {
        int row = tid >> 2, sub = tid & 3;
        const float4* Q4 = (const float4*)(g_Qf + bofs + (size_t)(n0 + row)*64);
        float q[64];
#pragma unroll
        for (int i = 0; i < 16; i++){
            float4 v = Q4[i];
            q[4*i] = v.x; q[4*i+1] = v.y; q[4*i+2] = v.z; q[4*i+3] = v.w;
        }
        float tv[8]; int ti8[8]; float tmn = -1e30f; int tmp = 0;
#pragma unroll
        for (int j = 0; j < 8; j++){ tv[j] = -1e30f; ti8[j] = 0; }
#pragma unroll
        for (int c = 0; c < 16; c++){
            int col = candI[row*64 + sub*16 + c];
            const float4* K4 = (const float4*)(g_Kf + bofs + (size_t)col*64);
            float a2 = 0.f;
#pragma unroll
            for (int i = 0; i < 16; i++){
                float4 kv = K4[i];
                a2 = fmaf(q[4*i],   kv.x, a2);
                a2 = fmaf(q[4*i+1], kv.y, a2);
                a2 = fmaf(q[4*i+2], kv.z, a2);
                a2 = fmaf(q[4*i+3], kv.w, a2);
            }
            a2 *= 0.125f;
            UPD8(tv, ti8, tmn, tmp, a2, col);
        }
#pragma unroll
        for (int s = 0; s < 8; s++){
            mergeV[row*32 + sub*8 + s] = tv[s];
            mergeI[row*32 + sub*8 + s] = ti8[s];
        }
    }
    __syncthreads();

    // ---- final merge + softmax (64 threads) ----
    float* topW = (float*)(sm + G_TOPW);
    int*   topI = (int*)(sm + G_TOPI);
    if (tid < 64){
        float tv[8]; int ti8[8]; float tmn = -1e30f; int tmp = 0;
#pragma unroll
        for (int j = 0; j < 8; j++){ tv[j] = -1e30f; ti8[j] = 0; }
#pragma unroll
        for (int c = 0; c < 32; c++){
            UPD8(tv, ti8, tmn, tmp, mergeV[tid*32 + c], mergeI[tid*32 + c]);
        }
        float mx = tv[0];
#pragma unroll
        for (int j = 1; j < 8; j++) mx = fmaxf(mx, tv[j]);
        float e[8], ssum = 0.f;
#pragma unroll
        for (int j = 0; j < 8; j++){ e[j] = __expf(tv[j] - mx); ssum += e[j]; }
        float inv = 1.f / ssum;
#pragma unroll
        for (int j = 0; j < 8; j++){ topW[tid*8+j] = e[j]*inv; topI[tid*8+j] = ti8[j]; }
    }
    __syncthreads();

    // ---- gather incoming (8 warps x 8 rows) ----
    const float* Sb = states + (size_t)bb*Nn*Dd;
    for (int rr = 0; rr < 8; rr++){
        int r = wid*8 + rr;
        float w8[8]; int i8[8];
#pragma unroll
        for (int j = 0; j < 8; j++){ w8[j] = topW[r*8+j]; i8[j] = topI[r*8+j]; }
        float* Ig = g_INC + ((size_t)bb*Nn + n0 + r)*Dd;
#pragma unroll
        for (int dd = 0; dd < 8; dd++){
            int d = lane + dd*32;
            float a2 = 0.f;
#pragma unroll
            for (int j = 0; j < 8; j++) a2 = fmaf(w8[j], Sb[(size_t)i8[j]*Dd + d], a2);
            Ig[d] = a2;
        }
    }
}

// ---------------- kernel 3a: phase-1 gather + X split (fp16) -------------
__global__ __launch_bounds__(256) void hdc_a(float* __restrict__ out_states){
    int tid = threadIdx.x, wid = tid >> 5, lane = tid & 31;
    int row0 = blockIdx.x * 64;
    int bb = row0 / Nn;
    for (int r8 = 0; r8 < 8; r8++){
        int row = row0 + wid*8 + r8;
        int cnt = g_hitcnt[row];
        int lim = cnt < 32 ? cnt : 32;
        const int* hl = g_hitlist + (size_t)row*32;
        float comb[8];
#pragma unroll
        for (int i = 0; i < 8; i++) comb[i] = 0.f;
        for (int j = 0; j < lim; j++){
            const float* src = g_INC + ((size_t)bb*Nn + hl[j])*Dd;
#pragma unroll
            for (int i = 0; i < 8; i++) comb[i] += src[lane + i*32];
        }
        const float* inc = g_INC + (size_t)row*Dd;
        float inv = 0.2f / ((float)cnt + 1e-8f);
#pragma unroll
        for (int i = 0; i < 8; i++){
            int d = lane + i*32;
            float ov = 0.8f*inc[d] + comb[i]*inv;
            out_states[(size_t)row*Dd + d] = ov;
            __half h = __float2half(ov);
            g_Xhi[(size_t)row*Dd + d] = h;
            g_Xlo[(size_t)row*Dd + d] = __float2half(ov - __half2float(h));
        }
    }
    if (tid < 64){
        g_dot[row0+tid] = 0.f; g_na[row0+tid] = 0.f; g_nb[row0+tid] = 0.f;
    }
}

// ---------------- kernel 3b: Wh GEMM (fp16 2-term) + fused episodic ------
#define SR 144
#define HB_BUFSZ 46080
#define HB_AH 0
#define HB_AL 18432
#define HB_BH 36864
#define HB_TOT 92160

__device__ __forceinline__ void cp_rows(uint32_t sb, int dst, const __half* src,
                                        int nrows, size_t srcstride, int tid){
    int total = nrows*8;
    for (int i = tid; i < total; i += 256){
        int row = i >> 3, ch = i & 7;
        uint32_t d = sb + dst + row*SR + ch*16;
        const char* s = (const char*)(src + (size_t)row*srcstride) + ch*16;
        asm volatile("cp.async.cg.shared.global [%0], [%1], 16;" :: "r"(d), "l"(s));
    }
}

__global__ __launch_bounds__(256,2) void hdc_b(
    const float* __restrict__ episodic,
    const float* __restrict__ bh,
    const float* __restrict__ keys, const float* __restrict__ pcodes,
    const int* __restrict__ step,
    float* __restrict__ out_epi)
{
    extern __shared__ char sm[];
    uint32_t sb = smem_u32(sm);
    int tid = threadIdx.x, wid = tid >> 5, lane = tid & 31;
    int row0 = blockIdx.x * 128;
    int c0   = blockIdx.y * 64;
    int prow = ((step[0] % NCc) + NCc) % NCc;
    const float* posr = pcodes + (size_t)prow*Hh;

    const __half* Xh = g_Xhi + (size_t)row0*Dd;
    const __half* Xl = g_Xlo + (size_t)row0*Dd;
    const __half* Wh = g_WhT + (size_t)c0*Dd;

    cp_rows(sb, HB_AH, Xh,      128, Dd, tid);
    cp_rows(sb, HB_AL, Xl,      128, Dd, tid);
    cp_rows(sb, HB_BH, Wh,      64,  Dd, tid);
    CP_COMMIT();
    cp_rows(sb, HB_BUFSZ + HB_AH, Xh + 64, 128, Dd, tid);
    cp_rows(sb, HB_BUFSZ + HB_AL, Xl + 64, 128, Dd, tid);
    cp_rows(sb, HB_BUFSZ + HB_BH, Wh + 64, 64,  Dd, tid);
    CP_COMMIT();

    int wm = wid*16;
    int rql = lane >> 2, cq = (lane & 3)*2, j4 = lane & 3;

    float acc[8][4];
#pragma unroll
    for (int nt = 0; nt < 8; nt++)
#pragma unroll
        for (int e = 0; e < 4; e++) acc[nt][e] = 0.f;

    for (int c = 0; c < 4; c++){
        int buf = c & 1;
        if (c + 1 < 4) CP_WAIT1(); else CP_WAIT0();
        __syncthreads();
        uint32_t aH = sb + buf*HB_BUFSZ + HB_AH;
        uint32_t aL = sb + buf*HB_BUFSZ + HB_AL;
        uint32_t bH = sb + buf*HB_BUFSZ + HB_BH;
#pragma unroll
        for (int kc = 0; kc < 4; kc++){
            uint32_t ah[4], al[4];
            ldmA(aH, wm, kc, SR, ah);
            ldmA(aL, wm, kc, SR, al);
            uint32_t bfh[4][4];
#pragma unroll
            for (int p = 0; p < 4; p++) ldmB4(bH, p*16, kc, SR, bfh[p]);
#pragma unroll
            for (int nt = 0; nt < 8; nt++) mma_h(acc[nt], ah, &bfh[nt>>1][(nt&1)*2]);
#pragma unroll
            for (int nt = 0; nt < 8; nt++) mma_h(acc[nt], al, &bfh[nt>>1][(nt&1)*2]);
        }
        __syncthreads();
        if (c + 2 < 4){
            int koff = (c+2)*64;
            cp_rows(sb, buf*HB_BUFSZ + HB_AH, Xh + koff, 128, Dd, tid);
            cp_rows(sb, buf*HB_BUFSZ + HB_AL, Xl + koff, 128, Dd, tid);
            cp_rows(sb, buf*HB_BUFSZ + HB_BH, Wh + koff, 64,  Dd, tid);
            CP_COMMIT();
        }
    }

    float d0 = 0.f, a0 = 0.f, b0 = 0.f;
    float d1 = 0.f, a1 = 0.f, b1 = 0.f;
    int grow0 = row0 + wm + rql, grow1 = grow0 + 8;
    int n0k = grow0 & (Nn-1), n1k = grow1 & (Nn-1);
#pragma unroll
    for (int nt = 0; nt < 8; nt++){
        int col = c0 + nt*8 + cq;
        float bh0 = __ldg(bh + col), bh1v = __ldg(bh + col + 1);
        float p0c = __ldg(posr + col), p1c = __ldg(posr + col + 1);
        {
            float y0 = 6.0f*(acc[nt][0] + bh0);
            float y1 = 6.0f*(acc[nt][1] + bh1v);
            float h0 = 1.0f - 2.0f/(__expf(y0) + 1.0f);
            float h1 = 1.0f - 2.0f/(__expf(y1) + 1.0f);
            float2 ky = *(const float2*)(keys + (size_t)n0k*Hh + col);
            float pe0 = h0*ky.x, pe1 = h1*ky.y;
            float2 ep = *(const float2*)(episodic + (size_t)grow0*Hh + col);
            float ne0 = 0.95f*ep.x + 0.05f*pe0*p0c;
            float ne1 = 0.95f*ep.y + 0.05f*pe1*p1c;
            *(float2*)(out_epi + (size_t)grow0*Hh + col) = make_float2(ne0, ne1);
            d0 = fmaf(ne0, pe0, fmaf(ne1, pe1, d0));
            a0 = fmaf(ne0, ne0, fmaf(ne1, ne1, a0));
            b0 = fmaf(pe0, pe0, fmaf(pe1, pe1, b0));
        }
        {
            float y0 = 6.0f*(acc[nt][2] + bh0);
            float y1 = 6.0f*(acc[nt][3] + bh1v);
            float h0 = 1.0f - 2.0f/(__expf(y0) + 1.0f);
            float h1 = 1.0f - 2.0f/(__expf(y1) + 1.0f);
            float2 ky = *(const float2*)(keys + (size_t)n1k*Hh + col);
            float pe0 = h0*ky.x, pe1 = h1*ky.y;
            float2 ep = *(const float2*)(episodic + (size_t)grow1*Hh + col);
            float ne0 = 0.95f*ep.x + 0.05f*pe0*p0c;
            float ne1 = 0.95f*ep.y + 0.05f*pe1*p1c;
            *(float2*)(out_epi + (size_t)grow1*Hh + col) = make_float2(ne0, ne1);
            d1 = fmaf(ne0, pe0, fmaf(ne1, pe1, d1));
            a1 = fmaf(ne0, ne0, fmaf(ne1, ne1, a1));
            b1 = fmaf(pe0, pe0, fmaf(pe1, pe1, b1));
        }
    }
#pragma unroll
    for (int off = 1; off <= 2; off <<= 1){
        d0 += __shfl_xor_sync(0xffffffffu, d0, off);
        a0 += __shfl_xor_sync(0xffffffffu, a0, off);
        b0 += __shfl_xor_sync(0xffffffffu, b0, off);
        d1 += __shfl_xor_sync(0xffffffffu, d1, off);
        a1 += __shfl_xor_sync(0xffffffffu, a1, off);
        b1 += __shfl_xor_sync(0xffffffffu, b1, off);
    }
    if (j4 == 0){
        atomicAdd(&g_dot[grow0], d0); atomicAdd(&g_na[grow0], a0); atomicAdd(&g_nb[grow0], b0);
        atomicAdd(&g_dot[grow1], d1); atomicAdd(&g_na[grow1], a1); atomicAdd(&g_nb[grow1], b1);
    }
}

// ---------------- kernel 3c: out_sim finisher ----------------
__global__ __launch_bounds__(256) void hdc_c(float* __restrict__ out_sim){
    int i = blockIdx.x*256 + threadIdx.x;
    out_sim[i] = g_dot[i] / (fmaxf(sqrtf(g_na[i]), 1e-8f)*fmaxf(sqrtf(g_nb[i]), 1e-8f));
}

// ---------------- launch ----------------
extern "C" void kernel_launch(void* const* d_in, const int* in_sizes, int n_in,
                              void* d_out, int out_size)
{
    (void)in_sizes; (void)n_in; (void)out_size;
    const float* states   = (const float*)d_in[0];
    const float* actions  = (const float*)d_in[1];
    const float* episodic = (const float*)d_in[2];
    const float* Wq = (const float*)d_in[3];  const float* bq = (const float*)d_in[4];
    const float* Wk = (const float*)d_in[5];  const float* bk = (const float*)d_in[6];
    const float* Wc = (const float*)d_in[7];  const float* bc = (const float*)d_in[8];
    const float* Wh = (const float*)d_in[9];  const float* bh = (const float*)d_in[10];
    const float* keys   = (const float*)d_in[11];
    const float* pcodes = (const float*)d_in[12];
    const int*   step   = (const int*)d_in[13];

    float* out = (float*)d_out;
    float* o_states = out;
    float* o_epi    = out + (size_t)BN*Dd;
    float* o_sim    = out + (size_t)BN*Dd + (size_t)BN*Hh;

    whprep<<<(Dd*Hh)/256, 256>>>(Wh);
    proj_kernel<<<BN/32, 256>>>(actions, Wq, bq, Wk, bk, Wc, bc);

    cudaFuncSetAttribute(graph_kernel, cudaFuncAttributeMaxDynamicSharedMemorySize, G_TOT);
    graph_kernel<<<dim3(Nn/64, Bb), 256, G_TOT>>>(states);

    hdc_a<<<BN/64, 256>>>(o_states);

    cudaFuncSetAttribute(hdc_b, cudaFuncAttributeMaxDynamicSharedMemorySize, HB_TOT);
    hdc_b<<<dim3(BN/128, Hh/64), 256, HB_TOT>>>(episodic, bh, keys, pcodes, step, o_epi);

    hdc_c<<<BN/256, 256>>>(o_sim);
}

// round 9
// speedup vs baseline: 2.7296x; 1.0806x over previous
#include <cuda_runtime.h>
#include <cuda_fp16.h>
#include <cstdint>
#include <math.h>

#define Bb 4
#define Nn 4096
#define Dd 256
#define Pp 64
#define Hh 1024
#define NCc 256
#define BN (Bb*Nn)

// ---------------- device scratch ----------------
__device__ float g_Qf[(size_t)BN*64];
__device__ float g_Kf[(size_t)BN*64];
__device__ __half g_Qh[(size_t)BN*64];
__device__ __half g_Kh[(size_t)BN*64];
__device__ __half g_Ph[(size_t)BN*64];
__device__ __half g_WhT[(size_t)Hh*Dd];
__device__ __half g_Xh[(size_t)BN*Dd];
__device__ float g_INC[(size_t)BN*Dd];
__device__ float g_dot[BN], g_na[BN], g_nb[BN];
__device__ int   g_hitcnt[BN];
__device__ int   g_hitlist[BN*32];

// ---------------- helpers ----------------
__device__ __forceinline__ uint32_t smem_u32(const void* p){
    uint32_t a;
    asm("{ .reg .u64 t; cvta.to.shared.u64 t, %1; cvt.u32.u64 %0, t; }" : "=r"(a) : "l"(p));
    return a;
}
__device__ __forceinline__ void ldmA(uint32_t tile, int m0, int kc, int stride, uint32_t* a){
    int lane = threadIdx.x & 31;
    uint32_t addr = tile + (uint32_t)(m0 + (lane & 15))*stride + (uint32_t)kc*32 + ((lane >> 4)*16);
    asm volatile("ldmatrix.sync.aligned.m8n8.x4.shared.b16 {%0,%1,%2,%3}, [%4];"
        : "=r"(a[0]),"=r"(a[1]),"=r"(a[2]),"=r"(a[3]) : "r"(addr));
}
__device__ __forceinline__ void ldmB4(uint32_t tile, int n0, int kc, int stride, uint32_t* b){
    int lane = threadIdx.x & 31;
    int g = lane >> 3;
    uint32_t addr = tile + (uint32_t)(n0 + ((g & 2) ? 8 : 0) + (lane & 7))*stride
                  + (uint32_t)kc*32 + ((g & 1)*16);
    asm volatile("ldmatrix.sync.aligned.m8n8.x4.shared.b16 {%0,%1,%2,%3}, [%4];"
        : "=r"(b[0]),"=r"(b[1]),"=r"(b[2]),"=r"(b[3]) : "r"(addr));
}
__device__ __forceinline__ void mma_h(float* c, const uint32_t* a, const uint32_t* b){
    asm volatile("mma.sync.aligned.m16n8k16.row.col.f32.f16.f16.f32 "
        "{%0,%1,%2,%3}, {%4,%5,%6,%7}, {%8,%9}, {%0,%1,%2,%3};"
        : "+f"(c[0]),"+f"(c[1]),"+f"(c[2]),"+f"(c[3])
        : "r"(a[0]),"r"(a[1]),"r"(a[2]),"r"(a[3]), "r"(b[0]),"r"(b[1]));
}
#define CP_COMMIT() asm volatile("cp.async.commit_group;" ::: "memory")
#define CP_WAIT1()  asm volatile("cp.async.wait_group 1;" ::: "memory")
#define CP_WAIT0()  asm volatile("cp.async.wait_group 0;" ::: "memory")

#define UPD8(VV, II, MN, MP, val, col) do { \
    if ((val) > (MN)){ VV[MP] = (val); II[MP] = (col); MN = VV[0]; MP = 0; \
        _Pragma("unroll") for (int _q = 1; _q < 8; _q++) \
            if (VV[_q] < MN){ MN = VV[_q]; MP = _q; } } } while(0)

// ---------------- kernel 1: projections (+fused Wh transpose) ------------
#define PROJ_BLOCKS (BN/32)
#define WH_BLOCKS   ((Dd*Hh)/256)

__global__ __launch_bounds__(256) void proj_kernel(
    const float* __restrict__ actions,
    const float* __restrict__ Wq, const float* __restrict__ bq,
    const float* __restrict__ Wk, const float* __restrict__ bk,
    const float* __restrict__ Wc, const float* __restrict__ bc,
    const float* __restrict__ Wh)
{
    __shared__ float As[32*Dd];
    __shared__ float invn[32];
    int tid = threadIdx.x;

    if (blockIdx.x >= PROJ_BLOCKS){
        // fused whprep
        int idx = (blockIdx.x - PROJ_BLOCKS)*256 + tid;
        int k = idx >> 10, n = idx & 1023;
        g_WhT[(size_t)n*Dd + k] = __float2half(Wh[idx]);
        return;
    }

    float* Qs = As;
    float* Ks = As + 32*65;
    float* Ps = As + 64*65;
    int row0 = blockIdx.x * 32;

    for (int idx = tid; idx < 32*Dd; idx += 256)
        As[idx] = actions[(size_t)row0*Dd + idx];
    __syncthreads();

    int p = tid & 63, g = tid >> 6;
    float aq[8], ak[8], ac[8];
#pragma unroll
    for (int i = 0; i < 8; i++){ aq[i]=0.f; ak[i]=0.f; ac[i]=0.f; }
    for (int d = 0; d < Dd; d++){
        float wq = Wq[d*Pp+p], wk = Wk[d*Pp+p], wc = Wc[d*Pp+p];
#pragma unroll
        for (int i = 0; i < 8; i++){
            float a = As[(g*8+i)*Dd + d];
            aq[i] = fmaf(a, wq, aq[i]);
            ak[i] = fmaf(a, wk, ak[i]);
            ac[i] = fmaf(a, wc, ac[i]);
        }
    }
    float vbq = bq[p], vbk = bk[p], vbc = bc[p];
    __syncthreads();
#pragma unroll
    for (int i = 0; i < 8; i++){
        int r = g*8+i;
        Qs[r*65+p] = aq[i]+vbq;
        Ks[r*65+p] = ak[i]+vbk;
        Ps[r*65+p] = ac[i]+vbc;
    }
    __syncthreads();
    if (tid < 32){
        float s = 0.f;
        for (int j = 0; j < 64; j++){ float v = Ps[tid*65+j]; s = fmaf(v,v,s); }
        invn[tid] = 1.0f / fmaxf(sqrtf(s), 1e-12f);
        g_hitcnt[row0 + tid] = 0;
    }
    __syncthreads();
    for (int idx = tid; idx < 32*64; idx += 256){
        int r = idx >> 6, pp = idx & 63;
        size_t o = (size_t)(row0 + r)*64 + pp;
        float q = Qs[r*65+pp], k = Ks[r*65+pp], pn = Ps[r*65+pp]*invn[r];
        g_Qf[o] = q; g_Kf[o] = k;
        g_Qh[o] = __float2half(q);
        g_Kh[o] = __float2half(k);
        g_Ph[o] = __float2half(pn);
    }
}

// ---------------- kernel 2: graph (fp16, symmetric sim skip) -------------
#define GSR 144
#define GA_QH 0
#define GA_PH 9216
#define GB 18432
#define GB_BUF 36864          // per buffer: Kh(18432) + Ph(18432)
#define GB_KH 0
#define GB_PH 18432
#define G_TOT 92160
// post-mainloop aliases
#define G_CANDI 0
#define G_MV 16384
#define G_MI 24576
#define G_TOPW 32768
#define G_TOPI 34816

__device__ __forceinline__ void cp_tile64(uint32_t sb, int dst, const __half* src, int tid){
    const char* s = (const char*)src;
#pragma unroll
    for (int i = tid; i < 512; i += 256){
        int row = i >> 3, ch = i & 7;
        uint32_t d = sb + dst + row*GSR + ch*16;
        asm volatile("cp.async.cg.shared.global [%0], [%1], 16;" :: "r"(d), "l"(s + i*16));
    }
}
__device__ __forceinline__ void cp_tile128(uint32_t sb, int dst, const __half* src, int tid){
    const char* s = (const char*)src;
#pragma unroll
    for (int i = tid; i < 1024; i += 256){
        int row = i >> 3, ch = i & 7;
        uint32_t d = sb + dst + row*GSR + ch*16;
        asm volatile("cp.async.cg.shared.global [%0], [%1], 16;" :: "r"(d), "l"(s + i*16));
    }
}

__global__ __launch_bounds__(256,2) void graph_kernel(const float* __restrict__ states)
{
    extern __shared__ char sm[];
    uint32_t sb = smem_u32(sm);
    int tid = threadIdx.x, wid = tid >> 5, lane = tid & 31;
    int bb = blockIdx.y, n0 = blockIdx.x * 64;
    size_t bofs = (size_t)bb*Nn*64;
    int tmin_sim = n0 >> 7;     // first tile whose cols reach the diagonal

    cp_tile64(sb, GA_QH, g_Qh + bofs + (size_t)n0*64, tid);
    cp_tile64(sb, GA_PH, g_Ph + bofs + (size_t)n0*64, tid);
    cp_tile128(sb, GB + GB_KH, g_Kh + bofs, tid);
    if (0 >= tmin_sim) cp_tile128(sb, GB + GB_PH, g_Ph + bofs, tid);
    CP_COMMIT();
    {
        size_t mofs = bofs + (size_t)128*64;
        cp_tile128(sb, GB + GB_BUF + GB_KH, g_Kh + mofs, tid);
        if (1 >= tmin_sim) cp_tile128(sb, GB + GB_BUF + GB_PH, g_Ph + mofs, tid);
        CP_COMMIT();
    }

    int wm = (wid & 3)*16, wn0 = (wid >> 2)*64, wng = wid >> 2;
    int rql = lane >> 2, cq = (lane & 3)*2, j4 = lane & 3;

    float v0[8], v1[8]; int i0[8], i1[8];
    float mn0 = -1e30f, mn1 = -1e30f; int mp0 = 0, mp1 = 0;
#pragma unroll
    for (int j = 0; j < 8; j++){ v0[j]=-1e30f; v1[j]=-1e30f; i0[j]=0; i1[j]=0; }

    for (int t = 0; t < Nn/128; t++){
        int buf = t & 1;
        if (t + 1 < Nn/128) CP_WAIT1(); else CP_WAIT0();
        __syncthreads();
        uint32_t bB = sb + GB + buf*GB_BUF;

        // ---- pass 1: scores = Qh . Kh ----
        float acc[8][4];
#pragma unroll
        for (int nt = 0; nt < 8; nt++)
#pragma unroll
            for (int e = 0; e < 4; e++) acc[nt][e] = 0.f;
#pragma unroll
        for (int kc = 0; kc < 4; kc++){
            uint32_t ah[4];
            ldmA(sb + GA_QH, wm, kc, GSR, ah);
            uint32_t bf[4][4];
#pragma unroll
            for (int p = 0; p < 4; p++) ldmB4(bB + GB_KH, wn0 + p*16, kc, GSR, bf[p]);
#pragma unroll
            for (int nt = 0; nt < 8; nt++) mma_h(acc[nt], ah, &bf[nt>>1][(nt&1)*2]);
        }
        {
            float t0 = -1e30f, t1 = -1e30f;
#pragma unroll
            for (int nt = 0; nt < 8; nt++){
                t0 = fmaxf(t0, fmaxf(acc[nt][0], acc[nt][1]));
                t1 = fmaxf(t1, fmaxf(acc[nt][2], acc[nt][3]));
            }
            if (t0 > mn0){
#pragma unroll
                for (int nt = 0; nt < 8; nt++){
                    int cb = t*128 + wn0 + nt*8 + cq;
                    UPD8(v0, i0, mn0, mp0, acc[nt][0], cb);
                    UPD8(v0, i0, mn0, mp0, acc[nt][1], cb+1);
                }
            }
            if (t1 > mn1){
#pragma unroll
                for (int nt = 0; nt < 8; nt++){
                    int cb = t*128 + wn0 + nt*8 + cq;
                    UPD8(v1, i1, mn1, mp1, acc[nt][2], cb);
                    UPD8(v1, i1, mn1, mp1, acc[nt][3], cb+1);
                }
            }
        }

        // ---- pass 2: sim = Ph . Ph (upper triangle only, mirrored) ----
        if (t >= tmin_sim){
#pragma unroll
            for (int nt = 0; nt < 8; nt++)
#pragma unroll
                for (int e = 0; e < 4; e++) acc[nt][e] = 0.f;
#pragma unroll
            for (int kc = 0; kc < 4; kc++){
                uint32_t ah[4];
                ldmA(sb + GA_PH, wm, kc, GSR, ah);
                uint32_t bf[4][4];
#pragma unroll
                for (int p = 0; p < 4; p++) ldmB4(bB + GB_PH, wn0 + p*16, kc, GSR, bf[p]);
#pragma unroll
                for (int nt = 0; nt < 8; nt++) mma_h(acc[nt], ah, &bf[nt>>1][(nt&1)*2]);
            }
#pragma unroll
            for (int nt = 0; nt < 8; nt++)
#pragma unroll
                for (int e = 0; e < 4; e++){
                    if (acc[nt][e] > 0.7f){
                        int row = n0 + wm + rql + ((e >= 2) ? 8 : 0);
                        int col = t*128 + wn0 + nt*8 + cq + (e & 1);
                        if (col >= row){
                            int hr = bb*Nn + row;
                            int s1 = atomicAdd(&g_hitcnt[hr], 1);
                            if (s1 < 32) g_hitlist[(size_t)hr*32 + s1] = col;
                            if (col > row){
                                int hc = bb*Nn + col;
                                int s2 = atomicAdd(&g_hitcnt[hc], 1);
                                if (s2 < 32) g_hitlist[(size_t)hc*32 + s2] = row;
                            }
                        }
                    }
                }
        }
        __syncthreads();

        if (t + 2 < Nn/128){
            size_t mofs = bofs + (size_t)(t+2)*128*64;
            cp_tile128(sb, GB + buf*GB_BUF + GB_KH, g_Kh + mofs, tid);
            if (t + 2 >= tmin_sim) cp_tile128(sb, GB + buf*GB_BUF + GB_PH, g_Ph + mofs, tid);
            CP_COMMIT();
        }
    }
    __syncthreads();

    // ---- dump candidates: 8 slices/row x 8 = 64 per row ----
    int* candI = (int*)(sm + G_CANDI);
    {
        int r0 = wm + rql, r1 = wm + rql + 8;
        int slice = wng*4 + j4;
#pragma unroll
        for (int s = 0; s < 8; s++){
            candI[r0*64 + slice*8 + s] = i0[s];
            candI[r1*64 + slice*8 + s] = i1[s];
        }
    }
    __syncthreads();

    // ---- exact fp32 rescore: 4 threads/row x 16 candidates ----
    float* mergeV = (float*)(sm + G_MV);
    int*   mergeI = (int*)(sm + G_MI);
    {
        int row = tid >> 2, sub = tid & 3;
        const float4* Q4 = (const float4*)(g_Qf + bofs + (size_t)(n0 + row)*64);
        float q[64];
#pragma unroll
        for (int i = 0; i < 16; i++){
            float4 v = Q4[i];
            q[4*i] = v.x; q[4*i+1] = v.y; q[4*i+2] = v.z; q[4*i+3] = v.w;
        }
        float tv[8]; int ti8[8]; float tmn = -1e30f; int tmp = 0;
#pragma unroll
        for (int j = 0; j < 8; j++){ tv[j] = -1e30f; ti8[j] = 0; }
#pragma unroll
        for (int c = 0; c < 16; c++){
            int col = candI[row*64 + sub*16 + c];
            const float4* K4 = (const float4*)(g_Kf + bofs + (size_t)col*64);
            float a2 = 0.f;
#pragma unroll
            for (int i = 0; i < 16; i++){
                float4 kv = K4[i];
                a2 = fmaf(q[4*i],   kv.x, a2);
                a2 = fmaf(q[4*i+1], kv.y, a2);
                a2 = fmaf(q[4*i+2], kv.z, a2);
                a2 = fmaf(q[4*i+3], kv.w, a2);
            }
            a2 *= 0.125f;
            UPD8(tv, ti8, tmn, tmp, a2, col);
        }
#pragma unroll
        for (int s = 0; s < 8; s++){
            mergeV[row*32 + sub*8 + s] = tv[s];
            mergeI[row*32 + sub*8 + s] = ti8[s];
        }
    }
    __syncthreads();

    // ---- final merge + softmax (64 threads) ----
    float* topW = (float*)(sm + G_TOPW);
    int*   topI = (int*)(sm + G_TOPI);
    if (tid < 64){
        float tv[8]; int ti8[8]; float tmn = -1e30f; int tmp = 0;
#pragma unroll
        for (int j = 0; j < 8; j++){ tv[j] = -1e30f; ti8[j] = 0; }
#pragma unroll
        for (int c = 0; c < 32; c++){
            UPD8(tv, ti8, tmn, tmp, mergeV[tid*32 + c], mergeI[tid*32 + c]);
        }
        float mx = tv[0];
#pragma unroll
        for (int j = 1; j < 8; j++) mx = fmaxf(mx, tv[j]);
        float e[8], ssum = 0.f;
#pragma unroll
        for (int j = 0; j < 8; j++){ e[j] = __expf(tv[j] - mx); ssum += e[j]; }
        float inv = 1.f / ssum;
#pragma unroll
        for (int j = 0; j < 8; j++){ topW[tid*8+j] = e[j]*inv; topI[tid*8+j] = ti8[j]; }
    }
    __syncthreads();

    // ---- gather incoming (8 warps x 8 rows) ----
    const float* Sb = states + (size_t)bb*Nn*Dd;
    for (int rr = 0; rr < 8; rr++){
        int r = wid*8 + rr;
        float w8[8]; int i8[8];
#pragma unroll
        for (int j = 0; j < 8; j++){ w8[j] = topW[r*8+j]; i8[j] = topI[r*8+j]; }
        float* Ig = g_INC + ((size_t)bb*Nn + n0 + r)*Dd;
#pragma unroll
        for (int dd = 0; dd < 8; dd++){
            int d = lane + dd*32;
            float a2 = 0.f;
#pragma unroll
            for (int j = 0; j < 8; j++) a2 = fmaf(w8[j], Sb[(size_t)i8[j]*Dd + d], a2);
            Ig[d] = a2;
        }
    }
}

// ---------------- kernel 3a: phase-1 gather + X (fp16) ----------------
__global__ __launch_bounds__(256) void hdc_a(float* __restrict__ out_states){
    int tid = threadIdx.x, wid = tid >> 5, lane = tid & 31;
    int row0 = blockIdx.x * 64;
    int bb = row0 / Nn;
    for (int r8 = 0; r8 < 8; r8++){
        int row = row0 + wid*8 + r8;
        int cnt = g_hitcnt[row];
        int lim = cnt < 32 ? cnt : 32;
        const int* hl = g_hitlist + (size_t)row*32;
        float comb[8];
#pragma unroll
        for (int i = 0; i < 8; i++) comb[i] = 0.f;
        for (int j = 0; j < lim; j++){
            const float* src = g_INC + ((size_t)bb*Nn + hl[j])*Dd;
#pragma unroll
            for (int i = 0; i < 8; i++) comb[i] += src[lane + i*32];
        }
        const float* inc = g_INC + (size_t)row*Dd;
        float inv = 0.2f / ((float)cnt + 1e-8f);
#pragma unroll
        for (int i = 0; i < 8; i++){
            int d = lane + i*32;
            float ov = 0.8f*inc[d] + comb[i]*inv;
            out_states[(size_t)row*Dd + d] = ov;
            g_Xh[(size_t)row*Dd + d] = __float2half(ov);
        }
    }
    if (tid < 64){
        g_dot[row0+tid] = 0.f; g_na[row0+tid] = 0.f; g_nb[row0+tid] = 0.f;
    }
}

// ---------------- kernel 3b: Wh GEMM (fp16 single-term) + episodic -------
#define SR 144
#define HB_BUFSZ 27648
#define HB_AH 0
#define HB_BH 18432
#define HB_TOT 55296

__device__ __forceinline__ void cp_rows(uint32_t sb, int dst, const __half* src,
                                        int nrows, size_t srcstride, int tid){
    int total = nrows*8;
    for (int i = tid; i < total; i += 256){
        int row = i >> 3, ch = i & 7;
        uint32_t d = sb + dst + row*SR + ch*16;
        const char* s = (const char*)(src + (size_t)row*srcstride) + ch*16;
        asm volatile("cp.async.cg.shared.global [%0], [%1], 16;" :: "r"(d), "l"(s));
    }
}

__global__ __launch_bounds__(256,3) void hdc_b(
    const float* __restrict__ episodic,
    const float* __restrict__ bh,
    const float* __restrict__ keys, const float* __restrict__ pcodes,
    const int* __restrict__ step,
    float* __restrict__ out_epi)
{
    extern __shared__ char sm[];
    uint32_t sb = smem_u32(sm);
    int tid = threadIdx.x, wid = tid >> 5, lane = tid & 31;
    int row0 = blockIdx.x * 128;
    int c0   = blockIdx.y * 64;
    int prow = ((step[0] % NCc) + NCc) % NCc;
    const float* posr = pcodes + (size_t)prow*Hh;

    const __half* Xh = g_Xh + (size_t)row0*Dd;
    const __half* Wh = g_WhT + (size_t)c0*Dd;

    cp_rows(sb, HB_AH, Xh,      128, Dd, tid);
    cp_rows(sb, HB_BH, Wh,      64,  Dd, tid);
    CP_COMMIT();
    cp_rows(sb, HB_BUFSZ + HB_AH, Xh + 64, 128, Dd, tid);
    cp_rows(sb, HB_BUFSZ + HB_BH, Wh + 64, 64,  Dd, tid);
    CP_COMMIT();

    int wm = wid*16;
    int rql = lane >> 2, cq = (lane & 3)*2, j4 = lane & 3;

    float acc[8][4];
#pragma unroll
    for (int nt = 0; nt < 8; nt++)
#pragma unroll
        for (int e = 0; e < 4; e++) acc[nt][e] = 0.f;

    for (int c = 0; c < 4; c++){
        int buf = c & 1;
        if (c + 1 < 4) CP_WAIT1(); else CP_WAIT0();
        __syncthreads();
        uint32_t aH = sb + buf*HB_BUFSZ + HB_AH;
        uint32_t bH = sb + buf*HB_BUFSZ + HB_BH;
#pragma unroll
        for (int kc = 0; kc < 4; kc++){
            uint32_t ah[4];
            ldmA(aH, wm, kc, SR, ah);
            uint32_t bfh[4][4];
#pragma unroll
            for (int p = 0; p < 4; p++) ldmB4(bH, p*16, kc, SR, bfh[p]);
#pragma unroll
            for (int nt = 0; nt < 8; nt++) mma_h(acc[nt], ah, &bfh[nt>>1][(nt&1)*2]);
        }
        __syncthreads();
        if (c + 2 < 4){
            int koff = (c+2)*64;
            cp_rows(sb, buf*HB_BUFSZ + HB_AH, Xh + koff, 128, Dd, tid);
            cp_rows(sb, buf*HB_BUFSZ + HB_BH, Wh + koff, 64,  Dd, tid);
            CP_COMMIT();
        }
    }

    float d0 = 0.f, a0 = 0.f, b0 = 0.f;
    float d1 = 0.f, a1 = 0.f, b1 = 0.f;
    int grow0 = row0 + wm + rql, grow1 = grow0 + 8;
    int n0k = grow0 & (Nn-1), n1k = grow1 & (Nn-1);
#pragma unroll
    for (int nt = 0; nt < 8; nt++){
        int col = c0 + nt*8 + cq;
        float bh0 = __ldg(bh + col), bh1v = __ldg(bh + col + 1);
        float p0c = __ldg(posr + col), p1c = __ldg(posr + col + 1);
        {
            float y0 = 6.0f*(acc[nt][0] + bh0);
            float y1 = 6.0f*(acc[nt][1] + bh1v);
            float h0 = 1.0f - 2.0f/(__expf(y0) + 1.0f);
            float h1 = 1.0f - 2.0f/(__expf(y1) + 1.0f);
            float2 ky = *(const float2*)(keys + (size_t)n0k*Hh + col);
            float pe0 = h0*ky.x, pe1 = h1*ky.y;
            float2 ep = *(const float2*)(episodic + (size_t)grow0*Hh + col);
            float ne0 = 0.95f*ep.x + 0.05f*pe0*p0c;
            float ne1 = 0.95f*ep.y + 0.05f*pe1*p1c;
            *(float2*)(out_epi + (size_t)grow0*Hh + col) = make_float2(ne0, ne1);
            d0 = fmaf(ne0, pe0, fmaf(ne1, pe1, d0));
            a0 = fmaf(ne0, ne0, fmaf(ne1, ne1, a0));
            b0 = fmaf(pe0, pe0, fmaf(pe1, pe1, b0));
        }
        {
            float y0 = 6.0f*(acc[nt][2] + bh0);
            float y1 = 6.0f*(acc[nt][3] + bh1v);
            float h0 = 1.0f - 2.0f/(__expf(y0) + 1.0f);
            float h1 = 1.0f - 2.0f/(__expf(y1) + 1.0f);
            float2 ky = *(const float2*)(keys + (size_t)n1k*Hh + col);
            float pe0 = h0*ky.x, pe1 = h1*ky.y;
            float2 ep = *(const float2*)(episodic + (size_t)grow1*Hh + col);
            float ne0 = 0.95f*ep.x + 0.05f*pe0*p0c;
            float ne1 = 0.95f*ep.y + 0.05f*pe1*p1c;
            *(float2*)(out_epi + (size_t)grow1*Hh + col) = make_float2(ne0, ne1);
            d1 = fmaf(ne0, pe0, fmaf(ne1, pe1, d1));
            a1 = fmaf(ne0, ne0, fmaf(ne1, ne1, a1));
            b1 = fmaf(pe0, pe0, fmaf(pe1, pe1, b1));
        }
    }
#pragma unroll
    for (int off = 1; off <= 2; off <<= 1){
        d0 += __shfl_xor_sync(0xffffffffu, d0, off);
        a0 += __shfl_xor_sync(0xffffffffu, a0, off);
        b0 += __shfl_xor_sync(0xffffffffu, b0, off);
        d1 += __shfl_xor_sync(0xffffffffu, d1, off);
        a1 += __shfl_xor_sync(0xffffffffu, a1, off);
        b1 += __shfl_xor_sync(0xffffffffu, b1, off);
    }
    if (j4 == 0){
        atomicAdd(&g_dot[grow0], d0); atomicAdd(&g_na[grow0], a0); atomicAdd(&g_nb[grow0], b0);
        atomicAdd(&g_dot[grow1], d1); atomicAdd(&g_na[grow1], a1); atomicAdd(&g_nb[grow1], b1);
    }
}

// ---------------- kernel 3c: out_sim finisher ----------------
__global__ __launch_bounds__(256) void hdc_c(float* __restrict__ out_sim){
    int i = blockIdx.x*256 + threadIdx.x;
    out_sim[i] = g_dot[i] / (fmaxf(sqrtf(g_na[i]), 1e-8f)*fmaxf(sqrtf(g_nb[i]), 1e-8f));
}

// ---------------- launch ----------------
extern "C" void kernel_launch(void* const* d_in, const int* in_sizes, int n_in,
                              void* d_out, int out_size)
{
    (void)in_sizes; (void)n_in; (void)out_size;
    const float* states   = (const float*)d_in[0];
    const float* actions  = (const float*)d_in[1];
    const float* episodic = (const float*)d_in[2];
    const float* Wq = (const float*)d_in[3];  const float* bq = (const float*)d_in[4];
    const float* Wk = (const float*)d_in[5];  const float* bk = (const float*)d_in[6];
    const float* Wc = (const float*)d_in[7];  const float* bc = (const float*)d_in[8];
    const float* Wh = (const float*)d_in[9];  const float* bh = (const float*)d_in[10];
    const float* keys   = (const float*)d_in[11];
    const float* pcodes = (const float*)d_in[12];
    const int*   step   = (const int*)d_in[13];

    float* out = (float*)d_out;
    float* o_states = out;
    float* o_epi    = out + (size_t)BN*Dd;
    float* o_sim    = out + (size_t)BN*Dd + (size_t)BN*Hh;

    proj_kernel<<<PROJ_BLOCKS + WH_BLOCKS, 256>>>(actions, Wq, bq, Wk, bk, Wc, bc, Wh);

    cudaFuncSetAttribute(graph_kernel, cudaFuncAttributeMaxDynamicSharedMemorySize, G_TOT);
    graph_kernel<<<dim3(Nn/64, Bb), 256, G_TOT>>>(states);

    hdc_a<<<BN/64, 256>>>(o_states);

    cudaFuncSetAttribute(hdc_b, cudaFuncAttributeMaxDynamicSharedMemorySize, HB_TOT);
    hdc_b<<<dim3(BN/128, Hh/64), 256, HB_TOT>>>(episodic, bh, keys, pcodes, step, o_epi);

    hdc_c<<<BN/256, 256>>>(o_sim);
}

// round 10
// speedup vs baseline: 3.3657x; 1.2331x over previous
#include <cuda_runtime.h>
#include <cuda_fp16.h>
#include <cstdint>
#include <math.h>

#define Bb 4
#define Nn 4096
#define Dd 256
#define Pp 64
#define Hh 1024
#define NCc 256
#define BN (Bb*Nn)

// ---------------- device scratch ----------------
__device__ float g_Qf[(size_t)BN*64];
__device__ float g_Kf[(size_t)BN*64];
__device__ __half g_Qh[(size_t)BN*64];
__device__ __half g_Kh[(size_t)BN*64];
__device__ __half g_Ph[(size_t)BN*64];
__device__ __half g_WhT[(size_t)Hh*Dd];
__device__ __half g_Xh[(size_t)BN*Dd];
__device__ float g_INC[(size_t)BN*Dd];
__device__ float g_dot[BN], g_na[BN], g_nb[BN];
__device__ int   g_hitcnt[BN];
__device__ int   g_hitlist[BN*32];

// ---------------- helpers ----------------
__device__ __forceinline__ uint32_t smem_u32(const void* p){
    uint32_t a;
    asm("{ .reg .u64 t; cvta.to.shared.u64 t, %1; cvt.u32.u64 %0, t; }" : "=r"(a) : "l"(p));
    return a;
}
__device__ __forceinline__ void ldmA(uint32_t tile, int m0, int kc, int stride, uint32_t* a){
    int lane = threadIdx.x & 31;
    uint32_t addr = tile + (uint32_t)(m0 + (lane & 15))*stride + (uint32_t)kc*32 + ((lane >> 4)*16);
    asm volatile("ldmatrix.sync.aligned.m8n8.x4.shared.b16 {%0,%1,%2,%3}, [%4];"
        : "=r"(a[0]),"=r"(a[1]),"=r"(a[2]),"=r"(a[3]) : "r"(addr));
}
__device__ __forceinline__ void ldmB4(uint32_t tile, int n0, int kc, int stride, uint32_t* b){
    int lane = threadIdx.x & 31;
    int g = lane >> 3;
    uint32_t addr = tile + (uint32_t)(n0 + ((g & 2) ? 8 : 0) + (lane & 7))*stride
                  + (uint32_t)kc*32 + ((g & 1)*16);
    asm volatile("ldmatrix.sync.aligned.m8n8.x4.shared.b16 {%0,%1,%2,%3}, [%4];"
        : "=r"(b[0]),"=r"(b[1]),"=r"(b[2]),"=r"(b[3]) : "r"(addr));
}
__device__ __forceinline__ void mma_h(float* c, const uint32_t* a, const uint32_t* b){
    asm volatile("mma.sync.aligned.m16n8k16.row.col.f32.f16.f16.f32 "
        "{%0,%1,%2,%3}, {%4,%5,%6,%7}, {%8,%9}, {%0,%1,%2,%3};"
        : "+f"(c[0]),"+f"(c[1]),"+f"(c[2]),"+f"(c[3])
        : "r"(a[0]),"r"(a[1]),"r"(a[2]),"r"(a[3]), "r"(b[0]),"r"(b[1]));
}
#define CP_COMMIT() asm volatile("cp.async.commit_group;" ::: "memory")
#define CP_WAIT1()  asm volatile("cp.async.wait_group 1;" ::: "memory")
#define CP_WAIT0()  asm volatile("cp.async.wait_group 0;" ::: "memory")

// Branchless sorted-insert into descending top-8 (STATIC indices only —
// stays in registers; V[7] is the running 8th-best, V[0] the max).
#define INS8(V, I, val, col) do { \
    if ((val) > V[7]){ \
        V[7] = (val); I[7] = (col); \
        _Pragma("unroll") \
        for (int _s = 7; _s > 0; _s--){ \
            bool _sw = V[_s] > V[_s-1]; \
            float _tv = _sw ? V[_s-1] : V[_s]; \
            int   _ti = _sw ? I[_s-1] : I[_s]; \
            V[_s-1] = _sw ? V[_s] : V[_s-1]; \
            I[_s-1] = _sw ? I[_s] : I[_s-1]; \
            V[_s] = _tv; I[_s] = _ti; \
        } \
    } } while(0)

// ---------------- kernel 1: projections (+fused Wh transpose) ------------
#define PROJ_BLOCKS (BN/32)
#define WH_BLOCKS   ((Dd*Hh)/256)

__global__ __launch_bounds__(256) void proj_kernel(
    const float* __restrict__ actions,
    const float* __restrict__ Wq, const float* __restrict__ bq,
    const float* __restrict__ Wk, const float* __restrict__ bk,
    const float* __restrict__ Wc, const float* __restrict__ bc,
    const float* __restrict__ Wh)
{
    __shared__ float As[32*Dd];
    __shared__ float invn[32];
    int tid = threadIdx.x;

    if (blockIdx.x >= PROJ_BLOCKS){
        int idx = (blockIdx.x - PROJ_BLOCKS)*256 + tid;
        int k = idx >> 10, n = idx & 1023;
        g_WhT[(size_t)n*Dd + k] = __float2half(Wh[idx]);
        return;
    }

    float* Qs = As;
    float* Ks = As + 32*65;
    float* Ps = As + 64*65;
    int row0 = blockIdx.x * 32;

    for (int idx = tid; idx < 32*Dd; idx += 256)
        As[idx] = actions[(size_t)row0*Dd + idx];
    __syncthreads();

    int p = tid & 63, g = tid >> 6;
    float aq[8], ak[8], ac[8];
#pragma unroll
    for (int i = 0; i < 8; i++){ aq[i]=0.f; ak[i]=0.f; ac[i]=0.f; }
#pragma unroll 4
    for (int d = 0; d < Dd; d++){
        float wq = Wq[d*Pp+p], wk = Wk[d*Pp+p], wc = Wc[d*Pp+p];
#pragma unroll
        for (int i = 0; i < 8; i++){
            float a = As[(g*8+i)*Dd + d];
            aq[i] = fmaf(a, wq, aq[i]);
            ak[i] = fmaf(a, wk, ak[i]);
            ac[i] = fmaf(a, wc, ac[i]);
        }
    }
    float vbq = bq[p], vbk = bk[p], vbc = bc[p];
    __syncthreads();
#pragma unroll
    for (int i = 0; i < 8; i++){
        int r = g*8+i;
        Qs[r*65+p] = aq[i]+vbq;
        Ks[r*65+p] = ak[i]+vbk;
        Ps[r*65+p] = ac[i]+vbc;
    }
    __syncthreads();
    if (tid < 32){
        float s = 0.f;
        for (int j = 0; j < 64; j++){ float v = Ps[tid*65+j]; s = fmaf(v,v,s); }
        invn[tid] = 1.0f / fmaxf(sqrtf(s), 1e-12f);
        g_hitcnt[row0 + tid] = 0;
    }
    __syncthreads();
    for (int idx = tid; idx < 32*64; idx += 256){
        int r = idx >> 6, pp = idx & 63;
        size_t o = (size_t)(row0 + r)*64 + pp;
        float q = Qs[r*65+pp], k = Ks[r*65+pp], pn = Ps[r*65+pp]*invn[r];
        g_Qf[o] = q; g_Kf[o] = k;
        g_Qh[o] = __float2half(q);
        g_Kh[o] = __float2half(k);
        g_Ph[o] = __float2half(pn);
    }
}

// ---------------- kernel 2: graph (fp16, symmetric sim skip) -------------
#define GSR 144
#define GA_QH 0
#define GA_PH 9216
#define GB 18432
#define GB_BUF 36864
#define GB_KH 0
#define GB_PH 18432
#define G_TOT 92160
#define G_CANDI 0
#define G_MV 16384
#define G_MI 24576
#define G_TOPW 32768
#define G_TOPI 34816

__device__ __forceinline__ void cp_tile64(uint32_t sb, int dst, const __half* src, int tid){
    const char* s = (const char*)src;
#pragma unroll
    for (int i = tid; i < 512; i += 256){
        int row = i >> 3, ch = i & 7;
        uint32_t d = sb + dst + row*GSR + ch*16;
        asm volatile("cp.async.cg.shared.global [%0], [%1], 16;" :: "r"(d), "l"(s + i*16));
    }
}
__device__ __forceinline__ void cp_tile128(uint32_t sb, int dst, const __half* src, int tid){
    const char* s = (const char*)src;
#pragma unroll
    for (int i = tid; i < 1024; i += 256){
        int row = i >> 3, ch = i & 7;
        uint32_t d = sb + dst + row*GSR + ch*16;
        asm volatile("cp.async.cg.shared.global [%0], [%1], 16;" :: "r"(d), "l"(s + i*16));
    }
}

__global__ __launch_bounds__(256,2) void graph_kernel(const float* __restrict__ states)
{
    extern __shared__ char sm[];
    uint32_t sb = smem_u32(sm);
    int tid = threadIdx.x, wid = tid >> 5, lane = tid & 31;
    int bb = blockIdx.y, n0 = blockIdx.x * 64;
    size_t bofs = (size_t)bb*Nn*64;
    int tmin_sim = n0 >> 7;

    cp_tile64(sb, GA_QH, g_Qh + bofs + (size_t)n0*64, tid);
    cp_tile64(sb, GA_PH, g_Ph + bofs + (size_t)n0*64, tid);
    cp_tile128(sb, GB + GB_KH, g_Kh + bofs, tid);
    if (0 >= tmin_sim) cp_tile128(sb, GB + GB_PH, g_Ph + bofs, tid);
    CP_COMMIT();
    {
        size_t mofs = bofs + (size_t)128*64;
        cp_tile128(sb, GB + GB_BUF + GB_KH, g_Kh + mofs, tid);
        if (1 >= tmin_sim) cp_tile128(sb, GB + GB_BUF + GB_PH, g_Ph + mofs, tid);
        CP_COMMIT();
    }

    int wm = (wid & 3)*16, wn0 = (wid >> 2)*64, wng = wid >> 2;
    int rql = lane >> 2, cq = (lane & 3)*2, j4 = lane & 3;

    float v0[8], v1[8]; int i0[8], i1[8];
#pragma unroll
    for (int j = 0; j < 8; j++){ v0[j]=-1e30f; v1[j]=-1e30f; i0[j]=0; i1[j]=0; }

    for (int t = 0; t < Nn/128; t++){
        int buf = t & 1;
        if (t + 1 < Nn/128) CP_WAIT1(); else CP_WAIT0();
        __syncthreads();
        uint32_t bB = sb + GB + buf*GB_BUF;

        // ---- pass 1: scores = Qh . Kh ----
        float acc[8][4];
#pragma unroll
        for (int nt = 0; nt < 8; nt++)
#pragma unroll
            for (int e = 0; e < 4; e++) acc[nt][e] = 0.f;
#pragma unroll
        for (int kc = 0; kc < 4; kc++){
            uint32_t ah[4];
            ldmA(sb + GA_QH, wm, kc, GSR, ah);
            uint32_t bf[4][4];
#pragma unroll
            for (int p = 0; p < 4; p++) ldmB4(bB + GB_KH, wn0 + p*16, kc, GSR, bf[p]);
#pragma unroll
            for (int nt = 0; nt < 8; nt++) mma_h(acc[nt], ah, &bf[nt>>1][(nt&1)*2]);
        }
        {
            float t0 = -1e30f, t1 = -1e30f;
#pragma unroll
            for (int nt = 0; nt < 8; nt++){
                t0 = fmaxf(t0, fmaxf(acc[nt][0], acc[nt][1]));
                t1 = fmaxf(t1, fmaxf(acc[nt][2], acc[nt][3]));
            }
            if (t0 > v0[7]){
#pragma unroll
                for (int nt = 0; nt < 8; nt++){
                    int cb = t*128 + wn0 + nt*8 + cq;
                    INS8(v0, i0, acc[nt][0], cb);
                    INS8(v0, i0, acc[nt][1], cb+1);
                }
            }
            if (t1 > v1[7]){
#pragma unroll
                for (int nt = 0; nt < 8; nt++){
                    int cb = t*128 + wn0 + nt*8 + cq;
                    INS8(v1, i1, acc[nt][2], cb);
                    INS8(v1, i1, acc[nt][3], cb+1);
                }
            }
        }

        // ---- pass 2: sim = Ph . Ph (upper triangle only, mirrored) ----
        if (t >= tmin_sim){
#pragma unroll
            for (int nt = 0; nt < 8; nt++)
#pragma unroll
                for (int e = 0; e < 4; e++) acc[nt][e] = 0.f;
#pragma unroll
            for (int kc = 0; kc < 4; kc++){
                uint32_t ah[4];
                ldmA(sb + GA_PH, wm, kc, GSR, ah);
                uint32_t bf[4][4];
#pragma unroll
                for (int p = 0; p < 4; p++) ldmB4(bB + GB_PH, wn0 + p*16, kc, GSR, bf[p]);
#pragma unroll
                for (int nt = 0; nt < 8; nt++) mma_h(acc[nt], ah, &bf[nt>>1][(nt&1)*2]);
            }
#pragma unroll
            for (int nt = 0; nt < 8; nt++)
#pragma unroll
                for (int e = 0; e < 4; e++){
                    if (acc[nt][e] > 0.7f){
                        int row = n0 + wm + rql + ((e >= 2) ? 8 : 0);
                        int col = t*128 + wn0 + nt*8 + cq + (e & 1);
                        if (col >= row){
                            int hr = bb*Nn + row;
                            int s1 = atomicAdd(&g_hitcnt[hr], 1);
                            if (s1 < 32) g_hitlist[(size_t)hr*32 + s1] = col;
                            if (col > row){
                                int hc = bb*Nn + col;
                                int s2 = atomicAdd(&g_hitcnt[hc], 1);
                                if (s2 < 32) g_hitlist[(size_t)hc*32 + s2] = row;
                            }
                        }
                    }
                }
        }
        __syncthreads();

        if (t + 2 < Nn/128){
            size_t mofs = bofs + (size_t)(t+2)*128*64;
            cp_tile128(sb, GB + buf*GB_BUF + GB_KH, g_Kh + mofs, tid);
            if (t + 2 >= tmin_sim) cp_tile128(sb, GB + buf*GB_BUF + GB_PH, g_Ph + mofs, tid);
            CP_COMMIT();
        }
    }
    __syncthreads();

    // ---- dump candidates: 8 slices/row x 8 = 64 per row ----
    int* candI = (int*)(sm + G_CANDI);
    {
        int r0 = wm + rql, r1 = wm + rql + 8;
        int slice = wng*4 + j4;
#pragma unroll
        for (int s = 0; s < 8; s++){
            candI[r0*64 + slice*8 + s] = i0[s];
            candI[r1*64 + slice*8 + s] = i1[s];
        }
    }
    __syncthreads();

    // ---- exact fp32 rescore: 4 threads/row x 16 candidates ----
    float* mergeV = (float*)(sm + G_MV);
    int*   mergeI = (int*)(sm + G_MI);
    {
        int row = tid >> 2, sub = tid & 3;
        const float4* Q4 = (const float4*)(g_Qf + bofs + (size_t)(n0 + row)*64);
        float q[64];
#pragma unroll
        for (int i = 0; i < 16; i++){
            float4 v = Q4[i];
            q[4*i] = v.x; q[4*i+1] = v.y; q[4*i+2] = v.z; q[4*i+3] = v.w;
        }
        float tv[8]; int ti8[8];
#pragma unroll
        for (int j = 0; j < 8; j++){ tv[j] = -1e30f; ti8[j] = 0; }
#pragma unroll
        for (int c = 0; c < 16; c++){
            int col = candI[row*64 + sub*16 + c];
            const float4* K4 = (const float4*)(g_Kf + bofs + (size_t)col*64);
            float a2 = 0.f;
#pragma unroll
            for (int i = 0; i < 16; i++){
                float4 kv = K4[i];
                a2 = fmaf(q[4*i],   kv.x, a2);
                a2 = fmaf(q[4*i+1], kv.y, a2);
                a2 = fmaf(q[4*i+2], kv.z, a2);
                a2 = fmaf(q[4*i+3], kv.w, a2);
            }
            a2 *= 0.125f;
            INS8(tv, ti8, a2, col);
        }
#pragma unroll
        for (int s = 0; s < 8; s++){
            mergeV[row*32 + sub*8 + s] = tv[s];
            mergeI[row*32 + sub*8 + s] = ti8[s];
        }
    }
    __syncthreads();

    // ---- final merge + softmax (64 threads) ----
    float* topW = (float*)(sm + G_TOPW);
    int*   topI = (int*)(sm + G_TOPI);
    if (tid < 64){
        float tv[8]; int ti8[8];
#pragma unroll
        for (int j = 0; j < 8; j++){ tv[j] = -1e30f; ti8[j] = 0; }
#pragma unroll
        for (int c = 0; c < 32; c++){
            float mv = mergeV[tid*32 + c];
            int  mi = mergeI[tid*32 + c];
            INS8(tv, ti8, mv, mi);
        }
        float mx = tv[0];        // sorted descending
        float e[8], ssum = 0.f;
#pragma unroll
        for (int j = 0; j < 8; j++){ e[j] = __expf(tv[j] - mx); ssum += e[j]; }
        float inv = 1.f / ssum;
#pragma unroll
        for (int j = 0; j < 8; j++){ topW[tid*8+j] = e[j]*inv; topI[tid*8+j] = ti8[j]; }
    }
    __syncthreads();

    // ---- gather incoming (8 warps x 8 rows) ----
    const float* Sb = states + (size_t)bb*Nn*Dd;
    for (int rr = 0; rr < 8; rr++){
        int r = wid*8 + rr;
        float w8[8]; int i8[8];
#pragma unroll
        for (int j = 0; j < 8; j++){ w8[j] = topW[r*8+j]; i8[j] = topI[r*8+j]; }
        float* Ig = g_INC + ((size_t)bb*Nn + n0 + r)*Dd;
#pragma unroll
        for (int dd = 0; dd < 8; dd++){
            int d = lane + dd*32;
            float a2 = 0.f;
#pragma unroll
            for (int j = 0; j < 8; j++) a2 = fmaf(w8[j], Sb[(size_t)i8[j]*Dd + d], a2);
            Ig[d] = a2;
        }
    }
}

// ---------------- kernel 3a: phase-1 gather + X (fp16) ----------------
__global__ __launch_bounds__(256) void hdc_a(float* __restrict__ out_states){
    int tid = threadIdx.x, wid = tid >> 5, lane = tid & 31;
    int row0 = blockIdx.x * 64;
    int bb = row0 / Nn;
    for (int r8 = 0; r8 < 8; r8++){
        int row = row0 + wid*8 + r8;
        int cnt = g_hitcnt[row];
        int lim = cnt < 32 ? cnt : 32;
        const int* hl = g_hitlist + (size_t)row*32;
        float comb[8];
#pragma unroll
        for (int i = 0; i < 8; i++) comb[i] = 0.f;
        for (int j = 0; j < lim; j++){
            const float* src = g_INC + ((size_t)bb*Nn + hl[j])*Dd;
#pragma unroll
            for (int i = 0; i < 8; i++) comb[i] += src[lane + i*32];
        }
        const float* inc = g_INC + (size_t)row*Dd;
        float inv = 0.2f / ((float)cnt + 1e-8f);
#pragma unroll
        for (int i = 0; i < 8; i++){
            int d = lane + i*32;
            float ov = 0.8f*inc[d] + comb[i]*inv;
            out_states[(size_t)row*Dd + d] = ov;
            g_Xh[(size_t)row*Dd + d] = __float2half(ov);
        }
    }
    if (tid < 64){
        g_dot[row0+tid] = 0.f; g_na[row0+tid] = 0.f; g_nb[row0+tid] = 0.f;
    }
}

// ---------------- kernel 3b: Wh GEMM (fp16 single-term) + episodic -------
#define SR 144
#define HB_BUFSZ 27648
#define HB_AH 0
#define HB_BH 18432
#define HB_TOT 55296

__device__ __forceinline__ void cp_rows(uint32_t sb, int dst, const __half* src,
                                        int nrows, size_t srcstride, int tid){
    int total = nrows*8;
    for (int i = tid; i < total; i += 256){
        int row = i >> 3, ch = i & 7;
        uint32_t d = sb + dst + row*SR + ch*16;
        const char* s = (const char*)(src + (size_t)row*srcstride) + ch*16;
        asm volatile("cp.async.cg.shared.global [%0], [%1], 16;" :: "r"(d), "l"(s));
    }
}

__global__ __launch_bounds__(256,3) void hdc_b(
    const float* __restrict__ episodic,
    const float* __restrict__ bh,
    const float* __restrict__ keys, const float* __restrict__ pcodes,
    const int* __restrict__ step,
    float* __restrict__ out_epi)
{
    extern __shared__ char sm[];
    uint32_t sb = smem_u32(sm);
    int tid = threadIdx.x, wid = tid >> 5, lane = tid & 31;
    int row0 = blockIdx.x * 128;
    int c0   = blockIdx.y * 64;
    int prow = ((step[0] % NCc) + NCc) % NCc;
    const float* posr = pcodes + (size_t)prow*Hh;

    const __half* Xh = g_Xh + (size_t)row0*Dd;
    const __half* Wh = g_WhT + (size_t)c0*Dd;

    cp_rows(sb, HB_AH, Xh,      128, Dd, tid);
    cp_rows(sb, HB_BH, Wh,      64,  Dd, tid);
    CP_COMMIT();
    cp_rows(sb, HB_BUFSZ + HB_AH, Xh + 64, 128, Dd, tid);
    cp_rows(sb, HB_BUFSZ + HB_BH, Wh + 64, 64,  Dd, tid);
    CP_COMMIT();

    int wm = wid*16;
    int rql = lane >> 2, cq = (lane & 3)*2, j4 = lane & 3;

    float acc[8][4];
#pragma unroll
    for (int nt = 0; nt < 8; nt++)
#pragma unroll
        for (int e = 0; e < 4; e++) acc[nt][e] = 0.f;

    for (int c = 0; c < 4; c++){
        int buf = c & 1;
        if (c + 1 < 4) CP_WAIT1(); else CP_WAIT0();
        __syncthreads();
        uint32_t aH = sb + buf*HB_BUFSZ + HB_AH;
        uint32_t bH = sb + buf*HB_BUFSZ + HB_BH;
#pragma unroll
        for (int kc = 0; kc < 4; kc++){
            uint32_t ah[4];
            ldmA(aH, wm, kc, SR, ah);
            uint32_t bfh[4][4];
#pragma unroll
            for (int p = 0; p < 4; p++) ldmB4(bH, p*16, kc, SR, bfh[p]);
#pragma unroll
            for (int nt = 0; nt < 8; nt++) mma_h(acc[nt], ah, &bfh[nt>>1][(nt&1)*2]);
        }
        __syncthreads();
        if (c + 2 < 4){
            int koff = (c+2)*64;
            cp_rows(sb, buf*HB_BUFSZ + HB_AH, Xh + koff, 128, Dd, tid);
            cp_rows(sb, buf*HB_BUFSZ + HB_BH, Wh + koff, 64,  Dd, tid);
            CP_COMMIT();
        }
    }

    float d0 = 0.f, a0 = 0.f, b0 = 0.f;
    float d1 = 0.f, a1 = 0.f, b1 = 0.f;
    int grow0 = row0 + wm + rql, grow1 = grow0 + 8;
    int n0k = grow0 & (Nn-1), n1k = grow1 & (Nn-1);
#pragma unroll
    for (int nt = 0; nt < 8; nt++){
        int col = c0 + nt*8 + cq;
        float bh0 = __ldg(bh + col), bh1v = __ldg(bh + col + 1);
        float p0c = __ldg(posr + col), p1c = __ldg(posr + col + 1);
        {
            float y0 = 6.0f*(acc[nt][0] + bh0);
            float y1 = 6.0f*(acc[nt][1] + bh1v);
            float h0 = 1.0f - 2.0f/(__expf(y0) + 1.0f);
            float h1 = 1.0f - 2.0f/(__expf(y1) + 1.0f);
            float2 ky = *(const float2*)(keys + (size_t)n0k*Hh + col);
            float pe0 = h0*ky.x, pe1 = h1*ky.y;
            float2 ep = *(const float2*)(episodic + (size_t)grow0*Hh + col);
            float ne0 = 0.95f*ep.x + 0.05f*pe0*p0c;
            float ne1 = 0.95f*ep.y + 0.05f*pe1*p1c;
            *(float2*)(out_epi + (size_t)grow0*Hh + col) = make_float2(ne0, ne1);
            d0 = fmaf(ne0, pe0, fmaf(ne1, pe1, d0));
            a0 = fmaf(ne0, ne0, fmaf(ne1, ne1, a0));
            b0 = fmaf(pe0, pe0, fmaf(pe1, pe1, b0));
        }
        {
            float y0 = 6.0f*(acc[nt][2] + bh0);
            float y1 = 6.0f*(acc[nt][3] + bh1v);
            float h0 = 1.0f - 2.0f/(__expf(y0) + 1.0f);
            float h1 = 1.0f - 2.0f/(__expf(y1) + 1.0f);
            float2 ky = *(const float2*)(keys + (size_t)n1k*Hh + col);
            float pe0 = h0*ky.x, pe1 = h1*ky.y;
            float2 ep = *(const float2*)(episodic + (size_t)grow1*Hh + col);
            float ne0 = 0.95f*ep.x + 0.05f*pe0*p0c;
            float ne1 = 0.95f*ep.y + 0.05f*pe1*p1c;
            *(float2*)(out_epi + (size_t)grow1*Hh + col) = make_float2(ne0, ne1);
            d1 = fmaf(ne0, pe0, fmaf(ne1, pe1, d1));
            a1 = fmaf(ne0, ne0, fmaf(ne1, ne1, a1));
            b1 = fmaf(pe0, pe0, fmaf(pe1, pe1, b1));
        }
    }
#pragma unroll
    for (int off = 1; off <= 2; off <<= 1){
        d0 += __shfl_xor_sync(0xffffffffu, d0, off);
        a0 += __shfl_xor_sync(0xffffffffu, a0, off);
        b0 += __shfl_xor_sync(0xffffffffu, b0, off);
        d1 += __shfl_xor_sync(0xffffffffu, d1, off);
        a1 += __shfl_xor_sync(0xffffffffu, a1, off);
        b1 += __shfl_xor_sync(0xffffffffu, b1, off);
    }
    if (j4 == 0){
        atomicAdd(&g_dot[grow0], d0); atomicAdd(&g_na[grow0], a0); atomicAdd(&g_nb[grow0], b0);
        atomicAdd(&g_dot[grow1], d1); atomicAdd(&g_na[grow1], a1); atomicAdd(&g_nb[grow1], b1);
    }
}

// ---------------- kernel 3c: out_sim finisher ----------------
__global__ __launch_bounds__(256) void hdc_c(float* __restrict__ out_sim){
    int i = blockIdx.x*256 + threadIdx.x;
    out_sim[i] = g_dot[i] / (fmaxf(sqrtf(g_na[i]), 1e-8f)*fmaxf(sqrtf(g_nb[i]), 1e-8f));
}

// ---------------- launch ----------------
extern "C" void kernel_launch(void* const* d_in, const int* in_sizes, int n_in,
                              void* d_out, int out_size)
{
    (void)in_sizes; (void)n_in; (void)out_size;
    const float* states   = (const float*)d_in[0];
    const float* actions  = (const float*)d_in[1];
    const float* episodic = (const float*)d_in[2];
    const float* Wq = (const float*)d_in[3];  const float* bq = (const float*)d_in[4];
    const float* Wk = (const float*)d_in[5];  const float* bk = (const float*)d_in[6];
    const float* Wc = (const float*)d_in[7];  const float* bc = (const float*)d_in[8];
    const float* Wh = (const float*)d_in[9];  const float* bh = (const float*)d_in[10];
    const float* keys   = (const float*)d_in[11];
    const float* pcodes = (const float*)d_in[12];
    const int*   step   = (const int*)d_in[13];

    float* out = (float*)d_out;
    float* o_states = out;
    float* o_epi    = out + (size_t)BN*Dd;
    float* o_sim    = out + (size_t)BN*Dd + (size_t)BN*Hh;

    proj_kernel<<<PROJ_BLOCKS + WH_BLOCKS, 256>>>(actions, Wq, bq, Wk, bk, Wc, bc, Wh);

    cudaFuncSetAttribute(graph_kernel, cudaFuncAttributeMaxDynamicSharedMemorySize, G_TOT);
    graph_kernel<<<dim3(Nn/64, Bb), 256, G_TOT>>>(states);

    hdc_a<<<BN/64, 256>>>(o_states);

    cudaFuncSetAttribute(hdc_b, cudaFuncAttributeMaxDynamicSharedMemorySize, HB_TOT);
    hdc_b<<<dim3(BN/128, Hh/64), 256, HB_TOT>>>(episodic, bh, keys, pcodes, step, o_epi);

    hdc_c<<<BN/256, 256>>>(o_sim);
}